// round 1
// baseline (speedup 1.0000x reference)
#include <cuda_runtime.h>
#include <cstdint>

#define N_NODES 10000
#define F_IN    256
#define H1      128
#define H2      64
#define E_MAX   320000

// ---------------- scratch (static device globals; no allocation) ------------
__device__ float g_deg[N_NODES];
__device__ float g_dis[N_NODES];
__device__ float g_norm[E_MAX];
__device__ float g_hw1[N_NODES * H1];
__device__ float g_h1 [N_NODES * H1];
__device__ float g_hw2[N_NODES * H2];
__device__ float g_hw3[N_NODES * H2];
__device__ int   g_is64;

// ---------------- int32/int64 edge-index detection --------------------------
__global__ void k_detect_idx(const void* ei, int E, int n) {
    if (blockIdx.x == 0 && threadIdx.x == 0) {
        const long long* p = (const long long*)ei;
        int is64 = 1;
        int m = E < 1024 ? E : 1024;
        for (int k = 0; k < m; k++) {
            long long v = p[k];
            if (v < 0 || v >= (long long)n) { is64 = 0; break; }
        }
        g_is64 = is64;
    }
}

__device__ __forceinline__ int edge_at(const void* ei, long long i) {
    if (g_is64) return (int)((const long long*)ei)[i];
    return ((const int*)ei)[i];
}

// ---------------- GCN normalization ------------------------------------------
__global__ void k_init_deg(int n) {
    int i = blockIdx.x * blockDim.x + threadIdx.x;
    if (i < n) g_deg[i] = 1.0f;                       // self-loop weight
}

__global__ void k_deg_accum(const void* ei, const float* __restrict__ w, int E) {
    int e = blockIdx.x * blockDim.x + threadIdx.x;
    if (e >= E) return;
    int c = edge_at(ei, (long long)E + e);            // col
    atomicAdd(&g_deg[c], w[e]);
}

__global__ void k_dis(int n) {
    int i = blockIdx.x * blockDim.x + threadIdx.x;
    if (i < n) {
        float d = g_deg[i];
        g_dis[i] = (d > 0.0f) ? rsqrtf(d) : 0.0f;
    }
}

__global__ void k_norm(const void* ei, const float* __restrict__ w, int E) {
    int e = blockIdx.x * blockDim.x + threadIdx.x;
    if (e >= E) return;
    int r = edge_at(ei, e);
    int c = edge_at(ei, (long long)E + e);
    g_norm[e] = g_dis[r] * w[e] * g_dis[c];
}

// ---------------- generic tiled SGEMM: C[MxNc] = A[MxK] @ B[KxNc] ------------
// 64x64 tile, K-chunks of 16, 256 threads, 4x4 microtile. Nc multiple of 64.
__global__ __launch_bounds__(256) void k_sgemm(
    const float* __restrict__ A, const float* __restrict__ B,
    float* __restrict__ C, int M, int K, int Nc)
{
    __shared__ float As[16][68];   // As[k][m]
    __shared__ float Bs[16][68];   // Bs[k][n]
    int bm = blockIdx.y * 64, bn = blockIdx.x * 64;
    int tx = threadIdx.x, ty = threadIdx.y;
    int tid = ty * 16 + tx;

    float acc[4][4] = {};
    for (int k0 = 0; k0 < K; k0 += 16) {
        #pragma unroll
        for (int i = tid; i < 1024; i += 256) {
            int m = i >> 4, k = i & 15;
            int gm = bm + m;
            As[k][m] = (gm < M) ? A[(size_t)gm * K + k0 + k] : 0.0f;
        }
        #pragma unroll
        for (int i = tid; i < 1024; i += 256) {
            int k = i >> 6, n = i & 63;
            Bs[k][n] = B[(size_t)(k0 + k) * Nc + bn + n];
        }
        __syncthreads();
        #pragma unroll
        for (int k = 0; k < 16; k++) {
            float4 a = *(const float4*)&As[k][4 * ty];
            float4 b = *(const float4*)&Bs[k][4 * tx];
            acc[0][0] += a.x * b.x; acc[0][1] += a.x * b.y; acc[0][2] += a.x * b.z; acc[0][3] += a.x * b.w;
            acc[1][0] += a.y * b.x; acc[1][1] += a.y * b.y; acc[1][2] += a.y * b.z; acc[1][3] += a.y * b.w;
            acc[2][0] += a.z * b.x; acc[2][1] += a.z * b.y; acc[2][2] += a.z * b.z; acc[2][3] += a.z * b.w;
            acc[3][0] += a.w * b.x; acc[3][1] += a.w * b.y; acc[3][2] += a.w * b.z; acc[3][3] += a.w * b.w;
        }
        __syncthreads();
    }
    #pragma unroll
    for (int i = 0; i < 4; i++) {
        int gm = bm + 4 * ty + i;
        if (gm < M) {
            float4 v = make_float4(acc[i][0], acc[i][1], acc[i][2], acc[i][3]);
            *(float4*)&C[(size_t)gm * Nc + bn + 4 * tx] = v;
        }
    }
}

// ---------------- bias init + relu ------------------------------------------
__global__ void k_init_bias(float* __restrict__ out, const float* __restrict__ b,
                            int total, int F) {
    int i = blockIdx.x * blockDim.x + threadIdx.x;
    if (i < total) out[i] = b[i % F];
}

__global__ void k_relu(float* __restrict__ x, int total) {
    int i = blockIdx.x * blockDim.x + threadIdx.x;
    if (i < total) x[i] = fmaxf(x[i], 0.0f);
}

// ---------------- edge aggregation: out[col] += norm * hw[row] ---------------
// Self-loops handled as virtual edges e in [E, E+n): norm = dis[i]^2.
template <int F>
__global__ void k_aggregate(const float* __restrict__ hw, float* __restrict__ out,
                            const void* ei, int E, int n) {
    long long idx = (long long)blockIdx.x * blockDim.x + threadIdx.x;
    long long total = (long long)(E + n) * F;
    if (idx >= total) return;
    int e = (int)(idx / F);
    int f = (int)(idx % F);
    int r, c; float nv;
    if (e < E) {
        r = edge_at(ei, e);
        c = edge_at(ei, (long long)E + e);
        nv = g_norm[e];
    } else {
        int i = e - E;
        r = c = i;
        float d = g_dis[i];
        nv = d * d;
    }
    atomicAdd(&out[(size_t)c * F + f], nv * hw[(size_t)r * F + f]);
}

// ---------------- adj = Z @ Z^T (NT sgemm, K=64 fully resident) --------------
__global__ __launch_bounds__(256) void k_adj(const float* __restrict__ Z,
                                             float* __restrict__ C, int n) {
    __shared__ float As[64][68];   // As[k][r] = Z[bi+r][k]
    __shared__ float Bs[64][68];   // Bs[k][r] = Z[bj+r][k]
    int bi = blockIdx.y * 64, bj = blockIdx.x * 64;
    int tx = threadIdx.x, ty = threadIdx.y;
    int tid = ty * 16 + tx;

    #pragma unroll
    for (int i = tid; i < 4096; i += 256) {
        int r = i >> 6, k = i & 63;
        As[k][r] = (bi + r < n) ? Z[(size_t)(bi + r) * H2 + k] : 0.0f;
        Bs[k][r] = (bj + r < n) ? Z[(size_t)(bj + r) * H2 + k] : 0.0f;
    }
    __syncthreads();

    float acc[4][4] = {};
    #pragma unroll 16
    for (int k = 0; k < 64; k++) {
        float4 a = *(const float4*)&As[k][4 * ty];
        float4 b = *(const float4*)&Bs[k][4 * tx];
        acc[0][0] += a.x * b.x; acc[0][1] += a.x * b.y; acc[0][2] += a.x * b.z; acc[0][3] += a.x * b.w;
        acc[1][0] += a.y * b.x; acc[1][1] += a.y * b.y; acc[1][2] += a.y * b.z; acc[1][3] += a.y * b.w;
        acc[2][0] += a.z * b.x; acc[2][1] += a.z * b.y; acc[2][2] += a.z * b.z; acc[2][3] += a.z * b.w;
        acc[3][0] += a.w * b.x; acc[3][1] += a.w * b.y; acc[3][2] += a.w * b.z; acc[3][3] += a.w * b.w;
    }

    #pragma unroll
    for (int i = 0; i < 4; i++) {
        int gm = bi + 4 * ty + i;
        if (gm >= n) continue;
        int gn = bj + 4 * tx;
        if (gn + 3 < n) {
            float4 v = make_float4(acc[i][0], acc[i][1], acc[i][2], acc[i][3]);
            *(float4*)&C[(size_t)gm * n + gn] = v;
        } else {
            #pragma unroll
            for (int j = 0; j < 4; j++)
                if (gn + j < n) C[(size_t)gm * n + gn + j] = acc[i][j];
        }
    }
}

// ---------------- launch ------------------------------------------------------
extern "C" void kernel_launch(void* const* d_in, const int* in_sizes, int n_in,
                              void* d_out, int out_size) {
    const float* x   = (const float*)d_in[0];
    const void*  ei  = d_in[1];                 // edge_index [2,E], int64 or int32
    const float* ew  = (const float*)d_in[2];
    const float* W1  = (const float*)d_in[3];
    const float* b1  = (const float*)d_in[4];
    const float* W2  = (const float*)d_in[5];
    const float* b2  = (const float*)d_in[6];
    const float* W3  = (const float*)d_in[7];
    const float* b3  = (const float*)d_in[8];

    const int n = N_NODES;
    const int E = in_sizes[1] / 2;

    float* adj    = (float*)d_out;                                  // [N,N]
    float* mu     = (float*)d_out + (size_t)n * n;                  // [N,H2]
    float* logvar = mu + (size_t)n * H2;                            // [N,H2]

    float* g_hw1_p; cudaGetSymbolAddress((void**)&g_hw1_p, g_hw1);
    float* g_h1_p;  cudaGetSymbolAddress((void**)&g_h1_p,  g_h1);
    float* g_hw2_p; cudaGetSymbolAddress((void**)&g_hw2_p, g_hw2);
    float* g_hw3_p; cudaGetSymbolAddress((void**)&g_hw3_p, g_hw3);

    const int T = 256;

    // 0. index width detection
    k_detect_idx<<<1, 32>>>(ei, E, n);

    // 1. GCN normalization
    k_init_deg<<<(n + T - 1) / T, T>>>(n);
    k_deg_accum<<<(E + T - 1) / T, T>>>(ei, ew, E);
    k_dis<<<(n + T - 1) / T, T>>>(n);
    k_norm<<<(E + T - 1) / T, T>>>(ei, ew, E);

    dim3 blk(16, 16);

    // 2. layer 1: hw1 = x @ W1 ; h1 = relu(agg(hw1) + b1)
    k_sgemm<<<dim3(H1 / 64, (n + 63) / 64), blk>>>(x, W1, g_hw1_p, n, F_IN, H1);
    k_init_bias<<<(n * H1 + T - 1) / T, T>>>(g_h1_p, b1, n * H1, H1);
    {
        long long tot = (long long)(E + n) * H1;
        k_aggregate<H1><<<(unsigned)((tot + T - 1) / T), T>>>(g_hw1_p, g_h1_p, ei, E, n);
    }
    k_relu<<<(n * H1 + T - 1) / T, T>>>(g_h1_p, n * H1);

    // 3. layer 2: mu / logvar
    k_sgemm<<<dim3(H2 / 64, (n + 63) / 64), blk>>>(g_h1_p, W2, g_hw2_p, n, H1, H2);
    k_sgemm<<<dim3(H2 / 64, (n + 63) / 64), blk>>>(g_h1_p, W3, g_hw3_p, n, H1, H2);
    k_init_bias<<<(n * H2 + T - 1) / T, T>>>(mu,     b2, n * H2, H2);
    k_init_bias<<<(n * H2 + T - 1) / T, T>>>(logvar, b3, n * H2, H2);
    {
        long long tot = (long long)(E + n) * H2;
        unsigned nb = (unsigned)((tot + T - 1) / T);
        k_aggregate<H2><<<nb, T>>>(g_hw2_p, mu,     ei, E, n);
        k_aggregate<H2><<<nb, T>>>(g_hw3_p, logvar, ei, E, n);
    }

    // 4. adj = mu @ mu^T
    k_adj<<<dim3((n + 63) / 64, (n + 63) / 64), blk>>>(mu, adj, n);
}

// round 3
// speedup vs baseline: 1.1005x; 1.1005x over previous
#include <cuda_runtime.h>
#include <cstdint>

#define N_NODES 10000
#define F_IN    256
#define H1      128
#define H2      64
#define E_MAX   320000

typedef unsigned long long ull;

// ---------------- scratch (static device globals; no allocation) ------------
__device__ float g_deg[N_NODES];
__device__ float g_dis[N_NODES];
__device__ float g_norm[E_MAX];
__device__ float g_hw1[N_NODES * H1];
__device__ float g_h1 [N_NODES * H1];
__device__ float g_hw2[N_NODES * H2];
__device__ float g_hw3[N_NODES * H2];
__device__ int   g_is64;

// ---------------- int32/int64 edge-index detection --------------------------
__global__ void k_detect_idx(const void* ei, int E, int n) {
    if (blockIdx.x == 0 && threadIdx.x == 0) {
        const long long* p = (const long long*)ei;
        int is64 = 1;
        int m = E < 1024 ? E : 1024;
        for (int k = 0; k < m; k++) {
            long long v = p[k];
            if (v < 0 || v >= (long long)n) { is64 = 0; break; }
        }
        g_is64 = is64;
    }
}

__device__ __forceinline__ int edge_at(const void* ei, long long i) {
    if (g_is64) return (int)((const long long*)ei)[i];
    return ((const int*)ei)[i];
}

// ---------------- GCN normalization ------------------------------------------
__global__ void k_init_deg(int n) {
    int i = blockIdx.x * blockDim.x + threadIdx.x;
    if (i < n) g_deg[i] = 1.0f;                       // self-loop weight
}

__global__ void k_deg_accum(const void* ei, const float* __restrict__ w, int E) {
    int e = blockIdx.x * blockDim.x + threadIdx.x;
    if (e >= E) return;
    int c = edge_at(ei, (long long)E + e);            // col
    atomicAdd(&g_deg[c], w[e]);
}

__global__ void k_dis(int n) {
    int i = blockIdx.x * blockDim.x + threadIdx.x;
    if (i < n) {
        float d = g_deg[i];
        g_dis[i] = (d > 0.0f) ? rsqrtf(d) : 0.0f;
    }
}

__global__ void k_norm(const void* ei, const float* __restrict__ w, int E) {
    int e = blockIdx.x * blockDim.x + threadIdx.x;
    if (e >= E) return;
    int r = edge_at(ei, e);
    int c = edge_at(ei, (long long)E + e);
    g_norm[e] = g_dis[r] * w[e] * g_dis[c];
}

// ---------------- generic tiled SGEMM: C[MxNc] = A[MxK] @ B[KxNc] ------------
__global__ __launch_bounds__(256) void k_sgemm(
    const float* __restrict__ A, const float* __restrict__ B,
    float* __restrict__ C, int M, int K, int Nc)
{
    __shared__ float As[16][68];   // As[k][m]
    __shared__ float Bs[16][68];   // Bs[k][n]
    int bm = blockIdx.y * 64, bn = blockIdx.x * 64;
    int tx = threadIdx.x, ty = threadIdx.y;
    int tid = ty * 16 + tx;

    float acc[4][4] = {};
    for (int k0 = 0; k0 < K; k0 += 16) {
        #pragma unroll
        for (int i = tid; i < 1024; i += 256) {
            int m = i >> 4, k = i & 15;
            int gm = bm + m;
            As[k][m] = (gm < M) ? A[(size_t)gm * K + k0 + k] : 0.0f;
        }
        #pragma unroll
        for (int i = tid; i < 1024; i += 256) {
            int k = i >> 6, n = i & 63;
            Bs[k][n] = B[(size_t)(k0 + k) * Nc + bn + n];
        }
        __syncthreads();
        #pragma unroll
        for (int k = 0; k < 16; k++) {
            float4 a = *(const float4*)&As[k][4 * ty];
            float4 b = *(const float4*)&Bs[k][4 * tx];
            acc[0][0] += a.x * b.x; acc[0][1] += a.x * b.y; acc[0][2] += a.x * b.z; acc[0][3] += a.x * b.w;
            acc[1][0] += a.y * b.x; acc[1][1] += a.y * b.y; acc[1][2] += a.y * b.z; acc[1][3] += a.y * b.w;
            acc[2][0] += a.z * b.x; acc[2][1] += a.z * b.y; acc[2][2] += a.z * b.z; acc[2][3] += a.z * b.w;
            acc[3][0] += a.w * b.x; acc[3][1] += a.w * b.y; acc[3][2] += a.w * b.z; acc[3][3] += a.w * b.w;
        }
        __syncthreads();
    }
    #pragma unroll
    for (int i = 0; i < 4; i++) {
        int gm = bm + 4 * ty + i;
        if (gm < M) {
            float4 v = make_float4(acc[i][0], acc[i][1], acc[i][2], acc[i][3]);
            *(float4*)&C[(size_t)gm * Nc + bn + 4 * tx] = v;
        }
    }
}

// ---------------- bias init + relu ------------------------------------------
__global__ void k_init_bias(float* __restrict__ out, const float* __restrict__ b,
                            int total, int F) {
    int i = blockIdx.x * blockDim.x + threadIdx.x;
    if (i < total) out[i] = b[i % F];
}

__global__ void k_relu(float* __restrict__ x, int total) {
    int i = blockIdx.x * blockDim.x + threadIdx.x;
    if (i < total) x[i] = fmaxf(x[i], 0.0f);
}

// ---------------- layer-1 aggregation: h1[col] += norm * hw1[row] ------------
// thread = (edge, float4-chunk); F = 128 -> 32 chunks
__global__ void k_agg1(const float* __restrict__ hw, float* __restrict__ out,
                       const void* ei, int E, int n) {
    int idx = blockIdx.x * blockDim.x + threadIdx.x;
    int total = (E + n) * 32;
    if (idx >= total) return;
    int e = idx >> 5;
    int f = (idx & 31) * 4;
    int r, c; float nv;
    if (e < E) {
        r = edge_at(ei, e);
        c = edge_at(ei, (long long)E + e);
        nv = g_norm[e];
    } else {
        r = c = e - E;
        float d = g_dis[r];
        nv = d * d;
    }
    float4 v = *(const float4*)&hw[(size_t)r * H1 + f];
    float* p = &out[(size_t)c * H1 + f];
    atomicAdd(p + 0, nv * v.x);
    atomicAdd(p + 1, nv * v.y);
    atomicAdd(p + 2, nv * v.z);
    atomicAdd(p + 3, nv * v.w);
}

// ---------------- fused layer-2/3 aggregation (mu + logvar) ------------------
// thread = (edge, float4-chunk); F = 64 -> 16 chunks; handles both tensors
__global__ void k_agg2(const float* __restrict__ hw2, const float* __restrict__ hw3,
                       float* __restrict__ mu, float* __restrict__ lv,
                       const void* ei, int E, int n) {
    int idx = blockIdx.x * blockDim.x + threadIdx.x;
    int total = (E + n) * 16;
    if (idx >= total) return;
    int e = idx >> 4;
    int f = (idx & 15) * 4;
    int r, c; float nv;
    if (e < E) {
        r = edge_at(ei, e);
        c = edge_at(ei, (long long)E + e);
        nv = g_norm[e];
    } else {
        r = c = e - E;
        float d = g_dis[r];
        nv = d * d;
    }
    float4 v2 = *(const float4*)&hw2[(size_t)r * H2 + f];
    float4 v3 = *(const float4*)&hw3[(size_t)r * H2 + f];
    float* pm = &mu[(size_t)c * H2 + f];
    float* pl = &lv[(size_t)c * H2 + f];
    atomicAdd(pm + 0, nv * v2.x);
    atomicAdd(pm + 1, nv * v2.y);
    atomicAdd(pm + 2, nv * v2.z);
    atomicAdd(pm + 3, nv * v2.w);
    atomicAdd(pl + 0, nv * v3.x);
    atomicAdd(pl + 1, nv * v3.y);
    atomicAdd(pl + 2, nv * v3.z);
    atomicAdd(pl + 3, nv * v3.w);
}

// ---------------- adj = Z @ Z^T, packed f32x2 FFMA ---------------------------
// 128x128 tile, 8x8 microtile, K=64 fully smem-resident. 1-D 256-thread block.
__device__ __forceinline__ ull pk2(float lo, float hi) {
    ull r; asm("mov.b64 %0, {%1, %2};" : "=l"(r) : "f"(lo), "f"(hi)); return r;
}
__device__ __forceinline__ void ffma2(ull& d, ull a, ull b) {
    asm("fma.rn.f32x2 %0, %1, %2, %0;" : "+l"(d) : "l"(a), "l"(b));
}
__device__ __forceinline__ float2 upk(ull v) {
    float2 f; asm("mov.b64 {%0, %1}, %2;" : "=f"(f.x), "=f"(f.y) : "l"(v)); return f;
}

#define ADJ_PAD 132
#define ADJ_SMEM (2 * 64 * ADJ_PAD * 4)

__global__ __launch_bounds__(256, 2) void k_adj(const float* __restrict__ Z,
                                                float* __restrict__ C, int n) {
    extern __shared__ float sm[];
    float* As = sm;                      // [64][ADJ_PAD], As[k*PAD + r] = Z[bi+r][k]
    float* Bs = sm + 64 * ADJ_PAD;
    int bi = blockIdx.y * 128, bj = blockIdx.x * 128;
    int tid = threadIdx.x;               // 1-D block of 256
    int tx = tid & 15, ty = tid >> 4;

    // load + transpose: 128 rows x 16 float4 per array
    #pragma unroll
    for (int i = tid; i < 128 * 16; i += 256) {
        int r = i >> 4, c = i & 15;
        float4 va = (bi + r < n) ? *(const float4*)&Z[(size_t)(bi + r) * H2 + 4 * c]
                                 : make_float4(0.f, 0.f, 0.f, 0.f);
        float4 vb = (bj + r < n) ? *(const float4*)&Z[(size_t)(bj + r) * H2 + 4 * c]
                                 : make_float4(0.f, 0.f, 0.f, 0.f);
        As[(4 * c + 0) * ADJ_PAD + r] = va.x;
        As[(4 * c + 1) * ADJ_PAD + r] = va.y;
        As[(4 * c + 2) * ADJ_PAD + r] = va.z;
        As[(4 * c + 3) * ADJ_PAD + r] = va.w;
        Bs[(4 * c + 0) * ADJ_PAD + r] = vb.x;
        Bs[(4 * c + 1) * ADJ_PAD + r] = vb.y;
        Bs[(4 * c + 2) * ADJ_PAD + r] = vb.z;
        Bs[(4 * c + 3) * ADJ_PAD + r] = vb.w;
    }
    __syncthreads();

    ull acc[8][4] = {};
    #pragma unroll 8
    for (int k = 0; k < 64; k++) {
        float4 a0 = *(const float4*)&As[k * ADJ_PAD + 8 * ty];
        float4 a1 = *(const float4*)&As[k * ADJ_PAD + 8 * ty + 4];
        float4 b0 = *(const float4*)&Bs[k * ADJ_PAD + 8 * tx];
        float4 b1 = *(const float4*)&Bs[k * ADJ_PAD + 8 * tx + 4];
        ull bp0 = pk2(b0.x, b0.y), bp1 = pk2(b0.z, b0.w);
        ull bp2 = pk2(b1.x, b1.y), bp3 = pk2(b1.z, b1.w);
        float av[8] = {a0.x, a0.y, a0.z, a0.w, a1.x, a1.y, a1.z, a1.w};
        #pragma unroll
        for (int i = 0; i < 8; i++) {
            ull ap = pk2(av[i], av[i]);
            ffma2(acc[i][0], ap, bp0);
            ffma2(acc[i][1], ap, bp1);
            ffma2(acc[i][2], ap, bp2);
            ffma2(acc[i][3], ap, bp3);
        }
    }

    int gn = bj + 8 * tx;
    #pragma unroll
    for (int i = 0; i < 8; i++) {
        int gm = bi + 8 * ty + i;
        if (gm >= n) continue;
        float2 p0 = upk(acc[i][0]), p1 = upk(acc[i][1]);
        float2 p2 = upk(acc[i][2]), p3 = upk(acc[i][3]);
        float* cp = &C[(size_t)gm * n + gn];
        if (gn + 7 < n) {
            *(float4*)(cp + 0) = make_float4(p0.x, p0.y, p1.x, p1.y);
            *(float4*)(cp + 4) = make_float4(p2.x, p2.y, p3.x, p3.y);
        } else {
            float v[8] = {p0.x, p0.y, p1.x, p1.y, p2.x, p2.y, p3.x, p3.y};
            #pragma unroll
            for (int j = 0; j < 8; j++)
                if (gn + j < n) cp[j] = v[j];
        }
    }
}

// ---------------- launch ------------------------------------------------------
extern "C" void kernel_launch(void* const* d_in, const int* in_sizes, int n_in,
                              void* d_out, int out_size) {
    const float* x   = (const float*)d_in[0];
    const void*  ei  = d_in[1];                 // edge_index [2,E], int64 or int32
    const float* ew  = (const float*)d_in[2];
    const float* W1  = (const float*)d_in[3];
    const float* b1  = (const float*)d_in[4];
    const float* W2  = (const float*)d_in[5];
    const float* b2  = (const float*)d_in[6];
    const float* W3  = (const float*)d_in[7];
    const float* b3  = (const float*)d_in[8];

    const int n = N_NODES;
    const int E = in_sizes[1] / 2;

    float* adj    = (float*)d_out;                                  // [N,N]
    float* mu     = (float*)d_out + (size_t)n * n;                  // [N,H2]
    float* logvar = mu + (size_t)n * H2;                            // [N,H2]

    float* g_hw1_p; cudaGetSymbolAddress((void**)&g_hw1_p, g_hw1);
    float* g_h1_p;  cudaGetSymbolAddress((void**)&g_h1_p,  g_h1);
    float* g_hw2_p; cudaGetSymbolAddress((void**)&g_hw2_p, g_hw2);
    float* g_hw3_p; cudaGetSymbolAddress((void**)&g_hw3_p, g_hw3);

    static int s_attr_set = 0;
    if (!s_attr_set) {
        cudaFuncSetAttribute(k_adj, cudaFuncAttributeMaxDynamicSharedMemorySize, ADJ_SMEM);
        s_attr_set = 1;
    }

    const int T = 256;

    // 0. index width detection
    k_detect_idx<<<1, 32>>>(ei, E, n);

    // 1. GCN normalization
    k_init_deg<<<(n + T - 1) / T, T>>>(n);
    k_deg_accum<<<(E + T - 1) / T, T>>>(ei, ew, E);
    k_dis<<<(n + T - 1) / T, T>>>(n);
    k_norm<<<(E + T - 1) / T, T>>>(ei, ew, E);

    dim3 blk(16, 16);

    // 2. layer 1: hw1 = x @ W1 ; h1 = relu(agg(hw1) + b1)
    k_sgemm<<<dim3(H1 / 64, (n + 63) / 64), blk>>>(x, W1, g_hw1_p, n, F_IN, H1);
    k_init_bias<<<(n * H1 + T - 1) / T, T>>>(g_h1_p, b1, n * H1, H1);
    {
        int tot = (E + n) * 32;
        k_agg1<<<(tot + T - 1) / T, T>>>(g_hw1_p, g_h1_p, ei, E, n);
    }
    k_relu<<<(n * H1 + T - 1) / T, T>>>(g_h1_p, n * H1);

    // 3. layer 2: mu / logvar (fused aggregation)
    k_sgemm<<<dim3(H2 / 64, (n + 63) / 64), blk>>>(g_h1_p, W2, g_hw2_p, n, H1, H2);
    k_sgemm<<<dim3(H2 / 64, (n + 63) / 64), blk>>>(g_h1_p, W3, g_hw3_p, n, H1, H2);
    k_init_bias<<<(n * H2 + T - 1) / T, T>>>(mu,     b2, n * H2, H2);
    k_init_bias<<<(n * H2 + T - 1) / T, T>>>(logvar, b3, n * H2, H2);
    {
        int tot = (E + n) * 16;
        k_agg2<<<(tot + T - 1) / T, T>>>(g_hw2_p, g_hw3_p, mu, logvar, ei, E, n);
    }

    // 4. adj = mu @ mu^T (packed f32x2), 1-D 256-thread block
    k_adj<<<dim3((n + 127) / 128, (n + 127) / 128), 256, ADJ_SMEM>>>(mu, adj, n);
}

// round 4
// speedup vs baseline: 1.3611x; 1.2369x over previous
#include <cuda_runtime.h>
#include <cstdint>

#define N_NODES 10000
#define F_IN    256
#define H1      128
#define H2      64
#define E_MAX   320000
#define CSR_MAX (E_MAX + N_NODES)

typedef unsigned long long ull;

// ---------------- scratch (static device globals; no allocation) ------------
__device__ float g_deg[N_NODES];
__device__ float g_dis[N_NODES];
__device__ int   g_cnt[N_NODES];
__device__ int   g_off[N_NODES + 1];
__device__ int   g_fill[N_NODES];
__device__ int   g_csr_row[CSR_MAX];
__device__ float g_csr_nrm[CSR_MAX];
__device__ float g_hw1[N_NODES * H1];
__device__ float g_h1 [N_NODES * H1];
__device__ float g_hw2[N_NODES * H2];
__device__ float g_hw3[N_NODES * H2];
__device__ int   g_is64;

// ---------------- int32/int64 edge-index detection --------------------------
__global__ void k_detect_idx(const void* ei, int E, int n) {
    if (blockIdx.x == 0 && threadIdx.x == 0) {
        const long long* p = (const long long*)ei;
        int is64 = 1;
        int m = E < 1024 ? E : 1024;
        for (int k = 0; k < m; k++) {
            long long v = p[k];
            if (v < 0 || v >= (long long)n) { is64 = 0; break; }
        }
        g_is64 = is64;
    }
}

__device__ __forceinline__ int edge_at(const void* ei, long long i) {
    if (g_is64) return (int)((const long long*)ei)[i];
    return ((const int*)ei)[i];
}

// ---------------- degree (weighted) + count histogram ------------------------
__global__ void k_init_deg(int n) {
    int i = blockIdx.x * blockDim.x + threadIdx.x;
    if (i < n) { g_deg[i] = 1.0f; g_cnt[i] = 1; }     // self-loop
}

__global__ void k_deg_accum(const void* ei, const float* __restrict__ w, int E) {
    int e = blockIdx.x * blockDim.x + threadIdx.x;
    if (e >= E) return;
    int c = edge_at(ei, (long long)E + e);            // col
    atomicAdd(&g_deg[c], w[e]);
    atomicAdd(&g_cnt[c], 1);
}

__global__ void k_dis(int n) {
    int i = blockIdx.x * blockDim.x + threadIdx.x;
    if (i < n) {
        float d = g_deg[i];
        g_dis[i] = (d > 0.0f) ? rsqrtf(d) : 0.0f;
    }
}

// ---------------- single-block exclusive prefix scan over g_cnt --------------
__global__ __launch_bounds__(1024) void k_scan(int n) {
    __shared__ int s[1024];
    __shared__ int carry;
    int tid = threadIdx.x;
    if (tid == 0) carry = 0;
    __syncthreads();
    for (int base = 0; base < n; base += 1024) {
        int v = (base + tid < n) ? g_cnt[base + tid] : 0;
        s[tid] = v;
        __syncthreads();
        #pragma unroll
        for (int off = 1; off < 1024; off <<= 1) {
            int t = (tid >= off) ? s[tid - off] : 0;
            __syncthreads();
            s[tid] += t;
            __syncthreads();
        }
        int excl = s[tid] - v + carry;
        if (base + tid < n) { g_off[base + tid] = excl; g_fill[base + tid] = excl; }
        __syncthreads();
        if (tid == 0) carry += s[1023];
        __syncthreads();
    }
    if (tid == 0) g_off[n] = carry;
}

// ---------------- scatter edges into CSR (grouped by col) --------------------
__global__ void k_scatter(const void* ei, const float* __restrict__ w, int E, int n) {
    int e = blockIdx.x * blockDim.x + threadIdx.x;
    if (e >= E + n) return;
    int r, c; float nv;
    if (e < E) {
        r = edge_at(ei, e);
        c = edge_at(ei, (long long)E + e);
        nv = g_dis[r] * w[e] * g_dis[c];
    } else {
        r = c = e - E;
        float d = g_dis[r];
        nv = d * d;
    }
    int pos = atomicAdd(&g_fill[c], 1);
    g_csr_row[pos] = r;
    g_csr_nrm[pos] = nv;
}

// ---------------- generic tiled SGEMM: C[MxNc] = A[MxK] @ B[KxNc] ------------
__global__ __launch_bounds__(256) void k_sgemm(
    const float* __restrict__ A, const float* __restrict__ B,
    float* __restrict__ C, int M, int K, int Nc)
{
    __shared__ float As[16][68];   // As[k][m]
    __shared__ float Bs[16][68];   // Bs[k][n]
    int bm = blockIdx.y * 64, bn = blockIdx.x * 64;
    int tx = threadIdx.x, ty = threadIdx.y;
    int tid = ty * 16 + tx;

    float acc[4][4] = {};
    for (int k0 = 0; k0 < K; k0 += 16) {
        #pragma unroll
        for (int i = tid; i < 1024; i += 256) {
            int m = i >> 4, k = i & 15;
            int gm = bm + m;
            As[k][m] = (gm < M) ? A[(size_t)gm * K + k0 + k] : 0.0f;
        }
        #pragma unroll
        for (int i = tid; i < 1024; i += 256) {
            int k = i >> 6, n = i & 63;
            Bs[k][n] = B[(size_t)(k0 + k) * Nc + bn + n];
        }
        __syncthreads();
        #pragma unroll
        for (int k = 0; k < 16; k++) {
            float4 a = *(const float4*)&As[k][4 * ty];
            float4 b = *(const float4*)&Bs[k][4 * tx];
            acc[0][0] += a.x * b.x; acc[0][1] += a.x * b.y; acc[0][2] += a.x * b.z; acc[0][3] += a.x * b.w;
            acc[1][0] += a.y * b.x; acc[1][1] += a.y * b.y; acc[1][2] += a.y * b.z; acc[1][3] += a.y * b.w;
            acc[2][0] += a.z * b.x; acc[2][1] += a.z * b.y; acc[2][2] += a.z * b.z; acc[2][3] += a.z * b.w;
            acc[3][0] += a.w * b.x; acc[3][1] += a.w * b.y; acc[3][2] += a.w * b.z; acc[3][3] += a.w * b.w;
        }
        __syncthreads();
    }
    #pragma unroll
    for (int i = 0; i < 4; i++) {
        int gm = bm + 4 * ty + i;
        if (gm < M) {
            float4 v = make_float4(acc[i][0], acc[i][1], acc[i][2], acc[i][3]);
            *(float4*)&C[(size_t)gm * Nc + bn + 4 * tx] = v;
        }
    }
}

// ---------------- CSR gather, layer 1: h1 = relu(agg(hw1) + b1) --------------
// one block (128 threads) per node; feature f = tid
__global__ __launch_bounds__(128) void k_gather1(
    const float* __restrict__ hw, float* __restrict__ out,
    const float* __restrict__ bias)
{
    __shared__ int   s_row[128];
    __shared__ float s_nrm[128];
    int c = blockIdx.x;
    int tid = threadIdx.x;
    int beg = g_off[c], end = g_off[c + 1];

    float a0 = 0.f, a1 = 0.f, a2 = 0.f, a3 = 0.f;
    for (int base = beg; base < end; base += 128) {
        int len = min(128, end - base);
        if (tid < len) {
            s_row[tid] = g_csr_row[base + tid];
            s_nrm[tid] = g_csr_nrm[base + tid];
        }
        __syncthreads();
        int j = 0;
        for (; j + 3 < len; j += 4) {
            a0 += s_nrm[j + 0] * hw[(size_t)s_row[j + 0] * H1 + tid];
            a1 += s_nrm[j + 1] * hw[(size_t)s_row[j + 1] * H1 + tid];
            a2 += s_nrm[j + 2] * hw[(size_t)s_row[j + 2] * H1 + tid];
            a3 += s_nrm[j + 3] * hw[(size_t)s_row[j + 3] * H1 + tid];
        }
        for (; j < len; j++)
            a0 += s_nrm[j] * hw[(size_t)s_row[j] * H1 + tid];
        __syncthreads();
    }
    float v = (a0 + a1) + (a2 + a3) + bias[tid];
    out[(size_t)c * H1 + tid] = fmaxf(v, 0.0f);
}

// ---------------- CSR gather, fused mu/logvar --------------------------------
// one block (128 threads) per node; tid<64 -> mu from hw2, tid>=64 -> lv from hw3
__global__ __launch_bounds__(128) void k_gather2(
    const float* __restrict__ hw2, const float* __restrict__ hw3,
    float* __restrict__ mu, float* __restrict__ lv,
    const float* __restrict__ b2, const float* __restrict__ b3)
{
    __shared__ int   s_row[128];
    __shared__ float s_nrm[128];
    int c = blockIdx.x;
    int tid = threadIdx.x;
    int half = tid >> 6;               // 0: mu, 1: logvar
    int f = tid & 63;
    const float* hw = half ? hw3 : hw2;
    int beg = g_off[c], end = g_off[c + 1];

    float a0 = 0.f, a1 = 0.f, a2 = 0.f, a3 = 0.f;
    for (int base = beg; base < end; base += 128) {
        int len = min(128, end - base);
        if (tid < len) {
            s_row[tid] = g_csr_row[base + tid];
            s_nrm[tid] = g_csr_nrm[base + tid];
        }
        __syncthreads();
        int j = 0;
        for (; j + 3 < len; j += 4) {
            a0 += s_nrm[j + 0] * hw[(size_t)s_row[j + 0] * H2 + f];
            a1 += s_nrm[j + 1] * hw[(size_t)s_row[j + 1] * H2 + f];
            a2 += s_nrm[j + 2] * hw[(size_t)s_row[j + 2] * H2 + f];
            a3 += s_nrm[j + 3] * hw[(size_t)s_row[j + 3] * H2 + f];
        }
        for (; j < len; j++)
            a0 += s_nrm[j] * hw[(size_t)s_row[j] * H2 + f];
        __syncthreads();
    }
    float v = (a0 + a1) + (a2 + a3);
    if (half == 0) mu[(size_t)c * H2 + f] = v + b2[f];
    else           lv[(size_t)c * H2 + f] = v + b3[f];
}

// ---------------- adj = Z @ Z^T, packed f32x2 FFMA ---------------------------
__device__ __forceinline__ ull pk2(float lo, float hi) {
    ull r; asm("mov.b64 %0, {%1, %2};" : "=l"(r) : "f"(lo), "f"(hi)); return r;
}
__device__ __forceinline__ void ffma2(ull& d, ull a, ull b) {
    asm("fma.rn.f32x2 %0, %1, %2, %0;" : "+l"(d) : "l"(a), "l"(b));
}
__device__ __forceinline__ float2 upk(ull v) {
    float2 f; asm("mov.b64 {%0, %1}, %2;" : "=f"(f.x), "=f"(f.y) : "l"(v)); return f;
}

#define ADJ_PAD 132
#define ADJ_SMEM (2 * 64 * ADJ_PAD * 4)

__global__ __launch_bounds__(256, 2) void k_adj(const float* __restrict__ Z,
                                                float* __restrict__ C, int n) {
    extern __shared__ float sm[];
    float* As = sm;                      // [64][ADJ_PAD], As[k*PAD + r] = Z[bi+r][k]
    float* Bs = sm + 64 * ADJ_PAD;
    int bi = blockIdx.y * 128, bj = blockIdx.x * 128;
    int tid = threadIdx.x;               // 1-D block of 256
    int tx = tid & 15, ty = tid >> 4;

    #pragma unroll
    for (int i = tid; i < 128 * 16; i += 256) {
        int r = i >> 4, c = i & 15;
        float4 va = (bi + r < n) ? *(const float4*)&Z[(size_t)(bi + r) * H2 + 4 * c]
                                 : make_float4(0.f, 0.f, 0.f, 0.f);
        float4 vb = (bj + r < n) ? *(const float4*)&Z[(size_t)(bj + r) * H2 + 4 * c]
                                 : make_float4(0.f, 0.f, 0.f, 0.f);
        As[(4 * c + 0) * ADJ_PAD + r] = va.x;
        As[(4 * c + 1) * ADJ_PAD + r] = va.y;
        As[(4 * c + 2) * ADJ_PAD + r] = va.z;
        As[(4 * c + 3) * ADJ_PAD + r] = va.w;
        Bs[(4 * c + 0) * ADJ_PAD + r] = vb.x;
        Bs[(4 * c + 1) * ADJ_PAD + r] = vb.y;
        Bs[(4 * c + 2) * ADJ_PAD + r] = vb.z;
        Bs[(4 * c + 3) * ADJ_PAD + r] = vb.w;
    }
    __syncthreads();

    ull acc[8][4] = {};
    #pragma unroll 8
    for (int k = 0; k < 64; k++) {
        float4 a0 = *(const float4*)&As[k * ADJ_PAD + 8 * ty];
        float4 a1 = *(const float4*)&As[k * ADJ_PAD + 8 * ty + 4];
        // b pairs are adjacent in smem: load directly as packed 64-bit words
        const ull* bp = (const ull*)&Bs[k * ADJ_PAD + 8 * tx];
        ull bp0 = bp[0], bp1 = bp[1], bp2 = bp[2], bp3 = bp[3];
        float av[8] = {a0.x, a0.y, a0.z, a0.w, a1.x, a1.y, a1.z, a1.w};
        #pragma unroll
        for (int i = 0; i < 8; i++) {
            ull ap = pk2(av[i], av[i]);
            ffma2(acc[i][0], ap, bp0);
            ffma2(acc[i][1], ap, bp1);
            ffma2(acc[i][2], ap, bp2);
            ffma2(acc[i][3], ap, bp3);
        }
    }

    int gn = bj + 8 * tx;
    #pragma unroll
    for (int i = 0; i < 8; i++) {
        int gm = bi + 8 * ty + i;
        if (gm >= n) continue;
        float2 p0 = upk(acc[i][0]), p1 = upk(acc[i][1]);
        float2 p2 = upk(acc[i][2]), p3 = upk(acc[i][3]);
        float* cp = &C[(size_t)gm * n + gn];
        if (gn + 7 < n) {
            *(float4*)(cp + 0) = make_float4(p0.x, p0.y, p1.x, p1.y);
            *(float4*)(cp + 4) = make_float4(p2.x, p2.y, p3.x, p3.y);
        } else {
            float v[8] = {p0.x, p0.y, p1.x, p1.y, p2.x, p2.y, p3.x, p3.y};
            #pragma unroll
            for (int j = 0; j < 8; j++)
                if (gn + j < n) cp[j] = v[j];
        }
    }
}

// ---------------- launch ------------------------------------------------------
extern "C" void kernel_launch(void* const* d_in, const int* in_sizes, int n_in,
                              void* d_out, int out_size) {
    const float* x   = (const float*)d_in[0];
    const void*  ei  = d_in[1];                 // edge_index [2,E], int64 or int32
    const float* ew  = (const float*)d_in[2];
    const float* W1  = (const float*)d_in[3];
    const float* b1  = (const float*)d_in[4];
    const float* W2  = (const float*)d_in[5];
    const float* b2  = (const float*)d_in[6];
    const float* W3  = (const float*)d_in[7];
    const float* b3  = (const float*)d_in[8];

    const int n = N_NODES;
    const int E = in_sizes[1] / 2;

    float* adj    = (float*)d_out;                                  // [N,N]
    float* mu     = (float*)d_out + (size_t)n * n;                  // [N,H2]
    float* logvar = mu + (size_t)n * H2;                            // [N,H2]

    float* g_hw1_p; cudaGetSymbolAddress((void**)&g_hw1_p, g_hw1);
    float* g_h1_p;  cudaGetSymbolAddress((void**)&g_h1_p,  g_h1);
    float* g_hw2_p; cudaGetSymbolAddress((void**)&g_hw2_p, g_hw2);
    float* g_hw3_p; cudaGetSymbolAddress((void**)&g_hw3_p, g_hw3);

    static int s_attr_set = 0;
    if (!s_attr_set) {
        cudaFuncSetAttribute(k_adj, cudaFuncAttributeMaxDynamicSharedMemorySize, ADJ_SMEM);
        s_attr_set = 1;
    }

    const int T = 256;

    // 0. index width detection
    k_detect_idx<<<1, 32>>>(ei, E, n);

    // 1. GCN normalization + CSR build (grouped by destination col)
    k_init_deg<<<(n + T - 1) / T, T>>>(n);
    k_deg_accum<<<(E + T - 1) / T, T>>>(ei, ew, E);
    k_dis<<<(n + T - 1) / T, T>>>(n);
    k_scan<<<1, 1024>>>(n);
    k_scatter<<<(E + n + T - 1) / T, T>>>(ei, ew, E, n);

    dim3 blk(16, 16);

    // 2. layer 1: hw1 = x @ W1 ; h1 = relu(gather(hw1) + b1)
    k_sgemm<<<dim3(H1 / 64, (n + 63) / 64), blk>>>(x, W1, g_hw1_p, n, F_IN, H1);
    k_gather1<<<n, 128>>>(g_hw1_p, g_h1_p, b1);

    // 3. layer 2: mu / logvar (fused gather)
    k_sgemm<<<dim3(H2 / 64, (n + 63) / 64), blk>>>(g_h1_p, W2, g_hw2_p, n, H1, H2);
    k_sgemm<<<dim3(H2 / 64, (n + 63) / 64), blk>>>(g_h1_p, W3, g_hw3_p, n, H1, H2);
    k_gather2<<<n, 128>>>(g_hw2_p, g_hw3_p, mu, logvar, b2, b3);

    // 4. adj = mu @ mu^T (packed f32x2), 1-D 256-thread block
    k_adj<<<dim3((n + 127) / 128, (n + 127) / 128), 256, ADJ_SMEM>>>(mu, adj, n);
}

// round 5
// speedup vs baseline: 1.3616x; 1.0003x over previous
#include <cuda_runtime.h>
#include <cstdint>

#define N_NODES 10000
#define F_IN    256
#define H1      128
#define H2      64
#define E_MAX   320000
#define CSR_MAX (E_MAX + N_NODES)

typedef unsigned long long ull;

// ---------------- scratch (static device globals; no allocation) ------------
__device__ float g_deg[N_NODES];
__device__ float g_dis[N_NODES];
__device__ int   g_cnt[N_NODES];
__device__ int   g_off[N_NODES + 1];
__device__ int   g_fill[N_NODES];
__device__ int   g_csr_row[CSR_MAX];
__device__ float g_csr_nrm[CSR_MAX];
__device__ float g_hw1[N_NODES * H1];
__device__ float g_h1 [N_NODES * H1];
__device__ float g_hw2[N_NODES * H2];
__device__ float g_hw3[N_NODES * H2];
__device__ int   g_is64;

// ---------------- int32/int64 edge-index detection --------------------------
__global__ void k_detect_idx(const void* ei, int E, int n) {
    if (blockIdx.x == 0 && threadIdx.x == 0) {
        const long long* p = (const long long*)ei;
        int is64 = 1;
        int m = E < 1024 ? E : 1024;
        for (int k = 0; k < m; k++) {
            long long v = p[k];
            if (v < 0 || v >= (long long)n) { is64 = 0; break; }
        }
        g_is64 = is64;
    }
}

__device__ __forceinline__ int edge_at(const void* ei, long long i) {
    if (g_is64) return (int)((const long long*)ei)[i];
    return ((const int*)ei)[i];
}

// ---------------- degree (weighted) + count histogram ------------------------
__global__ void k_init_deg(int n) {
    int i = blockIdx.x * blockDim.x + threadIdx.x;
    if (i < n) { g_deg[i] = 1.0f; g_cnt[i] = 1; }     // self-loop
}

__global__ void k_deg_accum(const void* ei, const float* __restrict__ w, int E) {
    int e = blockIdx.x * blockDim.x + threadIdx.x;
    if (e >= E) return;
    int c = edge_at(ei, (long long)E + e);            // col
    atomicAdd(&g_deg[c], w[e]);
    atomicAdd(&g_cnt[c], 1);
}

__global__ void k_dis(int n) {
    int i = blockIdx.x * blockDim.x + threadIdx.x;
    if (i < n) {
        float d = g_deg[i];
        g_dis[i] = (d > 0.0f) ? rsqrtf(d) : 0.0f;
    }
}

// ---------------- single-block exclusive prefix scan over g_cnt --------------
__global__ __launch_bounds__(1024) void k_scan(int n) {
    __shared__ int s[1024];
    __shared__ int carry;
    int tid = threadIdx.x;
    if (tid == 0) carry = 0;
    __syncthreads();
    for (int base = 0; base < n; base += 1024) {
        int v = (base + tid < n) ? g_cnt[base + tid] : 0;
        s[tid] = v;
        __syncthreads();
        #pragma unroll
        for (int off = 1; off < 1024; off <<= 1) {
            int t = (tid >= off) ? s[tid - off] : 0;
            __syncthreads();
            s[tid] += t;
            __syncthreads();
        }
        int excl = s[tid] - v + carry;
        if (base + tid < n) { g_off[base + tid] = excl; g_fill[base + tid] = excl; }
        __syncthreads();
        if (tid == 0) carry += s[1023];
        __syncthreads();
    }
    if (tid == 0) g_off[n] = carry;
}

// ---------------- scatter edges into CSR (grouped by col) --------------------
__global__ void k_scatter(const void* ei, const float* __restrict__ w, int E, int n) {
    int e = blockIdx.x * blockDim.x + threadIdx.x;
    if (e >= E + n) return;
    int r, c; float nv;
    if (e < E) {
        r = edge_at(ei, e);
        c = edge_at(ei, (long long)E + e);
        nv = g_dis[r] * w[e] * g_dis[c];
    } else {
        r = c = e - E;
        float d = g_dis[r];
        nv = d * d;
    }
    int pos = atomicAdd(&g_fill[c], 1);
    g_csr_row[pos] = r;
    g_csr_nrm[pos] = nv;
}

// ---------------- generic tiled SGEMM: C[MxNc] = A[MxK] @ B[KxNc] ------------
__global__ __launch_bounds__(256) void k_sgemm(
    const float* __restrict__ A, const float* __restrict__ B,
    float* __restrict__ C, int M, int K, int Nc)
{
    __shared__ float As[16][68];   // As[k][m]
    __shared__ float Bs[16][68];   // Bs[k][n]
    int bm = blockIdx.y * 64, bn = blockIdx.x * 64;
    int tx = threadIdx.x, ty = threadIdx.y;
    int tid = ty * 16 + tx;

    float acc[4][4] = {};
    for (int k0 = 0; k0 < K; k0 += 16) {
        #pragma unroll
        for (int i = tid; i < 1024; i += 256) {
            int m = i >> 4, k = i & 15;
            int gm = bm + m;
            As[k][m] = (gm < M) ? A[(size_t)gm * K + k0 + k] : 0.0f;
        }
        #pragma unroll
        for (int i = tid; i < 1024; i += 256) {
            int k = i >> 6, n = i & 63;
            Bs[k][n] = B[(size_t)(k0 + k) * Nc + bn + n];
        }
        __syncthreads();
        #pragma unroll
        for (int k = 0; k < 16; k++) {
            float4 a = *(const float4*)&As[k][4 * ty];
            float4 b = *(const float4*)&Bs[k][4 * tx];
            acc[0][0] += a.x * b.x; acc[0][1] += a.x * b.y; acc[0][2] += a.x * b.z; acc[0][3] += a.x * b.w;
            acc[1][0] += a.y * b.x; acc[1][1] += a.y * b.y; acc[1][2] += a.y * b.z; acc[1][3] += a.y * b.w;
            acc[2][0] += a.z * b.x; acc[2][1] += a.z * b.y; acc[2][2] += a.z * b.z; acc[2][3] += a.z * b.w;
            acc[3][0] += a.w * b.x; acc[3][1] += a.w * b.y; acc[3][2] += a.w * b.z; acc[3][3] += a.w * b.w;
        }
        __syncthreads();
    }
    #pragma unroll
    for (int i = 0; i < 4; i++) {
        int gm = bm + 4 * ty + i;
        if (gm < M) {
            float4 v = make_float4(acc[i][0], acc[i][1], acc[i][2], acc[i][3]);
            *(float4*)&C[(size_t)gm * Nc + bn + 4 * tx] = v;
        }
    }
}

// ---------------- CSR gather, layer 1: h1 = relu(agg(hw1) + b1) --------------
// one block (128 threads) per node; feature f = tid
__global__ __launch_bounds__(128) void k_gather1(
    const float* __restrict__ hw, float* __restrict__ out,
    const float* __restrict__ bias)
{
    __shared__ int   s_row[128];
    __shared__ float s_nrm[128];
    int c = blockIdx.x;
    int tid = threadIdx.x;
    int beg = g_off[c], end = g_off[c + 1];

    float a0 = 0.f, a1 = 0.f, a2 = 0.f, a3 = 0.f;
    for (int base = beg; base < end; base += 128) {
        int len = min(128, end - base);
        if (tid < len) {
            s_row[tid] = g_csr_row[base + tid];
            s_nrm[tid] = g_csr_nrm[base + tid];
        }
        __syncthreads();
        int j = 0;
        for (; j + 3 < len; j += 4) {
            a0 += s_nrm[j + 0] * hw[(size_t)s_row[j + 0] * H1 + tid];
            a1 += s_nrm[j + 1] * hw[(size_t)s_row[j + 1] * H1 + tid];
            a2 += s_nrm[j + 2] * hw[(size_t)s_row[j + 2] * H1 + tid];
            a3 += s_nrm[j + 3] * hw[(size_t)s_row[j + 3] * H1 + tid];
        }
        for (; j < len; j++)
            a0 += s_nrm[j] * hw[(size_t)s_row[j] * H1 + tid];
        __syncthreads();
    }
    float v = (a0 + a1) + (a2 + a3) + bias[tid];
    out[(size_t)c * H1 + tid] = fmaxf(v, 0.0f);
}

// ---------------- CSR gather, fused mu/logvar --------------------------------
// one block (128 threads) per node; tid<64 -> mu from hw2, tid>=64 -> lv from hw3
__global__ __launch_bounds__(128) void k_gather2(
    const float* __restrict__ hw2, const float* __restrict__ hw3,
    float* __restrict__ mu, float* __restrict__ lv,
    const float* __restrict__ b2, const float* __restrict__ b3)
{
    __shared__ int   s_row[128];
    __shared__ float s_nrm[128];
    int c = blockIdx.x;
    int tid = threadIdx.x;
    int half = tid >> 6;               // 0: mu, 1: logvar
    int f = tid & 63;
    const float* hw = half ? hw3 : hw2;
    int beg = g_off[c], end = g_off[c + 1];

    float a0 = 0.f, a1 = 0.f, a2 = 0.f, a3 = 0.f;
    for (int base = beg; base < end; base += 128) {
        int len = min(128, end - base);
        if (tid < len) {
            s_row[tid] = g_csr_row[base + tid];
            s_nrm[tid] = g_csr_nrm[base + tid];
        }
        __syncthreads();
        int j = 0;
        for (; j + 3 < len; j += 4) {
            a0 += s_nrm[j + 0] * hw[(size_t)s_row[j + 0] * H2 + f];
            a1 += s_nrm[j + 1] * hw[(size_t)s_row[j + 1] * H2 + f];
            a2 += s_nrm[j + 2] * hw[(size_t)s_row[j + 2] * H2 + f];
            a3 += s_nrm[j + 3] * hw[(size_t)s_row[j + 3] * H2 + f];
        }
        for (; j < len; j++)
            a0 += s_nrm[j] * hw[(size_t)s_row[j] * H2 + f];
        __syncthreads();
    }
    float v = (a0 + a1) + (a2 + a3);
    if (half == 0) mu[(size_t)c * H2 + f] = v + b2[f];
    else           lv[(size_t)c * H2 + f] = v + b3[f];
}

// ---------------- adj = Z @ Z^T, packed f32x2 FFMA ---------------------------
__device__ __forceinline__ ull pk2(float lo, float hi) {
    ull r; asm("mov.b64 %0, {%1, %2};" : "=l"(r) : "f"(lo), "f"(hi)); return r;
}
__device__ __forceinline__ void ffma2(ull& d, ull a, ull b) {
    asm("fma.rn.f32x2 %0, %1, %2, %0;" : "+l"(d) : "l"(a), "l"(b));
}
__device__ __forceinline__ float2 upk(ull v) {
    float2 f; asm("mov.b64 {%0, %1}, %2;" : "=f"(f.x), "=f"(f.y) : "l"(v)); return f;
}

#define ADJ_PAD 132
#define ADJ_SMEM (2 * 64 * ADJ_PAD * 4)

__global__ __launch_bounds__(256, 2) void k_adj(const float* __restrict__ Z,
                                                float* __restrict__ C, int n) {
    extern __shared__ float sm[];
    float* As = sm;                      // [64][ADJ_PAD], As[k*PAD + r] = Z[bi+r][k]
    float* Bs = sm + 64 * ADJ_PAD;
    int bi = blockIdx.y * 128, bj = blockIdx.x * 128;
    int tid = threadIdx.x;               // 1-D block of 256
    int tx = tid & 15, ty = tid >> 4;

    #pragma unroll
    for (int i = tid; i < 128 * 16; i += 256) {
        int r = i >> 4, c = i & 15;
        float4 va = (bi + r < n) ? *(const float4*)&Z[(size_t)(bi + r) * H2 + 4 * c]
                                 : make_float4(0.f, 0.f, 0.f, 0.f);
        float4 vb = (bj + r < n) ? *(const float4*)&Z[(size_t)(bj + r) * H2 + 4 * c]
                                 : make_float4(0.f, 0.f, 0.f, 0.f);
        As[(4 * c + 0) * ADJ_PAD + r] = va.x;
        As[(4 * c + 1) * ADJ_PAD + r] = va.y;
        As[(4 * c + 2) * ADJ_PAD + r] = va.z;
        As[(4 * c + 3) * ADJ_PAD + r] = va.w;
        Bs[(4 * c + 0) * ADJ_PAD + r] = vb.x;
        Bs[(4 * c + 1) * ADJ_PAD + r] = vb.y;
        Bs[(4 * c + 2) * ADJ_PAD + r] = vb.z;
        Bs[(4 * c + 3) * ADJ_PAD + r] = vb.w;
    }
    __syncthreads();

    ull acc[8][4] = {};
    #pragma unroll 8
    for (int k = 0; k < 64; k++) {
        float4 a0 = *(const float4*)&As[k * ADJ_PAD + 8 * ty];
        float4 a1 = *(const float4*)&As[k * ADJ_PAD + 8 * ty + 4];
        // b pairs are adjacent in smem: load directly as packed 64-bit words
        const ull* bp = (const ull*)&Bs[k * ADJ_PAD + 8 * tx];
        ull bp0 = bp[0], bp1 = bp[1], bp2 = bp[2], bp3 = bp[3];
        float av[8] = {a0.x, a0.y, a0.z, a0.w, a1.x, a1.y, a1.z, a1.w};
        #pragma unroll
        for (int i = 0; i < 8; i++) {
            ull ap = pk2(av[i], av[i]);
            ffma2(acc[i][0], ap, bp0);
            ffma2(acc[i][1], ap, bp1);
            ffma2(acc[i][2], ap, bp2);
            ffma2(acc[i][3], ap, bp3);
        }
    }

    int gn = bj + 8 * tx;
    #pragma unroll
    for (int i = 0; i < 8; i++) {
        int gm = bi + 8 * ty + i;
        if (gm >= n) continue;
        float2 p0 = upk(acc[i][0]), p1 = upk(acc[i][1]);
        float2 p2 = upk(acc[i][2]), p3 = upk(acc[i][3]);
        float* cp = &C[(size_t)gm * n + gn];
        if (gn + 7 < n) {
            *(float4*)(cp + 0) = make_float4(p0.x, p0.y, p1.x, p1.y);
            *(float4*)(cp + 4) = make_float4(p2.x, p2.y, p3.x, p3.y);
        } else {
            float v[8] = {p0.x, p0.y, p1.x, p1.y, p2.x, p2.y, p3.x, p3.y};
            #pragma unroll
            for (int j = 0; j < 8; j++)
                if (gn + j < n) cp[j] = v[j];
        }
    }
}

// ---------------- launch ------------------------------------------------------
extern "C" void kernel_launch(void* const* d_in, const int* in_sizes, int n_in,
                              void* d_out, int out_size) {
    const float* x   = (const float*)d_in[0];
    const void*  ei  = d_in[1];                 // edge_index [2,E], int64 or int32
    const float* ew  = (const float*)d_in[2];
    const float* W1  = (const float*)d_in[3];
    const float* b1  = (const float*)d_in[4];
    const float* W2  = (const float*)d_in[5];
    const float* b2  = (const float*)d_in[6];
    const float* W3  = (const float*)d_in[7];
    const float* b3  = (const float*)d_in[8];

    const int n = N_NODES;
    const int E = in_sizes[1] / 2;

    float* adj    = (float*)d_out;                                  // [N,N]
    float* mu     = (float*)d_out + (size_t)n * n;                  // [N,H2]
    float* logvar = mu + (size_t)n * H2;                            // [N,H2]

    float* g_hw1_p; cudaGetSymbolAddress((void**)&g_hw1_p, g_hw1);
    float* g_h1_p;  cudaGetSymbolAddress((void**)&g_h1_p,  g_h1);
    float* g_hw2_p; cudaGetSymbolAddress((void**)&g_hw2_p, g_hw2);
    float* g_hw3_p; cudaGetSymbolAddress((void**)&g_hw3_p, g_hw3);

    static int s_attr_set = 0;
    if (!s_attr_set) {
        cudaFuncSetAttribute(k_adj, cudaFuncAttributeMaxDynamicSharedMemorySize, ADJ_SMEM);
        s_attr_set = 1;
    }

    const int T = 256;

    // 0. index width detection
    k_detect_idx<<<1, 32>>>(ei, E, n);

    // 1. GCN normalization + CSR build (grouped by destination col)
    k_init_deg<<<(n + T - 1) / T, T>>>(n);
    k_deg_accum<<<(E + T - 1) / T, T>>>(ei, ew, E);
    k_dis<<<(n + T - 1) / T, T>>>(n);
    k_scan<<<1, 1024>>>(n);
    k_scatter<<<(E + n + T - 1) / T, T>>>(ei, ew, E, n);

    dim3 blk(16, 16);

    // 2. layer 1: hw1 = x @ W1 ; h1 = relu(gather(hw1) + b1)
    k_sgemm<<<dim3(H1 / 64, (n + 63) / 64), blk>>>(x, W1, g_hw1_p, n, F_IN, H1);
    k_gather1<<<n, 128>>>(g_hw1_p, g_h1_p, b1);

    // 3. layer 2: mu / logvar (fused gather)
    k_sgemm<<<dim3(H2 / 64, (n + 63) / 64), blk>>>(g_h1_p, W2, g_hw2_p, n, H1, H2);
    k_sgemm<<<dim3(H2 / 64, (n + 63) / 64), blk>>>(g_h1_p, W3, g_hw3_p, n, H1, H2);
    k_gather2<<<n, 128>>>(g_hw2_p, g_hw3_p, mu, logvar, b2, b3);

    // 4. adj = mu @ mu^T (packed f32x2), 1-D 256-thread block
    k_adj<<<dim3((n + 127) / 128, (n + 127) / 128), 256, ADJ_SMEM>>>(mu, adj, n);
}

// round 6
// speedup vs baseline: 1.3707x; 1.0067x over previous
#include <cuda_runtime.h>
#include <cstdint>

#define N_NODES 10000
#define F_IN    256
#define H1      128
#define H2      64
#define E_MAX   320000
#define CSR_MAX (E_MAX + N_NODES)

typedef unsigned long long ull;

// ---------------- scratch (static device globals; no allocation) ------------
__device__ float g_deg[N_NODES];
__device__ float g_dis[N_NODES];
__device__ int   g_cnt[N_NODES];
__device__ int   g_off[N_NODES + 1];
__device__ int   g_fill[N_NODES];
__device__ int   g_csr_row[CSR_MAX];
__device__ float g_csr_nrm[CSR_MAX];
__device__ float g_hw1[N_NODES * H1];
__device__ float g_h1 [N_NODES * H1];
__device__ float g_hw2[N_NODES * H2];
__device__ float g_hw3[N_NODES * H2];
__device__ int   g_is64;

// ---------------- int32/int64 edge-index detection --------------------------
__global__ void k_detect_idx(const void* ei, int E, int n) {
    if (blockIdx.x == 0 && threadIdx.x == 0) {
        const long long* p = (const long long*)ei;
        int is64 = 1;
        int m = E < 1024 ? E : 1024;
        for (int k = 0; k < m; k++) {
            long long v = p[k];
            if (v < 0 || v >= (long long)n) { is64 = 0; break; }
        }
        g_is64 = is64;
    }
}

__device__ __forceinline__ int edge_at(const void* ei, long long i) {
    if (g_is64) return (int)((const long long*)ei)[i];
    return ((const int*)ei)[i];
}

// ---------------- degree (weighted) + count histogram ------------------------
__global__ void k_init_deg(int n) {
    int i = blockIdx.x * blockDim.x + threadIdx.x;
    if (i < n) { g_deg[i] = 1.0f; g_cnt[i] = 1; }     // self-loop
}

__global__ void k_deg_accum(const void* ei, const float* __restrict__ w, int E) {
    int e = blockIdx.x * blockDim.x + threadIdx.x;
    if (e >= E) return;
    int c = edge_at(ei, (long long)E + e);            // col
    atomicAdd(&g_deg[c], w[e]);
    atomicAdd(&g_cnt[c], 1);
}

__global__ void k_dis(int n) {
    int i = blockIdx.x * blockDim.x + threadIdx.x;
    if (i < n) {
        float d = g_deg[i];
        g_dis[i] = (d > 0.0f) ? rsqrtf(d) : 0.0f;
    }
}

// ---------------- single-block exclusive prefix scan over g_cnt --------------
__global__ __launch_bounds__(1024) void k_scan(int n) {
    __shared__ int s[1024];
    __shared__ int carry;
    int tid = threadIdx.x;
    if (tid == 0) carry = 0;
    __syncthreads();
    for (int base = 0; base < n; base += 1024) {
        int v = (base + tid < n) ? g_cnt[base + tid] : 0;
        s[tid] = v;
        __syncthreads();
        #pragma unroll
        for (int off = 1; off < 1024; off <<= 1) {
            int t = (tid >= off) ? s[tid - off] : 0;
            __syncthreads();
            s[tid] += t;
            __syncthreads();
        }
        int excl = s[tid] - v + carry;
        if (base + tid < n) { g_off[base + tid] = excl; g_fill[base + tid] = excl; }
        __syncthreads();
        if (tid == 0) carry += s[1023];
        __syncthreads();
    }
    if (tid == 0) g_off[n] = carry;
}

// ---------------- scatter edges into CSR (grouped by col) --------------------
__global__ void k_scatter(const void* ei, const float* __restrict__ w, int E, int n) {
    int e = blockIdx.x * blockDim.x + threadIdx.x;
    if (e >= E + n) return;
    int r, c; float nv;
    if (e < E) {
        r = edge_at(ei, e);
        c = edge_at(ei, (long long)E + e);
        nv = g_dis[r] * w[e] * g_dis[c];
    } else {
        r = c = e - E;
        float d = g_dis[r];
        nv = d * d;
    }
    int pos = atomicAdd(&g_fill[c], 1);
    g_csr_row[pos] = r;
    g_csr_nrm[pos] = nv;
}

// ---------------- generic tiled SGEMM: C[MxNc] = A[MxK] @ B[KxNc] ------------
__global__ __launch_bounds__(256) void k_sgemm(
    const float* __restrict__ A, const float* __restrict__ B,
    float* __restrict__ C, int M, int K, int Nc)
{
    __shared__ float As[16][68];   // As[k][m]
    __shared__ float Bs[16][68];   // Bs[k][n]
    int bm = blockIdx.y * 64, bn = blockIdx.x * 64;
    int tx = threadIdx.x, ty = threadIdx.y;
    int tid = ty * 16 + tx;

    float acc[4][4] = {};
    for (int k0 = 0; k0 < K; k0 += 16) {
        #pragma unroll
        for (int i = tid; i < 1024; i += 256) {
            int m = i >> 4, k = i & 15;
            int gm = bm + m;
            As[k][m] = (gm < M) ? A[(size_t)gm * K + k0 + k] : 0.0f;
        }
        #pragma unroll
        for (int i = tid; i < 1024; i += 256) {
            int k = i >> 6, n = i & 63;
            Bs[k][n] = B[(size_t)(k0 + k) * Nc + bn + n];
        }
        __syncthreads();
        #pragma unroll
        for (int k = 0; k < 16; k++) {
            float4 a = *(const float4*)&As[k][4 * ty];
            float4 b = *(const float4*)&Bs[k][4 * tx];
            acc[0][0] += a.x * b.x; acc[0][1] += a.x * b.y; acc[0][2] += a.x * b.z; acc[0][3] += a.x * b.w;
            acc[1][0] += a.y * b.x; acc[1][1] += a.y * b.y; acc[1][2] += a.y * b.z; acc[1][3] += a.y * b.w;
            acc[2][0] += a.z * b.x; acc[2][1] += a.z * b.y; acc[2][2] += a.z * b.z; acc[2][3] += a.z * b.w;
            acc[3][0] += a.w * b.x; acc[3][1] += a.w * b.y; acc[3][2] += a.w * b.z; acc[3][3] += a.w * b.w;
        }
        __syncthreads();
    }
    #pragma unroll
    for (int i = 0; i < 4; i++) {
        int gm = bm + 4 * ty + i;
        if (gm < M) {
            float4 v = make_float4(acc[i][0], acc[i][1], acc[i][2], acc[i][3]);
            *(float4*)&C[(size_t)gm * Nc + bn + 4 * tx] = v;
        }
    }
}

// ---------------- CSR gather, layer 1: h1 = relu(agg(hw1) + b1) --------------
// one block (128 threads) per node; feature f = tid
__global__ __launch_bounds__(128) void k_gather1(
    const float* __restrict__ hw, float* __restrict__ out,
    const float* __restrict__ bias)
{
    __shared__ int   s_row[128];
    __shared__ float s_nrm[128];
    int c = blockIdx.x;
    int tid = threadIdx.x;
    int beg = g_off[c], end = g_off[c + 1];

    float a0 = 0.f, a1 = 0.f, a2 = 0.f, a3 = 0.f;
    for (int base = beg; base < end; base += 128) {
        int len = min(128, end - base);
        if (tid < len) {
            s_row[tid] = g_csr_row[base + tid];
            s_nrm[tid] = g_csr_nrm[base + tid];
        }
        __syncthreads();
        int j = 0;
        for (; j + 3 < len; j += 4) {
            a0 += s_nrm[j + 0] * hw[(size_t)s_row[j + 0] * H1 + tid];
            a1 += s_nrm[j + 1] * hw[(size_t)s_row[j + 1] * H1 + tid];
            a2 += s_nrm[j + 2] * hw[(size_t)s_row[j + 2] * H1 + tid];
            a3 += s_nrm[j + 3] * hw[(size_t)s_row[j + 3] * H1 + tid];
        }
        for (; j < len; j++)
            a0 += s_nrm[j] * hw[(size_t)s_row[j] * H1 + tid];
        __syncthreads();
    }
    float v = (a0 + a1) + (a2 + a3) + bias[tid];
    out[(size_t)c * H1 + tid] = fmaxf(v, 0.0f);
}

// ---------------- CSR gather, fused mu/logvar --------------------------------
// one block (128 threads) per node; tid<64 -> mu from hw2, tid>=64 -> lv from hw3
__global__ __launch_bounds__(128) void k_gather2(
    const float* __restrict__ hw2, const float* __restrict__ hw3,
    float* __restrict__ mu, float* __restrict__ lv,
    const float* __restrict__ b2, const float* __restrict__ b3)
{
    __shared__ int   s_row[128];
    __shared__ float s_nrm[128];
    int c = blockIdx.x;
    int tid = threadIdx.x;
    int half = tid >> 6;               // 0: mu, 1: logvar
    int f = tid & 63;
    const float* hw = half ? hw3 : hw2;
    int beg = g_off[c], end = g_off[c + 1];

    float a0 = 0.f, a1 = 0.f, a2 = 0.f, a3 = 0.f;
    for (int base = beg; base < end; base += 128) {
        int len = min(128, end - base);
        if (tid < len) {
            s_row[tid] = g_csr_row[base + tid];
            s_nrm[tid] = g_csr_nrm[base + tid];
        }
        __syncthreads();
        int j = 0;
        for (; j + 3 < len; j += 4) {
            a0 += s_nrm[j + 0] * hw[(size_t)s_row[j + 0] * H2 + f];
            a1 += s_nrm[j + 1] * hw[(size_t)s_row[j + 1] * H2 + f];
            a2 += s_nrm[j + 2] * hw[(size_t)s_row[j + 2] * H2 + f];
            a3 += s_nrm[j + 3] * hw[(size_t)s_row[j + 3] * H2 + f];
        }
        for (; j < len; j++)
            a0 += s_nrm[j] * hw[(size_t)s_row[j] * H2 + f];
        __syncthreads();
    }
    float v = (a0 + a1) + (a2 + a3);
    if (half == 0) mu[(size_t)c * H2 + f] = v + b2[f];
    else           lv[(size_t)c * H2 + f] = v + b3[f];
}

// ---------------- adj = Z @ Z^T, packed f32x2 FFMA ---------------------------
__device__ __forceinline__ ull pk2(float lo, float hi) {
    ull r; asm("mov.b64 %0, {%1, %2};" : "=l"(r) : "f"(lo), "f"(hi)); return r;
}
__device__ __forceinline__ void ffma2(ull& d, ull a, ull b) {
    asm("fma.rn.f32x2 %0, %1, %2, %0;" : "+l"(d) : "l"(a), "l"(b));
}
__device__ __forceinline__ float2 upk(ull v) {
    float2 f; asm("mov.b64 {%0, %1}, %2;" : "=f"(f.x), "=f"(f.y) : "l"(v)); return f;
}

#define ADJ_PAD 132
#define ADJ_SMEM (2 * 64 * ADJ_PAD * 4)

__global__ __launch_bounds__(256, 2) void k_adj(const float* __restrict__ Z,
                                                float* __restrict__ C, int n) {
    extern __shared__ float sm[];
    float* As = sm;                      // [64][ADJ_PAD], As[k*PAD + r] = Z[bi+r][k]
    float* Bs = sm + 64 * ADJ_PAD;
    int bi = blockIdx.y * 128, bj = blockIdx.x * 128;
    int tid = threadIdx.x;               // 1-D block of 256
    int tx = tid & 15, ty = tid >> 4;

    #pragma unroll
    for (int i = tid; i < 128 * 16; i += 256) {
        int r = i >> 4, c = i & 15;
        float4 va = (bi + r < n) ? *(const float4*)&Z[(size_t)(bi + r) * H2 + 4 * c]
                                 : make_float4(0.f, 0.f, 0.f, 0.f);
        float4 vb = (bj + r < n) ? *(const float4*)&Z[(size_t)(bj + r) * H2 + 4 * c]
                                 : make_float4(0.f, 0.f, 0.f, 0.f);
        As[(4 * c + 0) * ADJ_PAD + r] = va.x;
        As[(4 * c + 1) * ADJ_PAD + r] = va.y;
        As[(4 * c + 2) * ADJ_PAD + r] = va.z;
        As[(4 * c + 3) * ADJ_PAD + r] = va.w;
        Bs[(4 * c + 0) * ADJ_PAD + r] = vb.x;
        Bs[(4 * c + 1) * ADJ_PAD + r] = vb.y;
        Bs[(4 * c + 2) * ADJ_PAD + r] = vb.z;
        Bs[(4 * c + 3) * ADJ_PAD + r] = vb.w;
    }
    __syncthreads();

    ull acc[8][4] = {};
    #pragma unroll 8
    for (int k = 0; k < 64; k++) {
        float4 a0 = *(const float4*)&As[k * ADJ_PAD + 8 * ty];
        float4 a1 = *(const float4*)&As[k * ADJ_PAD + 8 * ty + 4];
        // b pairs are adjacent in smem: load directly as packed 64-bit words
        const ull* bp = (const ull*)&Bs[k * ADJ_PAD + 8 * tx];
        ull bp0 = bp[0], bp1 = bp[1], bp2 = bp[2], bp3 = bp[3];
        float av[8] = {a0.x, a0.y, a0.z, a0.w, a1.x, a1.y, a1.z, a1.w};
        #pragma unroll
        for (int i = 0; i < 8; i++) {
            ull ap = pk2(av[i], av[i]);
            ffma2(acc[i][0], ap, bp0);
            ffma2(acc[i][1], ap, bp1);
            ffma2(acc[i][2], ap, bp2);
            ffma2(acc[i][3], ap, bp3);
        }
    }

    int gn = bj + 8 * tx;
    #pragma unroll
    for (int i = 0; i < 8; i++) {
        int gm = bi + 8 * ty + i;
        if (gm >= n) continue;
        float2 p0 = upk(acc[i][0]), p1 = upk(acc[i][1]);
        float2 p2 = upk(acc[i][2]), p3 = upk(acc[i][3]);
        float* cp = &C[(size_t)gm * n + gn];
        if (gn + 7 < n) {
            *(float4*)(cp + 0) = make_float4(p0.x, p0.y, p1.x, p1.y);
            *(float4*)(cp + 4) = make_float4(p2.x, p2.y, p3.x, p3.y);
        } else {
            float v[8] = {p0.x, p0.y, p1.x, p1.y, p2.x, p2.y, p3.x, p3.y};
            #pragma unroll
            for (int j = 0; j < 8; j++)
                if (gn + j < n) cp[j] = v[j];
        }
    }
}

// ---------------- launch ------------------------------------------------------
extern "C" void kernel_launch(void* const* d_in, const int* in_sizes, int n_in,
                              void* d_out, int out_size) {
    const float* x   = (const float*)d_in[0];
    const void*  ei  = d_in[1];                 // edge_index [2,E], int64 or int32
    const float* ew  = (const float*)d_in[2];
    const float* W1  = (const float*)d_in[3];
    const float* b1  = (const float*)d_in[4];
    const float* W2  = (const float*)d_in[5];
    const float* b2  = (const float*)d_in[6];
    const float* W3  = (const float*)d_in[7];
    const float* b3  = (const float*)d_in[8];

    const int n = N_NODES;
    const int E = in_sizes[1] / 2;

    float* adj    = (float*)d_out;                                  // [N,N]
    float* mu     = (float*)d_out + (size_t)n * n;                  // [N,H2]
    float* logvar = mu + (size_t)n * H2;                            // [N,H2]

    float* g_hw1_p; cudaGetSymbolAddress((void**)&g_hw1_p, g_hw1);
    float* g_h1_p;  cudaGetSymbolAddress((void**)&g_h1_p,  g_h1);
    float* g_hw2_p; cudaGetSymbolAddress((void**)&g_hw2_p, g_hw2);
    float* g_hw3_p; cudaGetSymbolAddress((void**)&g_hw3_p, g_hw3);

    static int s_attr_set = 0;
    if (!s_attr_set) {
        cudaFuncSetAttribute(k_adj, cudaFuncAttributeMaxDynamicSharedMemorySize, ADJ_SMEM);
        s_attr_set = 1;
    }

    const int T = 256;

    // 0. index width detection
    k_detect_idx<<<1, 32>>>(ei, E, n);

    // 1. GCN normalization + CSR build (grouped by destination col)
    k_init_deg<<<(n + T - 1) / T, T>>>(n);
    k_deg_accum<<<(E + T - 1) / T, T>>>(ei, ew, E);
    k_dis<<<(n + T - 1) / T, T>>>(n);
    k_scan<<<1, 1024>>>(n);
    k_scatter<<<(E + n + T - 1) / T, T>>>(ei, ew, E, n);

    dim3 blk(16, 16);

    // 2. layer 1: hw1 = x @ W1 ; h1 = relu(gather(hw1) + b1)
    k_sgemm<<<dim3(H1 / 64, (n + 63) / 64), blk>>>(x, W1, g_hw1_p, n, F_IN, H1);
    k_gather1<<<n, 128>>>(g_hw1_p, g_h1_p, b1);

    // 3. layer 2: mu / logvar (fused gather)
    k_sgemm<<<dim3(H2 / 64, (n + 63) / 64), blk>>>(g_h1_p, W2, g_hw2_p, n, H1, H2);
    k_sgemm<<<dim3(H2 / 64, (n + 63) / 64), blk>>>(g_h1_p, W3, g_hw3_p, n, H1, H2);
    k_gather2<<<n, 128>>>(g_hw2_p, g_hw3_p, mu, logvar, b2, b3);

    // 4. adj = mu @ mu^T (packed f32x2), 1-D 256-thread block
    k_adj<<<dim3((n + 127) / 128, (n + 127) / 128), 256, ADJ_SMEM>>>(mu, adj, n);
}

// round 8
// speedup vs baseline: 1.7882x; 1.3046x over previous
#include <cuda_runtime.h>
#include <cuda_bf16.h>
#include <cstdint>

#define N_NODES 10000
#define F_IN    256
#define H1      128
#define H2      64
#define E_MAX   320000
#define CSR_MAX (E_MAX + N_NODES)
#define KSPLIT  192
#define BPAD    200     // bf16 row stride in smem (100 words; conflict-free frags)

typedef unsigned long long ull;

// ---------------- scratch (static device globals; no allocation) ------------
__device__ float g_deg[N_NODES];
__device__ float g_dis[N_NODES];
__device__ int   g_cnt[N_NODES];
__device__ int   g_off[N_NODES + 1];
__device__ int   g_fill[N_NODES];
__device__ int   g_csr_row[CSR_MAX];
__device__ float g_csr_nrm[CSR_MAX];
__device__ float g_hw1[N_NODES * H1];
__device__ float g_h1 [N_NODES * H1];
__device__ float g_hw2[N_NODES * H2];
__device__ float g_hw3[N_NODES * H2];
__device__ __align__(16) __nv_bfloat16 g_za[N_NODES * KSPLIT];
__device__ __align__(16) __nv_bfloat16 g_zb[N_NODES * KSPLIT];
__device__ int   g_is64;

// ---------------- int32/int64 edge-index detection --------------------------
__global__ void k_detect_idx(const void* ei, int E, int n) {
    if (blockIdx.x == 0 && threadIdx.x == 0) {
        const long long* p = (const long long*)ei;
        int is64 = 1;
        int m = E < 1024 ? E : 1024;
        for (int k = 0; k < m; k++) {
            long long v = p[k];
            if (v < 0 || v >= (long long)n) { is64 = 0; break; }
        }
        g_is64 = is64;
    }
}

__device__ __forceinline__ int edge_at(const void* ei, long long i) {
    if (g_is64) return (int)((const long long*)ei)[i];
    return ((const int*)ei)[i];
}

// ---------------- degree (weighted) + count histogram ------------------------
__global__ void k_init_deg(int n) {
    int i = blockIdx.x * blockDim.x + threadIdx.x;
    if (i < n) { g_deg[i] = 1.0f; g_cnt[i] = 1; }     // self-loop
}

__global__ void k_deg_accum(const void* ei, const float* __restrict__ w, int E) {
    int e = blockIdx.x * blockDim.x + threadIdx.x;
    if (e >= E) return;
    int c = edge_at(ei, (long long)E + e);            // col
    atomicAdd(&g_deg[c], w[e]);
    atomicAdd(&g_cnt[c], 1);
}

__global__ void k_dis(int n) {
    int i = blockIdx.x * blockDim.x + threadIdx.x;
    if (i < n) {
        float d = g_deg[i];
        g_dis[i] = (d > 0.0f) ? rsqrtf(d) : 0.0f;
    }
}

// ---------------- single-block exclusive prefix scan over g_cnt --------------
__global__ __launch_bounds__(1024) void k_scan(int n) {
    __shared__ int s[1024];
    __shared__ int carry;
    int tid = threadIdx.x;
    if (tid == 0) carry = 0;
    __syncthreads();
    for (int base = 0; base < n; base += 1024) {
        int v = (base + tid < n) ? g_cnt[base + tid] : 0;
        s[tid] = v;
        __syncthreads();
        #pragma unroll
        for (int off = 1; off < 1024; off <<= 1) {
            int t = (tid >= off) ? s[tid - off] : 0;
            __syncthreads();
            s[tid] += t;
            __syncthreads();
        }
        int excl = s[tid] - v + carry;
        if (base + tid < n) { g_off[base + tid] = excl; g_fill[base + tid] = excl; }
        __syncthreads();
        if (tid == 0) carry += s[1023];
        __syncthreads();
    }
    if (tid == 0) g_off[n] = carry;
}

// ---------------- scatter edges into CSR (grouped by col) --------------------
__global__ void k_scatter(const void* ei, const float* __restrict__ w, int E, int n) {
    int e = blockIdx.x * blockDim.x + threadIdx.x;
    if (e >= E + n) return;
    int r, c; float nv;
    if (e < E) {
        r = edge_at(ei, e);
        c = edge_at(ei, (long long)E + e);
        nv = g_dis[r] * w[e] * g_dis[c];
    } else {
        r = c = e - E;
        float d = g_dis[r];
        nv = d * d;
    }
    int pos = atomicAdd(&g_fill[c], 1);
    g_csr_row[pos] = r;
    g_csr_nrm[pos] = nv;
}

// ---------------- generic tiled SGEMM: C[MxNc] = A[MxK] @ B[KxNc] ------------
__global__ __launch_bounds__(256) void k_sgemm(
    const float* __restrict__ A, const float* __restrict__ B,
    float* __restrict__ C, int M, int K, int Nc)
{
    __shared__ float As[16][68];   // As[k][m]
    __shared__ float Bs[16][68];   // Bs[k][n]
    int bm = blockIdx.y * 64, bn = blockIdx.x * 64;
    int tx = threadIdx.x, ty = threadIdx.y;
    int tid = ty * 16 + tx;

    float acc[4][4] = {};
    for (int k0 = 0; k0 < K; k0 += 16) {
        #pragma unroll
        for (int i = tid; i < 1024; i += 256) {
            int m = i >> 4, k = i & 15;
            int gm = bm + m;
            As[k][m] = (gm < M) ? A[(size_t)gm * K + k0 + k] : 0.0f;
        }
        #pragma unroll
        for (int i = tid; i < 1024; i += 256) {
            int k = i >> 6, n = i & 63;
            Bs[k][n] = B[(size_t)(k0 + k) * Nc + bn + n];
        }
        __syncthreads();
        #pragma unroll
        for (int k = 0; k < 16; k++) {
            float4 a = *(const float4*)&As[k][4 * ty];
            float4 b = *(const float4*)&Bs[k][4 * tx];
            acc[0][0] += a.x * b.x; acc[0][1] += a.x * b.y; acc[0][2] += a.x * b.z; acc[0][3] += a.x * b.w;
            acc[1][0] += a.y * b.x; acc[1][1] += a.y * b.y; acc[1][2] += a.y * b.z; acc[1][3] += a.y * b.w;
            acc[2][0] += a.z * b.x; acc[2][1] += a.z * b.y; acc[2][2] += a.z * b.z; acc[2][3] += a.z * b.w;
            acc[3][0] += a.w * b.x; acc[3][1] += a.w * b.y; acc[3][2] += a.w * b.z; acc[3][3] += a.w * b.w;
        }
        __syncthreads();
    }
    #pragma unroll
    for (int i = 0; i < 4; i++) {
        int gm = bm + 4 * ty + i;
        if (gm < M) {
            float4 v = make_float4(acc[i][0], acc[i][1], acc[i][2], acc[i][3]);
            *(float4*)&C[(size_t)gm * Nc + bn + 4 * tx] = v;
        }
    }
}

// ---------------- CSR gather, layer 1: h1 = relu(agg(hw1) + b1) --------------
__global__ __launch_bounds__(128) void k_gather1(
    const float* __restrict__ hw, float* __restrict__ out,
    const float* __restrict__ bias)
{
    __shared__ int   s_row[128];
    __shared__ float s_nrm[128];
    int c = blockIdx.x;
    int tid = threadIdx.x;
    int beg = g_off[c], end = g_off[c + 1];

    float a0 = 0.f, a1 = 0.f, a2 = 0.f, a3 = 0.f;
    for (int base = beg; base < end; base += 128) {
        int len = min(128, end - base);
        if (tid < len) {
            s_row[tid] = g_csr_row[base + tid];
            s_nrm[tid] = g_csr_nrm[base + tid];
        }
        __syncthreads();
        int j = 0;
        for (; j + 3 < len; j += 4) {
            a0 += s_nrm[j + 0] * hw[(size_t)s_row[j + 0] * H1 + tid];
            a1 += s_nrm[j + 1] * hw[(size_t)s_row[j + 1] * H1 + tid];
            a2 += s_nrm[j + 2] * hw[(size_t)s_row[j + 2] * H1 + tid];
            a3 += s_nrm[j + 3] * hw[(size_t)s_row[j + 3] * H1 + tid];
        }
        for (; j < len; j++)
            a0 += s_nrm[j] * hw[(size_t)s_row[j] * H1 + tid];
        __syncthreads();
    }
    float v = (a0 + a1) + (a2 + a3) + bias[tid];
    out[(size_t)c * H1 + tid] = fmaxf(v, 0.0f);
}

// ---------------- CSR gather, fused mu/logvar --------------------------------
__global__ __launch_bounds__(128) void k_gather2(
    const float* __restrict__ hw2, const float* __restrict__ hw3,
    float* __restrict__ mu, float* __restrict__ lv,
    const float* __restrict__ b2, const float* __restrict__ b3)
{
    __shared__ int   s_row[128];
    __shared__ float s_nrm[128];
    int c = blockIdx.x;
    int tid = threadIdx.x;
    int half = tid >> 6;               // 0: mu, 1: logvar
    int f = tid & 63;
    const float* hw = half ? hw3 : hw2;
    int beg = g_off[c], end = g_off[c + 1];

    float a0 = 0.f, a1 = 0.f, a2 = 0.f, a3 = 0.f;
    for (int base = beg; base < end; base += 128) {
        int len = min(128, end - base);
        if (tid < len) {
            s_row[tid] = g_csr_row[base + tid];
            s_nrm[tid] = g_csr_nrm[base + tid];
        }
        __syncthreads();
        int j = 0;
        for (; j + 3 < len; j += 4) {
            a0 += s_nrm[j + 0] * hw[(size_t)s_row[j + 0] * H2 + f];
            a1 += s_nrm[j + 1] * hw[(size_t)s_row[j + 1] * H2 + f];
            a2 += s_nrm[j + 2] * hw[(size_t)s_row[j + 2] * H2 + f];
            a3 += s_nrm[j + 3] * hw[(size_t)s_row[j + 3] * H2 + f];
        }
        for (; j < len; j++)
            a0 += s_nrm[j] * hw[(size_t)s_row[j] * H2 + f];
        __syncthreads();
    }
    float v = (a0 + a1) + (a2 + a3);
    if (half == 0) mu[(size_t)c * H2 + f] = v + b2[f];
    else           lv[(size_t)c * H2 + f] = v + b3[f];
}

// ---------------- split-bf16 prep: ZA = [H|H|L], ZB = [H|L|H] ----------------
__global__ void k_split(const float* __restrict__ Z,
                        __nv_bfloat16* __restrict__ ZA,
                        __nv_bfloat16* __restrict__ ZB, int n) {
    int idx = blockIdx.x * blockDim.x + threadIdx.x;
    if (idx >= n * H2) return;
    int i = idx >> 6, k = idx & 63;
    float v = Z[idx];
    __nv_bfloat16 h = __float2bfloat16(v);
    __nv_bfloat16 l = __float2bfloat16(v - __bfloat162float(h));
    size_t base = (size_t)i * KSPLIT;
    ZA[base + k]       = h;
    ZA[base + 64 + k]  = h;
    ZA[base + 128 + k] = l;
    ZB[base + k]       = h;
    ZB[base + 64 + k]  = l;
    ZB[base + 128 + k] = h;
}

// ---------------- adj = ZA @ ZB^T via mma.sync bf16 (K=192) ------------------
// 128x128 CTA tile, 8 warps (2x4), warp tile 64x32, full K in smem.
#define ADJ2_SMEM (2 * 128 * BPAD * 2)

__global__ __launch_bounds__(256) void k_adj_mma(
    const __nv_bfloat16* __restrict__ ZA, const __nv_bfloat16* __restrict__ ZB,
    float* __restrict__ C, int n)
{
    extern __shared__ __nv_bfloat16 sm2[];
    __nv_bfloat16* As = sm2;              // [128][BPAD]
    __nv_bfloat16* Bs = sm2 + 128 * BPAD;
    const uint32_t* As32 = (const uint32_t*)As;
    const uint32_t* Bs32 = (const uint32_t*)Bs;
    int bi = blockIdx.y * 128, bj = blockIdx.x * 128;
    int tid = threadIdx.x, lane = tid & 31, warp = tid >> 5;
    int wm = warp >> 2, wn = warp & 3;    // 2 x 4 warp grid

    // prolog: 128 rows x 24 uint4 (24*8 = 192 bf16) each array
    const uint4 zero4 = make_uint4(0u, 0u, 0u, 0u);
    for (int i = tid; i < 128 * 24; i += 256) {
        int r = i / 24, c = i % 24;       // c in uint4 (8 bf16) units
        uint4 va = zero4, vb = zero4;
        if (bi + r < n) va = *(const uint4*)&ZA[(size_t)(bi + r) * KSPLIT + c * 8];
        if (bj + r < n) vb = *(const uint4*)&ZB[(size_t)(bj + r) * KSPLIT + c * 8];
        *(uint4*)&As[r * BPAD + c * 8] = va;
        *(uint4*)&Bs[r * BPAD + c * 8] = vb;
    }
    __syncthreads();

    float acc[4][4][4] = {};
    int mrow = wm * 64 + (lane >> 2);     // + im*16 (+8)
    int nrow = wn * 32 + (lane >> 2);     // + jn*8
    int kq = lane & 3;

    #pragma unroll
    for (int ks = 0; ks < KSPLIT / 16; ks++) {
        int kw = ks * 8 + kq;             // b32 word index within row
        uint32_t b[4][2];
        #pragma unroll
        for (int jn = 0; jn < 4; jn++) {
            int rb = (nrow + jn * 8) * (BPAD / 2);
            b[jn][0] = Bs32[rb + kw];
            b[jn][1] = Bs32[rb + kw + 4];
        }
        #pragma unroll
        for (int im = 0; im < 4; im++) {
            int ra = (mrow + im * 16) * (BPAD / 2);
            uint32_t a0 = As32[ra + kw];
            uint32_t a2 = As32[ra + kw + 4];
            uint32_t a1 = As32[ra + 8 * (BPAD / 2) + kw];
            uint32_t a3 = As32[ra + 8 * (BPAD / 2) + kw + 4];
            #pragma unroll
            for (int jn = 0; jn < 4; jn++) {
                asm volatile(
                    "mma.sync.aligned.m16n8k16.row.col.f32.bf16.bf16.f32 "
                    "{%0,%1,%2,%3}, {%4,%5,%6,%7}, {%8,%9}, {%0,%1,%2,%3};"
                    : "+f"(acc[im][jn][0]), "+f"(acc[im][jn][1]),
                      "+f"(acc[im][jn][2]), "+f"(acc[im][jn][3])
                    : "r"(a0), "r"(a1), "r"(a2), "r"(a3),
                      "r"(b[jn][0]), "r"(b[jn][1]));
            }
        }
    }

    #pragma unroll
    for (int im = 0; im < 4; im++) {
        int r0 = bi + wm * 64 + im * 16 + (lane >> 2);
        #pragma unroll
        for (int jn = 0; jn < 4; jn++) {
            int cc = bj + wn * 32 + jn * 8 + kq * 2;
            if (r0 < n) {
                if (cc + 1 < n)
                    *(float2*)&C[(size_t)r0 * n + cc] = make_float2(acc[im][jn][0], acc[im][jn][1]);
                else if (cc < n)
                    C[(size_t)r0 * n + cc] = acc[im][jn][0];
            }
            int r1 = r0 + 8;
            if (r1 < n) {
                if (cc + 1 < n)
                    *(float2*)&C[(size_t)r1 * n + cc] = make_float2(acc[im][jn][2], acc[im][jn][3]);
                else if (cc < n)
                    C[(size_t)r1 * n + cc] = acc[im][jn][2];
            }
        }
    }
}

// ---------------- launch ------------------------------------------------------
extern "C" void kernel_launch(void* const* d_in, const int* in_sizes, int n_in,
                              void* d_out, int out_size) {
    const float* x   = (const float*)d_in[0];
    const void*  ei  = d_in[1];                 // edge_index [2,E], int64 or int32
    const float* ew  = (const float*)d_in[2];
    const float* W1  = (const float*)d_in[3];
    const float* b1  = (const float*)d_in[4];
    const float* W2  = (const float*)d_in[5];
    const float* b2  = (const float*)d_in[6];
    const float* W3  = (const float*)d_in[7];
    const float* b3  = (const float*)d_in[8];

    const int n = N_NODES;
    const int E = in_sizes[1] / 2;

    float* adj    = (float*)d_out;                                  // [N,N]
    float* mu     = (float*)d_out + (size_t)n * n;                  // [N,H2]
    float* logvar = mu + (size_t)n * H2;                            // [N,H2]

    float* g_hw1_p; cudaGetSymbolAddress((void**)&g_hw1_p, g_hw1);
    float* g_h1_p;  cudaGetSymbolAddress((void**)&g_h1_p,  g_h1);
    float* g_hw2_p; cudaGetSymbolAddress((void**)&g_hw2_p, g_hw2);
    float* g_hw3_p; cudaGetSymbolAddress((void**)&g_hw3_p, g_hw3);
    __nv_bfloat16* g_za_p; cudaGetSymbolAddress((void**)&g_za_p, g_za);
    __nv_bfloat16* g_zb_p; cudaGetSymbolAddress((void**)&g_zb_p, g_zb);

    static int s_attr_set = 0;
    if (!s_attr_set) {
        cudaFuncSetAttribute(k_adj_mma, cudaFuncAttributeMaxDynamicSharedMemorySize, ADJ2_SMEM);
        s_attr_set = 1;
    }

    const int T = 256;

    // 0. index width detection
    k_detect_idx<<<1, 32>>>(ei, E, n);

    // 1. GCN normalization + CSR build (grouped by destination col)
    k_init_deg<<<(n + T - 1) / T, T>>>(n);
    k_deg_accum<<<(E + T - 1) / T, T>>>(ei, ew, E);
    k_dis<<<(n + T - 1) / T, T>>>(n);
    k_scan<<<1, 1024>>>(n);
    k_scatter<<<(E + n + T - 1) / T, T>>>(ei, ew, E, n);

    dim3 blk(16, 16);

    // 2. layer 1: hw1 = x @ W1 ; h1 = relu(gather(hw1) + b1)
    k_sgemm<<<dim3(H1 / 64, (n + 63) / 64), blk>>>(x, W1, g_hw1_p, n, F_IN, H1);
    k_gather1<<<n, 128>>>(g_hw1_p, g_h1_p, b1);

    // 3. layer 2: mu / logvar (fused gather)
    k_sgemm<<<dim3(H2 / 64, (n + 63) / 64), blk>>>(g_h1_p, W2, g_hw2_p, n, H1, H2);
    k_sgemm<<<dim3(H2 / 64, (n + 63) / 64), blk>>>(g_h1_p, W3, g_hw3_p, n, H1, H2);
    k_gather2<<<n, 128>>>(g_hw2_p, g_hw3_p, mu, logvar, b2, b3);

    // 4. adj = mu @ mu^T via split-bf16 tensor-core GEMM
    k_split<<<(n * H2 + T - 1) / T, T>>>(mu, g_za_p, g_zb_p, n);
    k_adj_mma<<<dim3((n + 127) / 128, (n + 127) / 128), 256, ADJ2_SMEM>>>(
        g_za_p, g_zb_p, adj, n);
}

// round 9
// speedup vs baseline: 2.2809x; 1.2755x over previous
#include <cuda_runtime.h>
#include <cuda_bf16.h>
#include <cstdint>

#define N_NODES 10000
#define F_IN    256
#define H1      128
#define H2      64
#define E_MAX   320000
#define CSR_MAX (E_MAX + N_NODES)
#define KSPLIT  192
#define BPAD    200     // bf16 row stride in smem (400 B)

typedef unsigned long long ull;

// ---------------- scratch (static device globals; no allocation) ------------
__device__ float g_deg[N_NODES];
__device__ float g_dis[N_NODES];
__device__ int   g_cnt[N_NODES];
__device__ int   g_off[N_NODES + 1];
__device__ int   g_fill[N_NODES];
__device__ int   g_csr_row[CSR_MAX];
__device__ float g_csr_nrm[CSR_MAX];
__device__ float g_hw1[N_NODES * H1];
__device__ float g_h1 [N_NODES * H1];
__device__ float g_w23[H1 * 128];
__device__ float g_hw23[N_NODES * 128];
__device__ __align__(16) __nv_bfloat16 g_za[N_NODES * KSPLIT];
__device__ __align__(16) __nv_bfloat16 g_zb[N_NODES * KSPLIT];
__device__ int   g_is64;

// ---------------- int32/int64 edge-index detection --------------------------
__global__ void k_detect_idx(const void* ei, int E, int n) {
    if (blockIdx.x == 0 && threadIdx.x == 0) {
        const long long* p = (const long long*)ei;
        int is64 = 1;
        int m = E < 1024 ? E : 1024;
        for (int k = 0; k < m; k++) {
            long long v = p[k];
            if (v < 0 || v >= (long long)n) { is64 = 0; break; }
        }
        g_is64 = is64;
    }
}

__device__ __forceinline__ int edge_at(const void* ei, long long i) {
    if (g_is64) return (int)((const long long*)ei)[i];
    return ((const int*)ei)[i];
}

// ---------------- degree (weighted) + count histogram ------------------------
__global__ void k_init_deg(int n) {
    int i = blockIdx.x * blockDim.x + threadIdx.x;
    if (i < n) { g_deg[i] = 1.0f; g_cnt[i] = 1; }     // self-loop
}

__global__ void k_deg_accum(const void* ei, const float* __restrict__ w, int E) {
    int e = blockIdx.x * blockDim.x + threadIdx.x;
    if (e >= E) return;
    int c = edge_at(ei, (long long)E + e);            // col
    atomicAdd(&g_deg[c], w[e]);
    atomicAdd(&g_cnt[c], 1);
}

__global__ void k_dis(int n) {
    int i = blockIdx.x * blockDim.x + threadIdx.x;
    if (i < n) {
        float d = g_deg[i];
        g_dis[i] = (d > 0.0f) ? rsqrtf(d) : 0.0f;
    }
}

// ---------------- single-block exclusive prefix scan over g_cnt --------------
__global__ __launch_bounds__(1024) void k_scan(int n) {
    __shared__ int s[1024];
    __shared__ int carry;
    int tid = threadIdx.x;
    if (tid == 0) carry = 0;
    __syncthreads();
    for (int base = 0; base < n; base += 1024) {
        int v = (base + tid < n) ? g_cnt[base + tid] : 0;
        s[tid] = v;
        __syncthreads();
        #pragma unroll
        for (int off = 1; off < 1024; off <<= 1) {
            int t = (tid >= off) ? s[tid - off] : 0;
            __syncthreads();
            s[tid] += t;
            __syncthreads();
        }
        int excl = s[tid] - v + carry;
        if (base + tid < n) { g_off[base + tid] = excl; g_fill[base + tid] = excl; }
        __syncthreads();
        if (tid == 0) carry += s[1023];
        __syncthreads();
    }
    if (tid == 0) g_off[n] = carry;
}

// ---------------- scatter edges into CSR (grouped by col) --------------------
__global__ void k_scatter(const void* ei, const float* __restrict__ w, int E, int n) {
    int e = blockIdx.x * blockDim.x + threadIdx.x;
    if (e >= E + n) return;
    int r, c; float nv;
    if (e < E) {
        r = edge_at(ei, e);
        c = edge_at(ei, (long long)E + e);
        nv = g_dis[r] * w[e] * g_dis[c];
    } else {
        r = c = e - E;
        float d = g_dis[r];
        nv = d * d;
    }
    int pos = atomicAdd(&g_fill[c], 1);
    g_csr_row[pos] = r;
    g_csr_nrm[pos] = nv;
}

// ---------------- pack W2|W3 into one [H1,128] weight ------------------------
__global__ void k_pack_w23(const float* __restrict__ W2, const float* __restrict__ W3,
                           float* __restrict__ W23) {
    int i = blockIdx.x * blockDim.x + threadIdx.x;
    if (i >= H1 * 64) return;
    int k = i >> 6, j = i & 63;
    W23[k * 128 + j]      = W2[i];
    W23[k * 128 + 64 + j] = W3[i];
}

// ---------------- generic tiled SGEMM: C[MxNc] = A[MxK] @ B[KxNc] ------------
__global__ __launch_bounds__(256) void k_sgemm(
    const float* __restrict__ A, const float* __restrict__ B,
    float* __restrict__ C, int M, int K, int Nc)
{
    __shared__ float As[16][68];   // As[k][m]
    __shared__ float Bs[16][68];   // Bs[k][n]
    int bm = blockIdx.y * 64, bn = blockIdx.x * 64;
    int tx = threadIdx.x, ty = threadIdx.y;
    int tid = ty * 16 + tx;

    float acc[4][4] = {};
    for (int k0 = 0; k0 < K; k0 += 16) {
        #pragma unroll
        for (int i = tid; i < 1024; i += 256) {
            int m = i >> 4, k = i & 15;
            int gm = bm + m;
            As[k][m] = (gm < M) ? A[(size_t)gm * K + k0 + k] : 0.0f;
        }
        #pragma unroll
        for (int i = tid; i < 1024; i += 256) {
            int k = i >> 6, n = i & 63;
            Bs[k][n] = B[(size_t)(k0 + k) * Nc + bn + n];
        }
        __syncthreads();
        #pragma unroll
        for (int k = 0; k < 16; k++) {
            float4 a = *(const float4*)&As[k][4 * ty];
            float4 b = *(const float4*)&Bs[k][4 * tx];
            acc[0][0] += a.x * b.x; acc[0][1] += a.x * b.y; acc[0][2] += a.x * b.z; acc[0][3] += a.x * b.w;
            acc[1][0] += a.y * b.x; acc[1][1] += a.y * b.y; acc[1][2] += a.y * b.z; acc[1][3] += a.y * b.w;
            acc[2][0] += a.z * b.x; acc[2][1] += a.z * b.y; acc[2][2] += a.z * b.z; acc[2][3] += a.z * b.w;
            acc[3][0] += a.w * b.x; acc[3][1] += a.w * b.y; acc[3][2] += a.w * b.z; acc[3][3] += a.w * b.w;
        }
        __syncthreads();
    }
    #pragma unroll
    for (int i = 0; i < 4; i++) {
        int gm = bm + 4 * ty + i;
        if (gm < M) {
            float4 v = make_float4(acc[i][0], acc[i][1], acc[i][2], acc[i][3]);
            *(float4*)&C[(size_t)gm * Nc + bn + 4 * tx] = v;
        }
    }
}

// ---------------- CSR gather, layer 1: h1 = relu(agg(hw1) + b1) --------------
__global__ __launch_bounds__(128) void k_gather1(
    const float* __restrict__ hw, float* __restrict__ out,
    const float* __restrict__ bias)
{
    __shared__ int   s_row[128];
    __shared__ float s_nrm[128];
    int c = blockIdx.x;
    int tid = threadIdx.x;
    int beg = g_off[c], end = g_off[c + 1];

    float a0 = 0.f, a1 = 0.f, a2 = 0.f, a3 = 0.f;
    for (int base = beg; base < end; base += 128) {
        int len = min(128, end - base);
        if (tid < len) {
            s_row[tid] = g_csr_row[base + tid];
            s_nrm[tid] = g_csr_nrm[base + tid];
        }
        __syncthreads();
        int j = 0;
        for (; j + 3 < len; j += 4) {
            a0 += s_nrm[j + 0] * hw[(size_t)s_row[j + 0] * H1 + tid];
            a1 += s_nrm[j + 1] * hw[(size_t)s_row[j + 1] * H1 + tid];
            a2 += s_nrm[j + 2] * hw[(size_t)s_row[j + 2] * H1 + tid];
            a3 += s_nrm[j + 3] * hw[(size_t)s_row[j + 3] * H1 + tid];
        }
        for (; j < len; j++)
            a0 += s_nrm[j] * hw[(size_t)s_row[j] * H1 + tid];
        __syncthreads();
    }
    float v = (a0 + a1) + (a2 + a3) + bias[tid];
    out[(size_t)c * H1 + tid] = fmaxf(v, 0.0f);
}

// ---------------- CSR gather, fused mu/logvar from combined hw23 -------------
// hw23: [N,128]  cols 0..63 = h1@W2, cols 64..127 = h1@W3
__global__ __launch_bounds__(128) void k_gather2(
    const float* __restrict__ hw23,
    float* __restrict__ mu, float* __restrict__ lv,
    const float* __restrict__ b2, const float* __restrict__ b3)
{
    __shared__ int   s_row[128];
    __shared__ float s_nrm[128];
    int c = blockIdx.x;
    int tid = threadIdx.x;
    int half = tid >> 6;               // 0: mu, 1: logvar
    int f = tid & 63;
    int col = tid;                     // half*64 + f
    int beg = g_off[c], end = g_off[c + 1];

    float a0 = 0.f, a1 = 0.f, a2 = 0.f, a3 = 0.f;
    for (int base = beg; base < end; base += 128) {
        int len = min(128, end - base);
        if (tid < len) {
            s_row[tid] = g_csr_row[base + tid];
            s_nrm[tid] = g_csr_nrm[base + tid];
        }
        __syncthreads();
        int j = 0;
        for (; j + 3 < len; j += 4) {
            a0 += s_nrm[j + 0] * hw23[(size_t)s_row[j + 0] * 128 + col];
            a1 += s_nrm[j + 1] * hw23[(size_t)s_row[j + 1] * 128 + col];
            a2 += s_nrm[j + 2] * hw23[(size_t)s_row[j + 2] * 128 + col];
            a3 += s_nrm[j + 3] * hw23[(size_t)s_row[j + 3] * 128 + col];
        }
        for (; j < len; j++)
            a0 += s_nrm[j] * hw23[(size_t)s_row[j] * 128 + col];
        __syncthreads();
    }
    float v = (a0 + a1) + (a2 + a3);
    if (half == 0) mu[(size_t)c * H2 + f] = v + b2[f];
    else           lv[(size_t)c * H2 + f] = v + b3[f];
}

// ---------------- split-bf16 prep: ZA = [H|H|L], ZB = [H|L|H] ----------------
__global__ void k_split(const float* __restrict__ Z,
                        __nv_bfloat16* __restrict__ ZA,
                        __nv_bfloat16* __restrict__ ZB, int n) {
    int idx = blockIdx.x * blockDim.x + threadIdx.x;
    if (idx >= n * H2) return;
    int i = idx >> 6, k = idx & 63;
    float v = Z[idx];
    __nv_bfloat16 h = __float2bfloat16(v);
    __nv_bfloat16 l = __float2bfloat16(v - __bfloat162float(h));
    size_t base = (size_t)i * KSPLIT;
    ZA[base + k]       = h;
    ZA[base + 64 + k]  = h;
    ZA[base + 128 + k] = l;
    ZB[base + k]       = h;
    ZB[base + 64 + k]  = l;
    ZB[base + 128 + k] = h;
}

// ---------------- adj = ZA @ ZB^T, symmetric, ldmatrix + mma.sync bf16 -------
// Upper-triangular tile grid; off-diagonal tiles mirror-stored via smem transpose.
#define ADJ2_SMEM (2 * 128 * BPAD * 2)

__device__ __forceinline__ void ldsm_x4(uint32_t& r0, uint32_t& r1,
                                        uint32_t& r2, uint32_t& r3, uint32_t addr) {
    asm volatile("ldmatrix.sync.aligned.m8n8.x4.shared.b16 {%0,%1,%2,%3}, [%4];"
                 : "=r"(r0), "=r"(r1), "=r"(r2), "=r"(r3) : "r"(addr));
}

__global__ __launch_bounds__(256) void k_adj_mma(
    const __nv_bfloat16* __restrict__ ZA, const __nv_bfloat16* __restrict__ ZB,
    float* __restrict__ C, int n, int mtiles)
{
    extern __shared__ __nv_bfloat16 sm2[];
    __nv_bfloat16* As = sm2;              // [128][BPAD]
    __nv_bfloat16* Bs = sm2 + 128 * BPAD;
    float* S = (float*)sm2;               // staging reuse: [128][132] fp32

    // triangular decode: blockIdx.x -> (ti, tj), ti <= tj
    int ti = 0, rem = blockIdx.x;
    while (rem >= mtiles - ti) { rem -= mtiles - ti; ti++; }
    int tj = ti + rem;
    int bi = ti * 128, bj = tj * 128;

    int tid = threadIdx.x, lane = tid & 31, warp = tid >> 5;
    int wm = warp >> 2, wn = warp & 3;    // 2 x 4 warp grid

    // prolog: 128 rows x 24 uint4 (192 bf16) each array
    const uint4 zero4 = make_uint4(0u, 0u, 0u, 0u);
    for (int i = tid; i < 128 * 24; i += 256) {
        int r = i / 24, c = i % 24;
        uint4 va = zero4, vb = zero4;
        if (bi + r < n) va = *(const uint4*)&ZA[(size_t)(bi + r) * KSPLIT + c * 8];
        if (bj + r < n) vb = *(const uint4*)&ZB[(size_t)(bj + r) * KSPLIT + c * 8];
        *(uint4*)&As[r * BPAD + c * 8] = va;
        *(uint4*)&Bs[r * BPAD + c * 8] = vb;
    }
    __syncthreads();

    // ldmatrix lane addressing (byte addresses in shared space)
    uint32_t as_u32 = (uint32_t)__cvta_generic_to_shared(As);
    uint32_t bs_u32 = (uint32_t)__cvta_generic_to_shared(Bs);
    int l7 = lane & 7, lb3 = (lane >> 3) & 1, lb4 = lane >> 4;
    // A x4: m0 rows0-7@k0 | m1 rows8-15@k0 | m2 rows0-7@k8 | m3 rows8-15@k8
    uint32_t a_addr[4];
    #pragma unroll
    for (int im = 0; im < 4; im++)
        a_addr[im] = as_u32 +
            (uint32_t)((wm * 64 + im * 16 + lb3 * 8 + l7) * BPAD) * 2 + lb4 * 16;
    // B x4 (two n8 tiles): m0 tile p0 rows@k0 | m1 tile p0 rows@k8 | m2 tile p1 @k0 | m3 tile p1 @k8
    uint32_t b_addr[2];
    #pragma unroll
    for (int p = 0; p < 2; p++)
        b_addr[p] = bs_u32 +
            (uint32_t)((wn * 32 + p * 16 + lb4 * 8 + l7) * BPAD) * 2 + lb3 * 16;

    float acc[4][4][4] = {};
    #pragma unroll
    for (int ks = 0; ks < KSPLIT / 16; ks++) {
        uint32_t koff = ks * 32;          // 16 bf16 = 32 bytes
        uint32_t b[4][2];
        ldsm_x4(b[0][0], b[0][1], b[1][0], b[1][1], b_addr[0] + koff);
        ldsm_x4(b[2][0], b[2][1], b[3][0], b[3][1], b_addr[1] + koff);
        #pragma unroll
        for (int im = 0; im < 4; im++) {
            uint32_t a0, a1, a2, a3;
            ldsm_x4(a0, a1, a2, a3, a_addr[im] + koff);
            #pragma unroll
            for (int jn = 0; jn < 4; jn++) {
                asm volatile(
                    "mma.sync.aligned.m16n8k16.row.col.f32.bf16.bf16.f32 "
                    "{%0,%1,%2,%3}, {%4,%5,%6,%7}, {%8,%9}, {%0,%1,%2,%3};"
                    : "+f"(acc[im][jn][0]), "+f"(acc[im][jn][1]),
                      "+f"(acc[im][jn][2]), "+f"(acc[im][jn][3])
                    : "r"(a0), "r"(a1), "r"(a2), "r"(a3),
                      "r"(b[jn][0]), "r"(b[jn][1]));
            }
        }
    }

    int kq = lane & 3;
    // direct store of tile (bi, bj)
    #pragma unroll
    for (int im = 0; im < 4; im++) {
        int r0 = bi + wm * 64 + im * 16 + (lane >> 2);
        #pragma unroll
        for (int jn = 0; jn < 4; jn++) {
            int cc = bj + wn * 32 + jn * 8 + kq * 2;
            if (r0 < n) {
                if (cc + 1 < n)
                    *(float2*)&C[(size_t)r0 * n + cc] = make_float2(acc[im][jn][0], acc[im][jn][1]);
                else if (cc < n)
                    C[(size_t)r0 * n + cc] = acc[im][jn][0];
            }
            int r1 = r0 + 8;
            if (r1 < n) {
                if (cc + 1 < n)
                    *(float2*)&C[(size_t)r1 * n + cc] = make_float2(acc[im][jn][2], acc[im][jn][3]);
                else if (cc < n)
                    C[(size_t)r1 * n + cc] = acc[im][jn][2];
            }
        }
    }

    // mirror store of tile (bj, bi) via smem transpose staging
    if (ti != tj) {
        __syncthreads();                  // done reading As/Bs
        int rbase = wm * 64 + (lane >> 2);
        int cbase = wn * 32 + kq * 2;
        #pragma unroll
        for (int im = 0; im < 4; im++) {
            int r = rbase + im * 16;
            #pragma unroll
            for (int jn = 0; jn < 4; jn++) {
                int c = cbase + jn * 8;
                S[(c + 0) * 132 + r]     = acc[im][jn][0];
                S[(c + 1) * 132 + r]     = acc[im][jn][1];
                S[(c + 0) * 132 + r + 8] = acc[im][jn][2];
                S[(c + 1) * 132 + r + 8] = acc[im][jn][3];
            }
        }
        __syncthreads();
        // rows of mirror tile = columns of original; cols bi+0..127 always < n (ti < tj)
        #pragma unroll
        for (int rr = warp * 16; rr < warp * 16 + 16; rr++) {
            int grow = bj + rr;
            if (grow < n) {
                float4 v = *(const float4*)&S[rr * 132 + lane * 4];
                *(float4*)&C[(size_t)grow * n + bi + lane * 4] = v;
            }
        }
    }
}

// ---------------- launch ------------------------------------------------------
extern "C" void kernel_launch(void* const* d_in, const int* in_sizes, int n_in,
                              void* d_out, int out_size) {
    const float* x   = (const float*)d_in[0];
    const void*  ei  = d_in[1];                 // edge_index [2,E], int64 or int32
    const float* ew  = (const float*)d_in[2];
    const float* W1  = (const float*)d_in[3];
    const float* b1  = (const float*)d_in[4];
    const float* W2  = (const float*)d_in[5];
    const float* b2  = (const float*)d_in[6];
    const float* W3  = (const float*)d_in[7];
    const float* b3  = (const float*)d_in[8];

    const int n = N_NODES;
    const int E = in_sizes[1] / 2;

    float* adj    = (float*)d_out;                                  // [N,N]
    float* mu     = (float*)d_out + (size_t)n * n;                  // [N,H2]
    float* logvar = mu + (size_t)n * H2;                            // [N,H2]

    float* g_hw1_p;  cudaGetSymbolAddress((void**)&g_hw1_p,  g_hw1);
    float* g_h1_p;   cudaGetSymbolAddress((void**)&g_h1_p,   g_h1);
    float* g_w23_p;  cudaGetSymbolAddress((void**)&g_w23_p,  g_w23);
    float* g_hw23_p; cudaGetSymbolAddress((void**)&g_hw23_p, g_hw23);
    __nv_bfloat16* g_za_p; cudaGetSymbolAddress((void**)&g_za_p, g_za);
    __nv_bfloat16* g_zb_p; cudaGetSymbolAddress((void**)&g_zb_p, g_zb);

    static int s_attr_set = 0;
    if (!s_attr_set) {
        cudaFuncSetAttribute(k_adj_mma, cudaFuncAttributeMaxDynamicSharedMemorySize, ADJ2_SMEM);
        s_attr_set = 1;
    }

    const int T = 256;

    // 0. index width detection
    k_detect_idx<<<1, 32>>>(ei, E, n);

    // 1. GCN normalization + CSR build (grouped by destination col)
    k_init_deg<<<(n + T - 1) / T, T>>>(n);
    k_deg_accum<<<(E + T - 1) / T, T>>>(ei, ew, E);
    k_dis<<<(n + T - 1) / T, T>>>(n);
    k_scan<<<1, 1024>>>(n);
    k_scatter<<<(E + n + T - 1) / T, T>>>(ei, ew, E, n);

    dim3 blk(16, 16);

    // 2. layer 1: hw1 = x @ W1 ; h1 = relu(gather(hw1) + b1)
    k_sgemm<<<dim3(H1 / 64, (n + 63) / 64), blk>>>(x, W1, g_hw1_p, n, F_IN, H1);
    k_gather1<<<n, 128>>>(g_hw1_p, g_h1_p, b1);

    // 3. layer 2: one fused [H1,128] gemm for W2|W3, then fused gather
    k_pack_w23<<<(H1 * 64 + T - 1) / T, T>>>(W2, W3, g_w23_p);
    k_sgemm<<<dim3(2, (n + 63) / 64), blk>>>(g_h1_p, g_w23_p, g_hw23_p, n, H1, 128);
    k_gather2<<<n, 128>>>(g_hw23_p, mu, logvar, b2, b3);

    // 4. adj = mu @ mu^T via split-bf16 tensor-core GEMM (triangular + mirror)
    k_split<<<(n * H2 + T - 1) / T, T>>>(mu, g_za_p, g_zb_p, n);
    int mtiles = (n + 127) / 128;
    k_adj_mma<<<mtiles * (mtiles + 1) / 2, 256, ADJ2_SMEM>>>(
        g_za_p, g_zb_p, adj, n, mtiles);
}

// round 13
// speedup vs baseline: 2.4974x; 1.0949x over previous
#include <cuda_runtime.h>
#include <cuda_bf16.h>
#include <cstdint>

#define N_NODES 10000
#define F_IN    256
#define H1      128
#define H2      64
#define E_MAX   320000
#define CSR_MAX (E_MAX + N_NODES)
#define KSPLIT  192
#define BPAD    200     // bf16 row stride in smem (400 B)

typedef unsigned long long ull;

// ---------------- scratch (static device globals; no allocation) ------------
__device__ float g_deg[N_NODES];
__device__ float g_dis[N_NODES];
__device__ int   g_cnt[N_NODES];
__device__ int   g_off[N_NODES];
__device__ int   g_end[N_NODES];
__device__ int   g_fill[N_NODES];
__device__ int   g_total;
__device__ int   g_csr_row[CSR_MAX];
__device__ float g_csr_nrm[CSR_MAX];
__device__ float g_hw1[N_NODES * H1];
__device__ float g_h1 [N_NODES * H1];
__device__ float g_w23[H1 * 128];
__device__ float g_hw23[N_NODES * 128];
__device__ __align__(16) __nv_bfloat16 g_za[N_NODES * KSPLIT];
__device__ __align__(16) __nv_bfloat16 g_zb[N_NODES * KSPLIT];
__device__ int   g_is64;

// ---------------- int32/int64 edge-index detection --------------------------
__global__ void k_detect_idx(const void* ei, int E, int n) {
    if (blockIdx.x == 0 && threadIdx.x == 0) {
        const long long* p = (const long long*)ei;
        int is64 = 1;
        int m = E < 1024 ? E : 1024;
        for (int k = 0; k < m; k++) {
            long long v = p[k];
            if (v < 0 || v >= (long long)n) { is64 = 0; break; }
        }
        g_is64 = is64;
    }
}

__device__ __forceinline__ int edge_at(const void* ei, long long i) {
    if (g_is64) return (int)((const long long*)ei)[i];
    return ((const int*)ei)[i];
}

// ---------------- degree (weighted) + count histogram ------------------------
__global__ void k_init_deg(int n) {
    int i = blockIdx.x * blockDim.x + threadIdx.x;
    if (i == 0) g_total = 0;
    if (i < n) { g_deg[i] = 1.0f; g_cnt[i] = 1; }     // self-loop
}

__global__ void k_deg_accum(const void* ei, const float* __restrict__ w, int E) {
    int e = blockIdx.x * blockDim.x + threadIdx.x;
    if (e >= E) return;
    int c = edge_at(ei, (long long)E + e);            // col
    atomicAdd(&g_deg[c], w[e]);
    atomicAdd(&g_cnt[c], 1);
}

// dis + CSR range allocation (order-free contiguous chunks via atomic cursor)
__global__ void k_dis_alloc(int n) {
    int i = blockIdx.x * blockDim.x + threadIdx.x;
    if (i < n) {
        float d = g_deg[i];
        g_dis[i] = (d > 0.0f) ? rsqrtf(d) : 0.0f;
        int cnt = g_cnt[i];
        int pos = atomicAdd(&g_total, cnt);
        g_off[i]  = pos;
        g_end[i]  = pos + cnt;
        g_fill[i] = pos;
    }
}

// ---------------- scatter edges into CSR (grouped by col) --------------------
__global__ void k_scatter(const void* ei, const float* __restrict__ w, int E, int n) {
    int e = blockIdx.x * blockDim.x + threadIdx.x;
    if (e >= E + n) return;
    int r, c; float nv;
    if (e < E) {
        r = edge_at(ei, e);
        c = edge_at(ei, (long long)E + e);
        nv = g_dis[r] * w[e] * g_dis[c];
    } else {
        r = c = e - E;
        float d = g_dis[r];
        nv = d * d;
    }
    int pos = atomicAdd(&g_fill[c], 1);
    g_csr_row[pos] = r;
    g_csr_nrm[pos] = nv;
}

// ---------------- pack W2|W3 into one [H1,128] weight ------------------------
__global__ void k_pack_w23(const float* __restrict__ W2, const float* __restrict__ W3,
                           float* __restrict__ W23) {
    int i = blockIdx.x * blockDim.x + threadIdx.x;
    if (i >= H1 * 64) return;
    int k = i >> 6, j = i & 63;
    W23[k * 128 + j]      = W2[i];
    W23[k * 128 + 64 + j] = W3[i];
}

// ---------------- generic tiled SGEMM: C[MxNc] = A[MxK] @ B[KxNc] ------------
__global__ __launch_bounds__(256) void k_sgemm(
    const float* __restrict__ A, const float* __restrict__ B,
    float* __restrict__ C, int M, int K, int Nc)
{
    __shared__ float As[16][68];   // As[k][m]
    __shared__ float Bs[16][68];   // Bs[k][n]
    int bm = blockIdx.y * 64, bn = blockIdx.x * 64;
    int tx = threadIdx.x, ty = threadIdx.y;
    int tid = ty * 16 + tx;

    float acc[4][4] = {};
    for (int k0 = 0; k0 < K; k0 += 16) {
        #pragma unroll
        for (int i = tid; i < 1024; i += 256) {
            int m = i >> 4, k = i & 15;
            int gm = bm + m;
            As[k][m] = (gm < M) ? A[(size_t)gm * K + k0 + k] : 0.0f;
        }
        #pragma unroll
        for (int i = tid; i < 1024; i += 256) {
            int k = i >> 6, n = i & 63;
            Bs[k][n] = B[(size_t)(k0 + k) * Nc + bn + n];
        }
        __syncthreads();
        #pragma unroll
        for (int k = 0; k < 16; k++) {
            float4 a = *(const float4*)&As[k][4 * ty];
            float4 b = *(const float4*)&Bs[k][4 * tx];
            acc[0][0] += a.x * b.x; acc[0][1] += a.x * b.y; acc[0][2] += a.x * b.z; acc[0][3] += a.x * b.w;
            acc[1][0] += a.y * b.x; acc[1][1] += a.y * b.y; acc[1][2] += a.y * b.z; acc[1][3] += a.y * b.w;
            acc[2][0] += a.z * b.x; acc[2][1] += a.z * b.y; acc[2][2] += a.z * b.z; acc[2][3] += a.z * b.w;
            acc[3][0] += a.w * b.x; acc[3][1] += a.w * b.y; acc[3][2] += a.w * b.z; acc[3][3] += a.w * b.w;
        }
        __syncthreads();
    }
    #pragma unroll
    for (int i = 0; i < 4; i++) {
        int gm = bm + 4 * ty + i;
        if (gm < M) {
            float4 v = make_float4(acc[i][0], acc[i][1], acc[i][2], acc[i][3]);
            *(float4*)&C[(size_t)gm * Nc + bn + 4 * tx] = v;
        }
    }
}

// ---------------- CSR gather, layer 1: h1 = relu(agg(hw1) + b1) --------------
__global__ __launch_bounds__(128) void k_gather1(
    const float* __restrict__ hw, float* __restrict__ out,
    const float* __restrict__ bias)
{
    __shared__ int   s_row[128];
    __shared__ float s_nrm[128];
    int c = blockIdx.x;
    int tid = threadIdx.x;
    int beg = g_off[c], end = g_end[c];

    float a0 = 0.f, a1 = 0.f, a2 = 0.f, a3 = 0.f;
    for (int base = beg; base < end; base += 128) {
        int len = min(128, end - base);
        if (tid < len) {
            s_row[tid] = g_csr_row[base + tid];
            s_nrm[tid] = g_csr_nrm[base + tid];
        }
        __syncthreads();
        int j = 0;
        for (; j + 3 < len; j += 4) {
            a0 += s_nrm[j + 0] * hw[(size_t)s_row[j + 0] * H1 + tid];
            a1 += s_nrm[j + 1] * hw[(size_t)s_row[j + 1] * H1 + tid];
            a2 += s_nrm[j + 2] * hw[(size_t)s_row[j + 2] * H1 + tid];
            a3 += s_nrm[j + 3] * hw[(size_t)s_row[j + 3] * H1 + tid];
        }
        for (; j < len; j++)
            a0 += s_nrm[j] * hw[(size_t)s_row[j] * H1 + tid];
        __syncthreads();
    }
    float v = (a0 + a1) + (a2 + a3) + bias[tid];
    out[(size_t)c * H1 + tid] = fmaxf(v, 0.0f);
}

// ---------------- CSR gather, fused mu/logvar + bf16 split -------------------
// hw23: [N,128] cols 0..63 = h1@W2, 64..127 = h1@W3.
// mu half also emits split-bf16 rows ZA=[H|H|L], ZB=[H|L|H].
__global__ __launch_bounds__(128) void k_gather2(
    const float* __restrict__ hw23,
    float* __restrict__ mu, float* __restrict__ lv,
    const float* __restrict__ b2, const float* __restrict__ b3,
    __nv_bfloat16* __restrict__ ZA, __nv_bfloat16* __restrict__ ZB)
{
    __shared__ int   s_row[128];
    __shared__ float s_nrm[128];
    int c = blockIdx.x;
    int tid = threadIdx.x;
    int half = tid >> 6;               // 0: mu, 1: logvar
    int f = tid & 63;
    int col = tid;
    int beg = g_off[c], end = g_end[c];

    float a0 = 0.f, a1 = 0.f, a2 = 0.f, a3 = 0.f;
    for (int base = beg; base < end; base += 128) {
        int len = min(128, end - base);
        if (tid < len) {
            s_row[tid] = g_csr_row[base + tid];
            s_nrm[tid] = g_csr_nrm[base + tid];
        }
        __syncthreads();
        int j = 0;
        for (; j + 3 < len; j += 4) {
            a0 += s_nrm[j + 0] * hw23[(size_t)s_row[j + 0] * 128 + col];
            a1 += s_nrm[j + 1] * hw23[(size_t)s_row[j + 1] * 128 + col];
            a2 += s_nrm[j + 2] * hw23[(size_t)s_row[j + 2] * 128 + col];
            a3 += s_nrm[j + 3] * hw23[(size_t)s_row[j + 3] * 128 + col];
        }
        for (; j < len; j++)
            a0 += s_nrm[j] * hw23[(size_t)s_row[j] * 128 + col];
        __syncthreads();
    }
    float v = (a0 + a1) + (a2 + a3);
    if (half == 0) {
        float m = v + b2[f];
        mu[(size_t)c * H2 + f] = m;
        __nv_bfloat16 h = __float2bfloat16(m);
        __nv_bfloat16 l = __float2bfloat16(m - __bfloat162float(h));
        size_t base = (size_t)c * KSPLIT;
        ZA[base + f]       = h;
        ZA[base + 64 + f]  = h;
        ZA[base + 128 + f] = l;
        ZB[base + f]       = h;
        ZB[base + 64 + f]  = l;
        ZB[base + 128 + f] = h;
    } else {
        lv[(size_t)c * H2 + f] = v + b3[f];
    }
}

// ---------------- adj = ZA @ ZB^T, symmetric, ldmatrix + mma.sync bf16 -------
// Upper-triangular tile grid; off-diagonal tiles mirror-stored via smem transpose.
#define ADJ2_SMEM (2 * 128 * BPAD * 2)

__device__ __forceinline__ void ldsm_x4(uint32_t& r0, uint32_t& r1,
                                        uint32_t& r2, uint32_t& r3, uint32_t addr) {
    asm volatile("ldmatrix.sync.aligned.m8n8.x4.shared.b16 {%0,%1,%2,%3}, [%4];"
                 : "=r"(r0), "=r"(r1), "=r"(r2), "=r"(r3) : "r"(addr));
}

__global__ __launch_bounds__(256) void k_adj_mma(
    const __nv_bfloat16* __restrict__ ZA, const __nv_bfloat16* __restrict__ ZB,
    float* __restrict__ C, int n, int mtiles)
{
    extern __shared__ __nv_bfloat16 sm2[];
    __nv_bfloat16* As = sm2;              // [128][BPAD]
    __nv_bfloat16* Bs = sm2 + 128 * BPAD;
    float* S = (float*)sm2;               // staging reuse: [128][132] fp32

    // triangular decode: blockIdx.x -> (ti, tj), ti <= tj
    int ti = 0, rem = blockIdx.x;
    while (rem >= mtiles - ti) { rem -= mtiles - ti; ti++; }
    int tj = ti + rem;
    int bi = ti * 128, bj = tj * 128;

    int tid = threadIdx.x, lane = tid & 31, warp = tid >> 5;
    int wm = warp >> 2, wn = warp & 3;    // 2 x 4 warp grid

    // prolog: 128 rows x 24 uint4 (192 bf16) each array
    const uint4 zero4 = make_uint4(0u, 0u, 0u, 0u);
    for (int i = tid; i < 128 * 24; i += 256) {
        int r = i / 24, c = i % 24;
        uint4 va = zero4, vb = zero4;
        if (bi + r < n) va = *(const uint4*)&ZA[(size_t)(bi + r) * KSPLIT + c * 8];
        if (bj + r < n) vb = *(const uint4*)&ZB[(size_t)(bj + r) * KSPLIT + c * 8];
        *(uint4*)&As[r * BPAD + c * 8] = va;
        *(uint4*)&Bs[r * BPAD + c * 8] = vb;
    }
    __syncthreads();

    // ldmatrix lane addressing (byte addresses in shared space)
    uint32_t as_u32 = (uint32_t)__cvta_generic_to_shared(As);
    uint32_t bs_u32 = (uint32_t)__cvta_generic_to_shared(Bs);
    int l7 = lane & 7, lb3 = (lane >> 3) & 1, lb4 = lane >> 4;
    uint32_t a_addr[4];
    #pragma unroll
    for (int im = 0; im < 4; im++)
        a_addr[im] = as_u32 +
            (uint32_t)((wm * 64 + im * 16 + lb3 * 8 + l7) * BPAD) * 2 + lb4 * 16;
    uint32_t b_addr[2];
    #pragma unroll
    for (int p = 0; p < 2; p++)
        b_addr[p] = bs_u32 +
            (uint32_t)((wn * 32 + p * 16 + lb4 * 8 + l7) * BPAD) * 2 + lb3 * 16;

    float acc[4][4][4] = {};
    #pragma unroll
    for (int ks = 0; ks < KSPLIT / 16; ks++) {
        uint32_t koff = ks * 32;          // 16 bf16 = 32 bytes
        uint32_t b[4][2];
        ldsm_x4(b[0][0], b[0][1], b[1][0], b[1][1], b_addr[0] + koff);
        ldsm_x4(b[2][0], b[2][1], b[3][0], b[3][1], b_addr[1] + koff);
        #pragma unroll
        for (int im = 0; im < 4; im++) {
            uint32_t a0, a1, a2, a3;
            ldsm_x4(a0, a1, a2, a3, a_addr[im] + koff);
            #pragma unroll
            for (int jn = 0; jn < 4; jn++) {
                asm volatile(
                    "mma.sync.aligned.m16n8k16.row.col.f32.bf16.bf16.f32 "
                    "{%0,%1,%2,%3}, {%4,%5,%6,%7}, {%8,%9}, {%0,%1,%2,%3};"
                    : "+f"(acc[im][jn][0]), "+f"(acc[im][jn][1]),
                      "+f"(acc[im][jn][2]), "+f"(acc[im][jn][3])
                    : "r"(a0), "r"(a1), "r"(a2), "r"(a3),
                      "r"(b[jn][0]), "r"(b[jn][1]));
            }
        }
    }

    int kq = lane & 3;
    // direct store of tile (bi, bj)
    #pragma unroll
    for (int im = 0; im < 4; im++) {
        int r0 = bi + wm * 64 + im * 16 + (lane >> 2);
        #pragma unroll
        for (int jn = 0; jn < 4; jn++) {
            int cc = bj + wn * 32 + jn * 8 + kq * 2;
            if (r0 < n) {
                if (cc + 1 < n)
                    *(float2*)&C[(size_t)r0 * n + cc] = make_float2(acc[im][jn][0], acc[im][jn][1]);
                else if (cc < n)
                    C[(size_t)r0 * n + cc] = acc[im][jn][0];
            }
            int r1 = r0 + 8;
            if (r1 < n) {
                if (cc + 1 < n)
                    *(float2*)&C[(size_t)r1 * n + cc] = make_float2(acc[im][jn][2], acc[im][jn][3]);
                else if (cc < n)
                    C[(size_t)r1 * n + cc] = acc[im][jn][2];
            }
        }
    }

    // mirror store of tile (bj, bi) via smem transpose staging
    if (ti != tj) {
        __syncthreads();                  // done reading As/Bs
        int rbase = wm * 64 + (lane >> 2);
        int cbase = wn * 32 + kq * 2;
        #pragma unroll
        for (int im = 0; im < 4; im++) {
            int r = rbase + im * 16;
            #pragma unroll
            for (int jn = 0; jn < 4; jn++) {
                int c = cbase + jn * 8;
                S[(c + 0) * 132 + r]     = acc[im][jn][0];
                S[(c + 1) * 132 + r]     = acc[im][jn][1];
                S[(c + 0) * 132 + r + 8] = acc[im][jn][2];
                S[(c + 1) * 132 + r + 8] = acc[im][jn][3];
            }
        }
        __syncthreads();
        #pragma unroll
        for (int rr = warp * 16; rr < warp * 16 + 16; rr++) {
            int grow = bj + rr;
            if (grow < n) {
                float4 v = *(const float4*)&S[rr * 132 + lane * 4];
                *(float4*)&C[(size_t)grow * n + bi + lane * 4] = v;
            }
        }
    }
}

// ---------------- launch ------------------------------------------------------
extern "C" void kernel_launch(void* const* d_in, const int* in_sizes, int n_in,
                              void* d_out, int out_size) {
    const float* x   = (const float*)d_in[0];
    const void*  ei  = d_in[1];                 // edge_index [2,E], int64 or int32
    const float* ew  = (const float*)d_in[2];
    const float* W1  = (const float*)d_in[3];
    const float* b1  = (const float*)d_in[4];
    const float* W2  = (const float*)d_in[5];
    const float* b2  = (const float*)d_in[6];
    const float* W3  = (const float*)d_in[7];
    const float* b3  = (const float*)d_in[8];

    const int n = N_NODES;
    const int E = in_sizes[1] / 2;

    float* adj    = (float*)d_out;                                  // [N,N]
    float* mu     = (float*)d_out + (size_t)n * n;                  // [N,H2]
    float* logvar = mu + (size_t)n * H2;                            // [N,H2]

    float* g_hw1_p;  cudaGetSymbolAddress((void**)&g_hw1_p,  g_hw1);
    float* g_h1_p;   cudaGetSymbolAddress((void**)&g_h1_p,   g_h1);
    float* g_w23_p;  cudaGetSymbolAddress((void**)&g_w23_p,  g_w23);
    float* g_hw23_p; cudaGetSymbolAddress((void**)&g_hw23_p, g_hw23);
    __nv_bfloat16* g_za_p; cudaGetSymbolAddress((void**)&g_za_p, g_za);
    __nv_bfloat16* g_zb_p; cudaGetSymbolAddress((void**)&g_zb_p, g_zb);

    static int s_init = 0;
    static cudaStream_t s2;
    static cudaEvent_t evF, evB;
    if (!s_init) {
        cudaFuncSetAttribute(k_adj_mma, cudaFuncAttributeMaxDynamicSharedMemorySize, ADJ2_SMEM);
        cudaStreamCreateWithFlags(&s2, cudaStreamNonBlocking);
        cudaEventCreateWithFlags(&evF, cudaEventDisableTiming);
        cudaEventCreateWithFlags(&evB, cudaEventDisableTiming);
        s_init = 1;
    }

    const int T = 256;
    dim3 blk(16, 16);

    // 0. index width detection (needed by branch A)
    k_detect_idx<<<1, 32>>>(ei, E, n);

    // fork: branch B (stream s2) runs x@W1 + weight packing concurrently
    cudaEventRecord(evF, 0);
    cudaStreamWaitEvent(s2, evF, 0);
    k_pack_w23<<<(H1 * 64 + T - 1) / T, T, 0, s2>>>(W2, W3, g_w23_p);
    k_sgemm<<<dim3(H1 / 64, (n + 63) / 64), blk, 0, s2>>>(x, W1, g_hw1_p, n, F_IN, H1);
    cudaEventRecord(evB, s2);

    // branch A (stream 0): GCN normalization + CSR build (atomic chunk alloc)
    k_init_deg<<<(n + T - 1) / T, T>>>(n);
    k_deg_accum<<<(E + T - 1) / T, T>>>(ei, ew, E);
    k_dis_alloc<<<(n + T - 1) / T, T>>>(n);
    k_scatter<<<(E + n + T - 1) / T, T>>>(ei, ew, E, n);

    // join
    cudaStreamWaitEvent(0, evB, 0);

    // 2. layer 1: h1 = relu(gather(hw1) + b1)
    k_gather1<<<n, 128>>>(g_hw1_p, g_h1_p, b1);

    // 3. layer 2: one fused [H1,128] gemm for W2|W3, then fused gather+split
    k_sgemm<<<dim3(2, (n + 63) / 64), blk>>>(g_h1_p, g_w23_p, g_hw23_p, n, H1, 128);
    k_gather2<<<n, 128>>>(g_hw23_p, mu, logvar, b2, b3, g_za_p, g_zb_p);

    // 4. adj = mu @ mu^T via split-bf16 tensor-core GEMM (triangular + mirror)
    int mtiles = (n + 127) / 128;
    k_adj_mma<<<mtiles * (mtiles + 1) / 2, 256, ADJ2_SMEM>>>(
        g_za_p, g_zb_p, adj, n, mtiles);
}

// round 14
// speedup vs baseline: 2.8380x; 1.1364x over previous
#include <cuda_runtime.h>
#include <cuda_bf16.h>
#include <cstdint>

#define N_NODES 10000
#define F_IN    256
#define H1      128
#define H2      64
#define E_MAX   320000
#define CSR_MAX (E_MAX + N_NODES)
#define KSPLIT  192
#define BPAD    200     // bf16 row stride in smem (400 B)

typedef unsigned long long ull;

// ---------------- scratch (static device globals; no allocation) ------------
__device__ float g_deg[N_NODES];
__device__ float g_dis[N_NODES];
__device__ int   g_cnt[N_NODES];
__device__ int   g_off[N_NODES];
__device__ int   g_end[N_NODES];
__device__ int   g_fill[N_NODES];
__device__ int   g_total;
__device__ int   g_csr_row[CSR_MAX];
__device__ float g_csr_nrm[CSR_MAX];
__device__ float g_hw1[N_NODES * H1];
__device__ float g_h1 [N_NODES * H1];
__device__ float g_w23[H1 * 128];
__device__ float g_hw23[N_NODES * 128];
__device__ __align__(16) __nv_bfloat16 g_za[N_NODES * KSPLIT];
__device__ __align__(16) __nv_bfloat16 g_zb[N_NODES * KSPLIT];
__device__ int   g_is64;

__device__ __forceinline__ int edge_at(const void* ei, long long i) {
    if (g_is64) return (int)((const long long*)ei)[i];
    return ((const int*)ei)[i];
}

// ---------------- init deg/cnt + parallel int64/int32 detection --------------
__global__ __launch_bounds__(1024) void k_init(const void* ei, int E, int n) {
    int i = blockIdx.x * 1024 + threadIdx.x;
    if (i == 0) g_total = 0;
    if (i < n) { g_deg[i] = 1.0f; g_cnt[i] = 1; }     // self-loop
    if (blockIdx.x == 0) {
        int m = E < 1024 ? E : 1024;
        int ok = 1;
        if ((int)threadIdx.x < m) {
            long long v = ((const long long*)ei)[threadIdx.x];
            ok = (v >= 0 && v < (long long)n) ? 1 : 0;
        }
        int all = __syncthreads_and(ok);
        if (threadIdx.x == 0) g_is64 = all;
    }
}

__global__ void k_deg_accum(const void* ei, const float* __restrict__ w, int E) {
    int e = blockIdx.x * blockDim.x + threadIdx.x;
    if (e >= E) return;
    int c = edge_at(ei, (long long)E + e);            // col
    atomicAdd(&g_deg[c], w[e]);
    atomicAdd(&g_cnt[c], 1);
}

// dis + CSR range allocation (order-free contiguous chunks via atomic cursor)
__global__ void k_dis_alloc(int n) {
    int i = blockIdx.x * blockDim.x + threadIdx.x;
    if (i < n) {
        float d = g_deg[i];
        g_dis[i] = (d > 0.0f) ? rsqrtf(d) : 0.0f;
        int cnt = g_cnt[i];
        int pos = atomicAdd(&g_total, cnt);
        g_off[i]  = pos;
        g_end[i]  = pos + cnt;
        g_fill[i] = pos;
    }
}

// ---------------- scatter edges into CSR (grouped by col) --------------------
__global__ void k_scatter(const void* ei, const float* __restrict__ w, int E, int n) {
    int e = blockIdx.x * blockDim.x + threadIdx.x;
    if (e >= E + n) return;
    int r, c; float nv;
    if (e < E) {
        r = edge_at(ei, e);
        c = edge_at(ei, (long long)E + e);
        nv = g_dis[r] * w[e] * g_dis[c];
    } else {
        r = c = e - E;
        float d = g_dis[r];
        nv = d * d;
    }
    int pos = atomicAdd(&g_fill[c], 1);
    g_csr_row[pos] = r;
    g_csr_nrm[pos] = nv;
}

// ---------------- pack W2|W3 into one [H1,128] weight ------------------------
__global__ void k_pack_w23(const float* __restrict__ W2, const float* __restrict__ W3,
                           float* __restrict__ W23) {
    int i = blockIdx.x * blockDim.x + threadIdx.x;
    if (i >= H1 * 64) return;
    int k = i >> 6, j = i & 63;
    W23[k * 128 + j]      = W2[i];
    W23[k * 128 + 64 + j] = W3[i];
}

// ---------------- generic tiled SGEMM: C[MxNc] = A[MxK] @ B[KxNc] ------------
__global__ __launch_bounds__(256) void k_sgemm(
    const float* __restrict__ A, const float* __restrict__ B,
    float* __restrict__ C, int M, int K, int Nc)
{
    __shared__ float As[16][68];   // As[k][m]
    __shared__ float Bs[16][68];   // Bs[k][n]
    int bm = blockIdx.y * 64, bn = blockIdx.x * 64;
    int tx = threadIdx.x, ty = threadIdx.y;
    int tid = ty * 16 + tx;

    float acc[4][4] = {};
    for (int k0 = 0; k0 < K; k0 += 16) {
        #pragma unroll
        for (int i = tid; i < 1024; i += 256) {
            int m = i >> 4, k = i & 15;
            int gm = bm + m;
            As[k][m] = (gm < M) ? A[(size_t)gm * K + k0 + k] : 0.0f;
        }
        #pragma unroll
        for (int i = tid; i < 1024; i += 256) {
            int k = i >> 6, n = i & 63;
            Bs[k][n] = B[(size_t)(k0 + k) * Nc + bn + n];
        }
        __syncthreads();
        #pragma unroll
        for (int k = 0; k < 16; k++) {
            float4 a = *(const float4*)&As[k][4 * ty];
            float4 b = *(const float4*)&Bs[k][4 * tx];
            acc[0][0] += a.x * b.x; acc[0][1] += a.x * b.y; acc[0][2] += a.x * b.z; acc[0][3] += a.x * b.w;
            acc[1][0] += a.y * b.x; acc[1][1] += a.y * b.y; acc[1][2] += a.y * b.z; acc[1][3] += a.y * b.w;
            acc[2][0] += a.z * b.x; acc[2][1] += a.z * b.y; acc[2][2] += a.z * b.z; acc[2][3] += a.z * b.w;
            acc[3][0] += a.w * b.x; acc[3][1] += a.w * b.y; acc[3][2] += a.w * b.z; acc[3][3] += a.w * b.w;
        }
        __syncthreads();
    }
    #pragma unroll
    for (int i = 0; i < 4; i++) {
        int gm = bm + 4 * ty + i;
        if (gm < M) {
            float4 v = make_float4(acc[i][0], acc[i][1], acc[i][2], acc[i][3]);
            *(float4*)&C[(size_t)gm * Nc + bn + 4 * tx] = v;
        }
    }
}

// ---------------- CSR gather, layer 1: h1 = relu(agg(hw1) + b1) --------------
__global__ __launch_bounds__(128) void k_gather1(
    const float* __restrict__ hw, float* __restrict__ out,
    const float* __restrict__ bias)
{
    __shared__ int   s_row[128];
    __shared__ float s_nrm[128];
    int c = blockIdx.x;
    int tid = threadIdx.x;
    int beg = g_off[c], end = g_end[c];

    float a0 = 0.f, a1 = 0.f, a2 = 0.f, a3 = 0.f;
    for (int base = beg; base < end; base += 128) {
        int len = min(128, end - base);
        if (tid < len) {
            s_row[tid] = g_csr_row[base + tid];
            s_nrm[tid] = g_csr_nrm[base + tid];
        }
        __syncthreads();
        int j = 0;
        for (; j + 3 < len; j += 4) {
            a0 += s_nrm[j + 0] * hw[(size_t)s_row[j + 0] * H1 + tid];
            a1 += s_nrm[j + 1] * hw[(size_t)s_row[j + 1] * H1 + tid];
            a2 += s_nrm[j + 2] * hw[(size_t)s_row[j + 2] * H1 + tid];
            a3 += s_nrm[j + 3] * hw[(size_t)s_row[j + 3] * H1 + tid];
        }
        for (; j < len; j++)
            a0 += s_nrm[j] * hw[(size_t)s_row[j] * H1 + tid];
        __syncthreads();
    }
    float v = (a0 + a1) + (a2 + a3) + bias[tid];
    out[(size_t)c * H1 + tid] = fmaxf(v, 0.0f);
}

// ---------------- CSR gather, fused mu/logvar + bf16 split -------------------
__global__ __launch_bounds__(128) void k_gather2(
    const float* __restrict__ hw23,
    float* __restrict__ mu, float* __restrict__ lv,
    const float* __restrict__ b2, const float* __restrict__ b3,
    __nv_bfloat16* __restrict__ ZA, __nv_bfloat16* __restrict__ ZB)
{
    __shared__ int   s_row[128];
    __shared__ float s_nrm[128];
    int c = blockIdx.x;
    int tid = threadIdx.x;
    int half = tid >> 6;               // 0: mu, 1: logvar
    int f = tid & 63;
    int col = tid;
    int beg = g_off[c], end = g_end[c];

    float a0 = 0.f, a1 = 0.f, a2 = 0.f, a3 = 0.f;
    for (int base = beg; base < end; base += 128) {
        int len = min(128, end - base);
        if (tid < len) {
            s_row[tid] = g_csr_row[base + tid];
            s_nrm[tid] = g_csr_nrm[base + tid];
        }
        __syncthreads();
        int j = 0;
        for (; j + 3 < len; j += 4) {
            a0 += s_nrm[j + 0] * hw23[(size_t)s_row[j + 0] * 128 + col];
            a1 += s_nrm[j + 1] * hw23[(size_t)s_row[j + 1] * 128 + col];
            a2 += s_nrm[j + 2] * hw23[(size_t)s_row[j + 2] * 128 + col];
            a3 += s_nrm[j + 3] * hw23[(size_t)s_row[j + 3] * 128 + col];
        }
        for (; j < len; j++)
            a0 += s_nrm[j] * hw23[(size_t)s_row[j] * 128 + col];
        __syncthreads();
    }
    float v = (a0 + a1) + (a2 + a3);
    if (half == 0) {
        float m = v + b2[f];
        mu[(size_t)c * H2 + f] = m;
        __nv_bfloat16 h = __float2bfloat16(m);
        __nv_bfloat16 l = __float2bfloat16(m - __bfloat162float(h));
        size_t base = (size_t)c * KSPLIT;
        ZA[base + f]       = h;
        ZA[base + 64 + f]  = h;
        ZA[base + 128 + f] = l;
        ZB[base + f]       = h;
        ZB[base + 64 + f]  = l;
        ZB[base + 128 + f] = h;
    } else {
        lv[(size_t)c * H2 + f] = v + b3[f];
    }
}

// ---------------- adj = ZA @ ZB^T, symmetric, ldmatrix + mma.sync bf16 -------
// Upper-triangular tile grid; off-diagonal tiles mirror-stored via smem transpose.
// 2 CTAs/SM forced so one CTA's stores overlap the other's HMMA mainloop.
#define ADJ2_SMEM (2 * 128 * BPAD * 2)

__device__ __forceinline__ void ldsm_x4(uint32_t& r0, uint32_t& r1,
                                        uint32_t& r2, uint32_t& r3, uint32_t addr) {
    asm volatile("ldmatrix.sync.aligned.m8n8.x4.shared.b16 {%0,%1,%2,%3}, [%4];"
                 : "=r"(r0), "=r"(r1), "=r"(r2), "=r"(r3) : "r"(addr));
}

__global__ __launch_bounds__(256, 2) void k_adj_mma(
    const __nv_bfloat16* __restrict__ ZA, const __nv_bfloat16* __restrict__ ZB,
    float* __restrict__ C, int n, int mtiles)
{
    extern __shared__ __nv_bfloat16 sm2[];
    __nv_bfloat16* As = sm2;              // [128][BPAD]
    __nv_bfloat16* Bs = sm2 + 128 * BPAD;
    float* S = (float*)sm2;               // staging reuse: [128][132] fp32

    // triangular decode: blockIdx.x -> (ti, tj), ti <= tj
    int ti = 0, rem = blockIdx.x;
    while (rem >= mtiles - ti) { rem -= mtiles - ti; ti++; }
    int tj = ti + rem;
    int bi = ti * 128, bj = tj * 128;

    int tid = threadIdx.x, lane = tid & 31, warp = tid >> 5;
    int wm = warp >> 2, wn = warp & 3;    // 2 x 4 warp grid

    // prolog: 128 rows x 24 uint4 (192 bf16) each array
    const uint4 zero4 = make_uint4(0u, 0u, 0u, 0u);
    for (int i = tid; i < 128 * 24; i += 256) {
        int r = i / 24, c = i % 24;
        uint4 va = zero4, vb = zero4;
        if (bi + r < n) va = *(const uint4*)&ZA[(size_t)(bi + r) * KSPLIT + c * 8];
        if (bj + r < n) vb = *(const uint4*)&ZB[(size_t)(bj + r) * KSPLIT + c * 8];
        *(uint4*)&As[r * BPAD + c * 8] = va;
        *(uint4*)&Bs[r * BPAD + c * 8] = vb;
    }
    __syncthreads();

    // ldmatrix lane addressing (byte addresses in shared space)
    uint32_t as_u32 = (uint32_t)__cvta_generic_to_shared(As);
    uint32_t bs_u32 = (uint32_t)__cvta_generic_to_shared(Bs);
    int l7 = lane & 7, lb3 = (lane >> 3) & 1, lb4 = lane >> 4;
    uint32_t a_addr[4];
    #pragma unroll
    for (int im = 0; im < 4; im++)
        a_addr[im] = as_u32 +
            (uint32_t)((wm * 64 + im * 16 + lb3 * 8 + l7) * BPAD) * 2 + lb4 * 16;
    uint32_t b_addr[2];
    #pragma unroll
    for (int p = 0; p < 2; p++)
        b_addr[p] = bs_u32 +
            (uint32_t)((wn * 32 + p * 16 + lb4 * 8 + l7) * BPAD) * 2 + lb3 * 16;

    float acc[4][4][4] = {};
    #pragma unroll
    for (int ks = 0; ks < KSPLIT / 16; ks++) {
        uint32_t koff = ks * 32;          // 16 bf16 = 32 bytes
        uint32_t b[4][2];
        ldsm_x4(b[0][0], b[0][1], b[1][0], b[1][1], b_addr[0] + koff);
        ldsm_x4(b[2][0], b[2][1], b[3][0], b[3][1], b_addr[1] + koff);
        #pragma unroll
        for (int im = 0; im < 4; im++) {
            uint32_t a0, a1, a2, a3;
            ldsm_x4(a0, a1, a2, a3, a_addr[im] + koff);
            #pragma unroll
            for (int jn = 0; jn < 4; jn++) {
                asm volatile(
                    "mma.sync.aligned.m16n8k16.row.col.f32.bf16.bf16.f32 "
                    "{%0,%1,%2,%3}, {%4,%5,%6,%7}, {%8,%9}, {%0,%1,%2,%3};"
                    : "+f"(acc[im][jn][0]), "+f"(acc[im][jn][1]),
                      "+f"(acc[im][jn][2]), "+f"(acc[im][jn][3])
                    : "r"(a0), "r"(a1), "r"(a2), "r"(a3),
                      "r"(b[jn][0]), "r"(b[jn][1]));
            }
        }
    }

    int kq = lane & 3;
    // direct store of tile (bi, bj) — streaming (evict-first) stores
    #pragma unroll
    for (int im = 0; im < 4; im++) {
        int r0 = bi + wm * 64 + im * 16 + (lane >> 2);
        #pragma unroll
        for (int jn = 0; jn < 4; jn++) {
            int cc = bj + wn * 32 + jn * 8 + kq * 2;
            if (r0 < n) {
                if (cc + 1 < n)
                    __stcs((float2*)&C[(size_t)r0 * n + cc],
                           make_float2(acc[im][jn][0], acc[im][jn][1]));
                else if (cc < n)
                    C[(size_t)r0 * n + cc] = acc[im][jn][0];
            }
            int r1 = r0 + 8;
            if (r1 < n) {
                if (cc + 1 < n)
                    __stcs((float2*)&C[(size_t)r1 * n + cc],
                           make_float2(acc[im][jn][2], acc[im][jn][3]));
                else if (cc < n)
                    C[(size_t)r1 * n + cc] = acc[im][jn][2];
            }
        }
    }

    // mirror store of tile (bj, bi) via smem transpose staging
    if (ti != tj) {
        __syncthreads();                  // done reading As/Bs
        int rbase = wm * 64 + (lane >> 2);
        int cbase = wn * 32 + kq * 2;
        #pragma unroll
        for (int im = 0; im < 4; im++) {
            int r = rbase + im * 16;
            #pragma unroll
            for (int jn = 0; jn < 4; jn++) {
                int c = cbase + jn * 8;
                S[(c + 0) * 132 + r]     = acc[im][jn][0];
                S[(c + 1) * 132 + r]     = acc[im][jn][1];
                S[(c + 0) * 132 + r + 8] = acc[im][jn][2];
                S[(c + 1) * 132 + r + 8] = acc[im][jn][3];
            }
        }
        __syncthreads();
        #pragma unroll
        for (int rr = warp * 16; rr < warp * 16 + 16; rr++) {
            int grow = bj + rr;
            if (grow < n) {
                float4 v = *(const float4*)&S[rr * 132 + lane * 4];
                __stcs((float4*)&C[(size_t)grow * n + bi + lane * 4], v);
            }
        }
    }
}

// ---------------- launch ------------------------------------------------------
extern "C" void kernel_launch(void* const* d_in, const int* in_sizes, int n_in,
                              void* d_out, int out_size) {
    const float* x   = (const float*)d_in[0];
    const void*  ei  = d_in[1];                 // edge_index [2,E], int64 or int32
    const float* ew  = (const float*)d_in[2];
    const float* W1  = (const float*)d_in[3];
    const float* b1  = (const float*)d_in[4];
    const float* W2  = (const float*)d_in[5];
    const float* b2  = (const float*)d_in[6];
    const float* W3  = (const float*)d_in[7];
    const float* b3  = (const float*)d_in[8];

    const int n = N_NODES;
    const int E = in_sizes[1] / 2;

    float* adj    = (float*)d_out;                                  // [N,N]
    float* mu     = (float*)d_out + (size_t)n * n;                  // [N,H2]
    float* logvar = mu + (size_t)n * H2;                            // [N,H2]

    float* g_hw1_p;  cudaGetSymbolAddress((void**)&g_hw1_p,  g_hw1);
    float* g_h1_p;   cudaGetSymbolAddress((void**)&g_h1_p,   g_h1);
    float* g_w23_p;  cudaGetSymbolAddress((void**)&g_w23_p,  g_w23);
    float* g_hw23_p; cudaGetSymbolAddress((void**)&g_hw23_p, g_hw23);
    __nv_bfloat16* g_za_p; cudaGetSymbolAddress((void**)&g_za_p, g_za);
    __nv_bfloat16* g_zb_p; cudaGetSymbolAddress((void**)&g_zb_p, g_zb);

    static int s_init = 0;
    static cudaStream_t s2;
    static cudaEvent_t evF, evB;
    if (!s_init) {
        cudaFuncSetAttribute(k_adj_mma, cudaFuncAttributeMaxDynamicSharedMemorySize, ADJ2_SMEM);
        cudaStreamCreateWithFlags(&s2, cudaStreamNonBlocking);
        cudaEventCreateWithFlags(&evF, cudaEventDisableTiming);
        cudaEventCreateWithFlags(&evB, cudaEventDisableTiming);
        s_init = 1;
    }

    const int T = 256;
    dim3 blk(16, 16);

    // fork: branch B (stream s2) runs x@W1 + weight packing concurrently
    cudaEventRecord(evF, 0);
    cudaStreamWaitEvent(s2, evF, 0);
    k_pack_w23<<<(H1 * 64 + T - 1) / T, T, 0, s2>>>(W2, W3, g_w23_p);
    k_sgemm<<<dim3(H1 / 64, (n + 63) / 64), blk, 0, s2>>>(x, W1, g_hw1_p, n, F_IN, H1);
    cudaEventRecord(evB, s2);

    // branch A (stream 0): init+detect, GCN normalization + CSR build
    k_init<<<(n + 1023) / 1024, 1024>>>(ei, E, n);
    k_deg_accum<<<(E + T - 1) / T, T>>>(ei, ew, E);
    k_dis_alloc<<<(n + T - 1) / T, T>>>(n);
    k_scatter<<<(E + n + T - 1) / T, T>>>(ei, ew, E, n);

    // join
    cudaStreamWaitEvent(0, evB, 0);

    // 2. layer 1: h1 = relu(gather(hw1) + b1)
    k_gather1<<<n, 128>>>(g_hw1_p, g_h1_p, b1);

    // 3. layer 2: one fused [H1,128] gemm for W2|W3, then fused gather+split
    k_sgemm<<<dim3(2, (n + 63) / 64), blk>>>(g_h1_p, g_w23_p, g_hw23_p, n, H1, 128);
    k_gather2<<<n, 128>>>(g_hw23_p, mu, logvar, b2, b3, g_za_p, g_zb_p);

    // 4. adj = mu @ mu^T via split-bf16 tensor-core GEMM (triangular + mirror)
    int mtiles = (n + 127) / 128;
    k_adj_mma<<<mtiles * (mtiles + 1) / 2, 256, ADJ2_SMEM>>>(
        g_za_p, g_zb_p, adj, n, mtiles);
}

// round 15
// speedup vs baseline: 2.9055x; 1.0238x over previous
#include <cuda_runtime.h>
#include <cuda_bf16.h>
#include <cstdint>

#define N_NODES 10000
#define F_IN    256
#define H1      128
#define H2      64
#define E_MAX   320000
#define CSR_MAX (E_MAX + N_NODES)
#define KSPLIT  192
#define BPAD    200     // bf16 row stride in smem (400 B)

typedef unsigned long long ull;

// fixed-point degree packing: low 40 bits = weight sum * 2^20, high bits = count
#define DEG_SCALE 1048576.0f
#define CNT_SHIFT 40

// ---------------- scratch (static device globals; no allocation) ------------
__device__ ull   g_degcnt[N_NODES];
__device__ float g_dis[N_NODES];
__device__ int   g_off[N_NODES];
__device__ int   g_end[N_NODES];
__device__ int   g_fill[N_NODES];
__device__ int   g_total;
__device__ int   g_csr_row[CSR_MAX];
__device__ float g_csr_nrm[CSR_MAX];
__device__ float g_hw1[N_NODES * H1];
__device__ float g_h1 [N_NODES * H1];
__device__ float g_w23[H1 * 128];
__device__ float g_hw23[N_NODES * 128];
__device__ __align__(16) __nv_bfloat16 g_za[N_NODES * KSPLIT];
__device__ __align__(16) __nv_bfloat16 g_zb[N_NODES * KSPLIT];
__device__ int   g_is64;

__device__ __forceinline__ int edge_at(const void* ei, long long i) {
    if (g_is64) return (int)((const long long*)ei)[i];
    return ((const int*)ei)[i];
}

// ---------------- init degcnt + parallel int64/int32 detection ---------------
__global__ __launch_bounds__(1024) void k_init(const void* ei, int E, int n) {
    int i = blockIdx.x * 1024 + threadIdx.x;
    if (i == 0) g_total = 0;
    if (i < n)                                        // self-loop: w=1, cnt=1
        g_degcnt[i] = ((ull)1 << CNT_SHIFT) | (ull)(unsigned)(DEG_SCALE);
    if (blockIdx.x == 0) {
        int m = E < 1024 ? E : 1024;
        int ok = 1;
        if ((int)threadIdx.x < m) {
            long long v = ((const long long*)ei)[threadIdx.x];
            ok = (v >= 0 && v < (long long)n) ? 1 : 0;
        }
        int all = __syncthreads_and(ok);
        if (threadIdx.x == 0) g_is64 = all;
    }
}

// single 64-bit atomic per edge: packed (count, fixed-point weight sum)
__global__ void k_deg_accum(const void* ei, const float* __restrict__ w, int E) {
    int e = blockIdx.x * blockDim.x + threadIdx.x;
    if (e >= E) return;
    int c = edge_at(ei, (long long)E + e);            // col
    ull pk = ((ull)1 << CNT_SHIFT) | (ull)(unsigned)(w[e] * DEG_SCALE + 0.5f);
    atomicAdd(&g_degcnt[c], pk);
}

// dis + CSR range allocation (order-free contiguous chunks via atomic cursor)
__global__ void k_dis_alloc(int n) {
    int i = blockIdx.x * blockDim.x + threadIdx.x;
    if (i < n) {
        ull v = g_degcnt[i];
        int cnt = (int)(v >> CNT_SHIFT);
        float d = (float)(v & (((ull)1 << CNT_SHIFT) - 1)) * (1.0f / DEG_SCALE);
        g_dis[i] = (d > 0.0f) ? rsqrtf(d) : 0.0f;
        int pos = atomicAdd(&g_total, cnt);
        g_off[i]  = pos;
        g_end[i]  = pos + cnt;
        g_fill[i] = pos;
    }
}

// ---------------- scatter edges into CSR (grouped by col) --------------------
__global__ void k_scatter(const void* ei, const float* __restrict__ w, int E, int n) {
    int e = blockIdx.x * blockDim.x + threadIdx.x;
    if (e >= E + n) return;
    int r, c; float nv;
    if (e < E) {
        r = edge_at(ei, e);
        c = edge_at(ei, (long long)E + e);
        nv = g_dis[r] * w[e] * g_dis[c];
    } else {
        r = c = e - E;
        float d = g_dis[r];
        nv = d * d;
    }
    int pos = atomicAdd(&g_fill[c], 1);
    g_csr_row[pos] = r;
    g_csr_nrm[pos] = nv;
}

// ---------------- pack W2|W3 into one [H1,128] weight ------------------------
__global__ void k_pack_w23(const float* __restrict__ W2, const float* __restrict__ W3,
                           float* __restrict__ W23) {
    int i = blockIdx.x * blockDim.x + threadIdx.x;
    if (i >= H1 * 64) return;
    int k = i >> 6, j = i & 63;
    W23[k * 128 + j]      = W2[i];
    W23[k * 128 + 64 + j] = W3[i];
}

// ---------------- generic tiled SGEMM: C[MxNc] = A[MxK] @ B[KxNc] ------------
__global__ __launch_bounds__(256) void k_sgemm(
    const float* __restrict__ A, const float* __restrict__ B,
    float* __restrict__ C, int M, int K, int Nc)
{
    __shared__ float As[16][68];   // As[k][m]
    __shared__ float Bs[16][68];   // Bs[k][n]
    int bm = blockIdx.y * 64, bn = blockIdx.x * 64;
    int tx = threadIdx.x, ty = threadIdx.y;
    int tid = ty * 16 + tx;

    float acc[4][4] = {};
    for (int k0 = 0; k0 < K; k0 += 16) {
        #pragma unroll
        for (int i = tid; i < 1024; i += 256) {
            int m = i >> 4, k = i & 15;
            int gm = bm + m;
            As[k][m] = (gm < M) ? A[(size_t)gm * K + k0 + k] : 0.0f;
        }
        #pragma unroll
        for (int i = tid; i < 1024; i += 256) {
            int k = i >> 6, n = i & 63;
            Bs[k][n] = B[(size_t)(k0 + k) * Nc + bn + n];
        }
        __syncthreads();
        #pragma unroll
        for (int k = 0; k < 16; k++) {
            float4 a = *(const float4*)&As[k][4 * ty];
            float4 b = *(const float4*)&Bs[k][4 * tx];
            acc[0][0] += a.x * b.x; acc[0][1] += a.x * b.y; acc[0][2] += a.x * b.z; acc[0][3] += a.x * b.w;
            acc[1][0] += a.y * b.x; acc[1][1] += a.y * b.y; acc[1][2] += a.y * b.z; acc[1][3] += a.y * b.w;
            acc[2][0] += a.z * b.x; acc[2][1] += a.z * b.y; acc[2][2] += a.z * b.z; acc[2][3] += a.z * b.w;
            acc[3][0] += a.w * b.x; acc[3][1] += a.w * b.y; acc[3][2] += a.w * b.z; acc[3][3] += a.w * b.w;
        }
        __syncthreads();
    }
    #pragma unroll
    for (int i = 0; i < 4; i++) {
        int gm = bm + 4 * ty + i;
        if (gm < M) {
            float4 v = make_float4(acc[i][0], acc[i][1], acc[i][2], acc[i][3]);
            *(float4*)&C[(size_t)gm * Nc + bn + 4 * tx] = v;
        }
    }
}

// ---------------- CSR gather, layer 1: h1 = relu(agg(hw1) + b1) --------------
__global__ __launch_bounds__(128) void k_gather1(
    const float* __restrict__ hw, float* __restrict__ out,
    const float* __restrict__ bias)
{
    __shared__ int   s_row[128];
    __shared__ float s_nrm[128];
    int c = blockIdx.x;
    int tid = threadIdx.x;
    int beg = g_off[c], end = g_end[c];

    float a0 = 0.f, a1 = 0.f, a2 = 0.f, a3 = 0.f;
    for (int base = beg; base < end; base += 128) {
        int len = min(128, end - base);
        if (tid < len) {
            s_row[tid] = g_csr_row[base + tid];
            s_nrm[tid] = g_csr_nrm[base + tid];
        }
        __syncthreads();
        int j = 0;
        for (; j + 3 < len; j += 4) {
            a0 += s_nrm[j + 0] * hw[(size_t)s_row[j + 0] * H1 + tid];
            a1 += s_nrm[j + 1] * hw[(size_t)s_row[j + 1] * H1 + tid];
            a2 += s_nrm[j + 2] * hw[(size_t)s_row[j + 2] * H1 + tid];
            a3 += s_nrm[j + 3] * hw[(size_t)s_row[j + 3] * H1 + tid];
        }
        for (; j < len; j++)
            a0 += s_nrm[j] * hw[(size_t)s_row[j] * H1 + tid];
        __syncthreads();
    }
    float v = (a0 + a1) + (a2 + a3) + bias[tid];
    out[(size_t)c * H1 + tid] = fmaxf(v, 0.0f);
}

// ---------------- CSR gather: mu + bf16 split (critical path) ----------------
__global__ __launch_bounds__(64) void k_gather_mu(
    const float* __restrict__ hw23, float* __restrict__ mu,
    const float* __restrict__ b2,
    __nv_bfloat16* __restrict__ ZA, __nv_bfloat16* __restrict__ ZB)
{
    __shared__ int   s_row[64];
    __shared__ float s_nrm[64];
    int c = blockIdx.x;
    int f = threadIdx.x;               // 0..63
    int beg = g_off[c], end = g_end[c];

    float a0 = 0.f, a1 = 0.f, a2 = 0.f, a3 = 0.f;
    for (int base = beg; base < end; base += 64) {
        int len = min(64, end - base);
        if (f < len) {
            s_row[f] = g_csr_row[base + f];
            s_nrm[f] = g_csr_nrm[base + f];
        }
        __syncthreads();
        int j = 0;
        for (; j + 3 < len; j += 4) {
            a0 += s_nrm[j + 0] * hw23[(size_t)s_row[j + 0] * 128 + f];
            a1 += s_nrm[j + 1] * hw23[(size_t)s_row[j + 1] * 128 + f];
            a2 += s_nrm[j + 2] * hw23[(size_t)s_row[j + 2] * 128 + f];
            a3 += s_nrm[j + 3] * hw23[(size_t)s_row[j + 3] * 128 + f];
        }
        for (; j < len; j++)
            a0 += s_nrm[j] * hw23[(size_t)s_row[j] * 128 + f];
        __syncthreads();
    }
    float m = (a0 + a1) + (a2 + a3) + b2[f];
    mu[(size_t)c * H2 + f] = m;
    __nv_bfloat16 h = __float2bfloat16(m);
    __nv_bfloat16 l = __float2bfloat16(m - __bfloat162float(h));
    size_t base = (size_t)c * KSPLIT;
    ZA[base + f]       = h;
    ZA[base + 64 + f]  = h;
    ZA[base + 128 + f] = l;
    ZB[base + f]       = h;
    ZB[base + 64 + f]  = l;
    ZB[base + 128 + f] = h;
}

// ---------------- CSR gather: logvar (overlapped with adj GEMM) --------------
__global__ __launch_bounds__(64) void k_gather_lv(
    const float* __restrict__ hw23, float* __restrict__ lv,
    const float* __restrict__ b3)
{
    __shared__ int   s_row[64];
    __shared__ float s_nrm[64];
    int c = blockIdx.x;
    int f = threadIdx.x;               // 0..63
    int beg = g_off[c], end = g_end[c];

    float a0 = 0.f, a1 = 0.f, a2 = 0.f, a3 = 0.f;
    for (int base = beg; base < end; base += 64) {
        int len = min(64, end - base);
        if (f < len) {
            s_row[f] = g_csr_row[base + f];
            s_nrm[f] = g_csr_nrm[base + f];
        }
        __syncthreads();
        int j = 0;
        for (; j + 3 < len; j += 4) {
            a0 += s_nrm[j + 0] * hw23[(size_t)s_row[j + 0] * 128 + 64 + f];
            a1 += s_nrm[j + 1] * hw23[(size_t)s_row[j + 1] * 128 + 64 + f];
            a2 += s_nrm[j + 2] * hw23[(size_t)s_row[j + 2] * 128 + 64 + f];
            a3 += s_nrm[j + 3] * hw23[(size_t)s_row[j + 3] * 128 + 64 + f];
        }
        for (; j < len; j++)
            a0 += s_nrm[j] * hw23[(size_t)s_row[j] * 128 + 64 + f];
        __syncthreads();
    }
    lv[(size_t)c * H2 + f] = (a0 + a1) + (a2 + a3) + b3[f];
}

// ---------------- adj = ZA @ ZB^T, symmetric, ldmatrix + mma.sync bf16 -------
#define ADJ2_SMEM (2 * 128 * BPAD * 2)

__device__ __forceinline__ void ldsm_x4(uint32_t& r0, uint32_t& r1,
                                        uint32_t& r2, uint32_t& r3, uint32_t addr) {
    asm volatile("ldmatrix.sync.aligned.m8n8.x4.shared.b16 {%0,%1,%2,%3}, [%4];"
                 : "=r"(r0), "=r"(r1), "=r"(r2), "=r"(r3) : "r"(addr));
}

__global__ __launch_bounds__(256, 2) void k_adj_mma(
    const __nv_bfloat16* __restrict__ ZA, const __nv_bfloat16* __restrict__ ZB,
    float* __restrict__ C, int n, int mtiles)
{
    extern __shared__ __nv_bfloat16 sm2[];
    __nv_bfloat16* As = sm2;              // [128][BPAD]
    __nv_bfloat16* Bs = sm2 + 128 * BPAD;
    float* S = (float*)sm2;               // staging reuse: [128][132] fp32

    // triangular decode: blockIdx.x -> (ti, tj), ti <= tj
    int ti = 0, rem = blockIdx.x;
    while (rem >= mtiles - ti) { rem -= mtiles - ti; ti++; }
    int tj = ti + rem;
    int bi = ti * 128, bj = tj * 128;

    int tid = threadIdx.x, lane = tid & 31, warp = tid >> 5;
    int wm = warp >> 2, wn = warp & 3;    // 2 x 4 warp grid

    // prolog: 128 rows x 24 uint4 (192 bf16) each array
    const uint4 zero4 = make_uint4(0u, 0u, 0u, 0u);
    for (int i = tid; i < 128 * 24; i += 256) {
        int r = i / 24, c = i % 24;
        uint4 va = zero4, vb = zero4;
        if (bi + r < n) va = *(const uint4*)&ZA[(size_t)(bi + r) * KSPLIT + c * 8];
        if (bj + r < n) vb = *(const uint4*)&ZB[(size_t)(bj + r) * KSPLIT + c * 8];
        *(uint4*)&As[r * BPAD + c * 8] = va;
        *(uint4*)&Bs[r * BPAD + c * 8] = vb;
    }
    __syncthreads();

    // ldmatrix lane addressing (byte addresses in shared space)
    uint32_t as_u32 = (uint32_t)__cvta_generic_to_shared(As);
    uint32_t bs_u32 = (uint32_t)__cvta_generic_to_shared(Bs);
    int l7 = lane & 7, lb3 = (lane >> 3) & 1, lb4 = lane >> 4;
    uint32_t a_addr[4];
    #pragma unroll
    for (int im = 0; im < 4; im++)
        a_addr[im] = as_u32 +
            (uint32_t)((wm * 64 + im * 16 + lb3 * 8 + l7) * BPAD) * 2 + lb4 * 16;
    uint32_t b_addr[2];
    #pragma unroll
    for (int p = 0; p < 2; p++)
        b_addr[p] = bs_u32 +
            (uint32_t)((wn * 32 + p * 16 + lb4 * 8 + l7) * BPAD) * 2 + lb3 * 16;

    float acc[4][4][4] = {};
    #pragma unroll
    for (int ks = 0; ks < KSPLIT / 16; ks++) {
        uint32_t koff = ks * 32;          // 16 bf16 = 32 bytes
        uint32_t b[4][2];
        ldsm_x4(b[0][0], b[0][1], b[1][0], b[1][1], b_addr[0] + koff);
        ldsm_x4(b[2][0], b[2][1], b[3][0], b[3][1], b_addr[1] + koff);
        #pragma unroll
        for (int im = 0; im < 4; im++) {
            uint32_t a0, a1, a2, a3;
            ldsm_x4(a0, a1, a2, a3, a_addr[im] + koff);
            #pragma unroll
            for (int jn = 0; jn < 4; jn++) {
                asm volatile(
                    "mma.sync.aligned.m16n8k16.row.col.f32.bf16.bf16.f32 "
                    "{%0,%1,%2,%3}, {%4,%5,%6,%7}, {%8,%9}, {%0,%1,%2,%3};"
                    : "+f"(acc[im][jn][0]), "+f"(acc[im][jn][1]),
                      "+f"(acc[im][jn][2]), "+f"(acc[im][jn][3])
                    : "r"(a0), "r"(a1), "r"(a2), "r"(a3),
                      "r"(b[jn][0]), "r"(b[jn][1]));
            }
        }
    }

    int kq = lane & 3;
    // direct store of tile (bi, bj) — streaming (evict-first) stores
    #pragma unroll
    for (int im = 0; im < 4; im++) {
        int r0 = bi + wm * 64 + im * 16 + (lane >> 2);
        #pragma unroll
        for (int jn = 0; jn < 4; jn++) {
            int cc = bj + wn * 32 + jn * 8 + kq * 2;
            if (r0 < n) {
                if (cc + 1 < n)
                    __stcs((float2*)&C[(size_t)r0 * n + cc],
                           make_float2(acc[im][jn][0], acc[im][jn][1]));
                else if (cc < n)
                    C[(size_t)r0 * n + cc] = acc[im][jn][0];
            }
            int r1 = r0 + 8;
            if (r1 < n) {
                if (cc + 1 < n)
                    __stcs((float2*)&C[(size_t)r1 * n + cc],
                           make_float2(acc[im][jn][2], acc[im][jn][3]));
                else if (cc < n)
                    C[(size_t)r1 * n + cc] = acc[im][jn][2];
            }
        }
    }

    // mirror store of tile (bj, bi) via smem transpose staging
    if (ti != tj) {
        __syncthreads();                  // done reading As/Bs
        int rbase = wm * 64 + (lane >> 2);
        int cbase = wn * 32 + kq * 2;
        #pragma unroll
        for (int im = 0; im < 4; im++) {
            int r = rbase + im * 16;
            #pragma unroll
            for (int jn = 0; jn < 4; jn++) {
                int c = cbase + jn * 8;
                S[(c + 0) * 132 + r]     = acc[im][jn][0];
                S[(c + 1) * 132 + r]     = acc[im][jn][1];
                S[(c + 0) * 132 + r + 8] = acc[im][jn][2];
                S[(c + 1) * 132 + r + 8] = acc[im][jn][3];
            }
        }
        __syncthreads();
        #pragma unroll
        for (int rr = warp * 16; rr < warp * 16 + 16; rr++) {
            int grow = bj + rr;
            if (grow < n) {
                float4 v = *(const float4*)&S[rr * 132 + lane * 4];
                __stcs((float4*)&C[(size_t)grow * n + bi + lane * 4], v);
            }
        }
    }
}

// ---------------- launch ------------------------------------------------------
extern "C" void kernel_launch(void* const* d_in, const int* in_sizes, int n_in,
                              void* d_out, int out_size) {
    const float* x   = (const float*)d_in[0];
    const void*  ei  = d_in[1];                 // edge_index [2,E], int64 or int32
    const float* ew  = (const float*)d_in[2];
    const float* W1  = (const float*)d_in[3];
    const float* b1  = (const float*)d_in[4];
    const float* W2  = (const float*)d_in[5];
    const float* b2  = (const float*)d_in[6];
    const float* W3  = (const float*)d_in[7];
    const float* b3  = (const float*)d_in[8];

    const int n = N_NODES;
    const int E = in_sizes[1] / 2;

    float* adj    = (float*)d_out;                                  // [N,N]
    float* mu     = (float*)d_out + (size_t)n * n;                  // [N,H2]
    float* logvar = mu + (size_t)n * H2;                            // [N,H2]

    float* g_hw1_p;  cudaGetSymbolAddress((void**)&g_hw1_p,  g_hw1);
    float* g_h1_p;   cudaGetSymbolAddress((void**)&g_h1_p,   g_h1);
    float* g_w23_p;  cudaGetSymbolAddress((void**)&g_w23_p,  g_w23);
    float* g_hw23_p; cudaGetSymbolAddress((void**)&g_hw23_p, g_hw23);
    __nv_bfloat16* g_za_p; cudaGetSymbolAddress((void**)&g_za_p, g_za);
    __nv_bfloat16* g_zb_p; cudaGetSymbolAddress((void**)&g_zb_p, g_zb);

    static int s_init = 0;
    static cudaStream_t s2;
    static cudaEvent_t evF, evB, evC, evD;
    if (!s_init) {
        cudaFuncSetAttribute(k_adj_mma, cudaFuncAttributeMaxDynamicSharedMemorySize, ADJ2_SMEM);
        cudaStreamCreateWithFlags(&s2, cudaStreamNonBlocking);
        cudaEventCreateWithFlags(&evF, cudaEventDisableTiming);
        cudaEventCreateWithFlags(&evB, cudaEventDisableTiming);
        cudaEventCreateWithFlags(&evC, cudaEventDisableTiming);
        cudaEventCreateWithFlags(&evD, cudaEventDisableTiming);
        s_init = 1;
    }

    const int T = 256;
    dim3 blk(16, 16);

    // fork: branch B (stream s2) runs x@W1 + weight packing concurrently
    cudaEventRecord(evF, 0);
    cudaStreamWaitEvent(s2, evF, 0);
    k_pack_w23<<<(H1 * 64 + T - 1) / T, T, 0, s2>>>(W2, W3, g_w23_p);
    k_sgemm<<<dim3(H1 / 64, (n + 63) / 64), blk, 0, s2>>>(x, W1, g_hw1_p, n, F_IN, H1);
    cudaEventRecord(evB, s2);

    // branch A (stream 0): init+detect, packed degree accum + CSR build
    k_init<<<(n + 1023) / 1024, 1024>>>(ei, E, n);
    k_deg_accum<<<(E + T - 1) / T, T>>>(ei, ew, E);
    k_dis_alloc<<<(n + T - 1) / T, T>>>(n);
    k_scatter<<<(E + n + T - 1) / T, T>>>(ei, ew, E, n);

    // join
    cudaStreamWaitEvent(0, evB, 0);

    // 2. layer 1: h1 = relu(gather(hw1) + b1)
    k_gather1<<<n, 128>>>(g_hw1_p, g_h1_p, b1);

    // 3. layer 2: one fused [H1,128] gemm for W2|W3
    k_sgemm<<<dim3(2, (n + 63) / 64), blk>>>(g_h1_p, g_w23_p, g_hw23_p, n, H1, 128);
    cudaEventRecord(evC, 0);

    // mu (+ bf16 split) on critical path; logvar overlapped with adj on s2
    k_gather_mu<<<n, 64>>>(g_hw23_p, mu, b2, g_za_p, g_zb_p);
    cudaStreamWaitEvent(s2, evC, 0);
    k_gather_lv<<<n, 64, 0, s2>>>(g_hw23_p, logvar, b3);
    cudaEventRecord(evD, s2);

    // 4. adj = mu @ mu^T via split-bf16 tensor-core GEMM (triangular + mirror)
    int mtiles = (n + 127) / 128;
    k_adj_mma<<<mtiles * (mtiles + 1) / 2, 256, ADJ2_SMEM>>>(
        g_za_p, g_zb_p, adj, n, mtiles);

    // rejoin s2 so capture ends with a single terminal stream
    cudaStreamWaitEvent(0, evD, 0);
}

// round 16
// speedup vs baseline: 3.0543x; 1.0512x over previous
#include <cuda_runtime.h>
#include <cuda_bf16.h>
#include <cuda_fp16.h>
#include <cstdint>

#define N_NODES 10000
#define F_IN    256
#define H1      128
#define H2      64
#define E_MAX   320000
#define CSR_MAX (E_MAX + N_NODES)
#define KADJ    128
#define BPAD    136     // fp16 row stride in smem (272 B) — conflict-free ldmatrix

typedef unsigned long long ull;

// fixed-point degree packing: low 40 bits = weight sum * 2^20, high bits = count
#define DEG_SCALE 1048576.0f
#define CNT_SHIFT 40

// ---------------- scratch (static device globals; no allocation) ------------
__device__ ull   g_degcnt[N_NODES];
__device__ float g_dis[N_NODES];
__device__ int   g_off[N_NODES];
__device__ int   g_end[N_NODES];
__device__ int   g_fill[N_NODES];
__device__ int   g_total;
__device__ int   g_csr_row[CSR_MAX];
__device__ float g_csr_nrm[CSR_MAX];
__device__ float g_hw1[N_NODES * H1];
__device__ float g_h1 [N_NODES * H1];
__device__ float g_w23[H1 * 128];
__device__ float g_hw23[N_NODES * 128];
__device__ __align__(16) __half g_zh[N_NODES * H2];
__device__ __align__(16) __half g_zl[N_NODES * H2];
__device__ int   g_is64;

__device__ __forceinline__ int edge_at(const void* ei, long long i) {
    if (g_is64) return (int)((const long long*)ei)[i];
    return ((const int*)ei)[i];
}

// ---------------- init degcnt + parallel int64/int32 detection ---------------
__global__ __launch_bounds__(1024) void k_init(const void* ei, int E, int n) {
    int i = blockIdx.x * 1024 + threadIdx.x;
    if (i == 0) g_total = 0;
    if (i < n)                                        // self-loop: w=1, cnt=1
        g_degcnt[i] = ((ull)1 << CNT_SHIFT) | (ull)(unsigned)(DEG_SCALE);
    if (blockIdx.x == 0) {
        int m = E < 1024 ? E : 1024;
        int ok = 1;
        if ((int)threadIdx.x < m) {
            long long v = ((const long long*)ei)[threadIdx.x];
            ok = (v >= 0 && v < (long long)n) ? 1 : 0;
        }
        int all = __syncthreads_and(ok);
        if (threadIdx.x == 0) g_is64 = all;
    }
}

// single 64-bit atomic per edge: packed (count, fixed-point weight sum)
__global__ void k_deg_accum(const void* ei, const float* __restrict__ w, int E) {
    int e = blockIdx.x * blockDim.x + threadIdx.x;
    if (e >= E) return;
    int c = edge_at(ei, (long long)E + e);            // col
    ull pk = ((ull)1 << CNT_SHIFT) | (ull)(unsigned)(w[e] * DEG_SCALE + 0.5f);
    atomicAdd(&g_degcnt[c], pk);
}

// dis + CSR range allocation (order-free contiguous chunks via atomic cursor)
__global__ void k_dis_alloc(int n) {
    int i = blockIdx.x * blockDim.x + threadIdx.x;
    if (i < n) {
        ull v = g_degcnt[i];
        int cnt = (int)(v >> CNT_SHIFT);
        float d = (float)(v & (((ull)1 << CNT_SHIFT) - 1)) * (1.0f / DEG_SCALE);
        g_dis[i] = (d > 0.0f) ? rsqrtf(d) : 0.0f;
        int pos = atomicAdd(&g_total, cnt);
        g_off[i]  = pos;
        g_end[i]  = pos + cnt;
        g_fill[i] = pos;
    }
}

// ---------------- scatter edges into CSR (grouped by col) --------------------
__global__ void k_scatter(const void* ei, const float* __restrict__ w, int E, int n) {
    int e = blockIdx.x * blockDim.x + threadIdx.x;
    if (e >= E + n) return;
    int r, c; float nv;
    if (e < E) {
        r = edge_at(ei, e);
        c = edge_at(ei, (long long)E + e);
        nv = g_dis[r] * w[e] * g_dis[c];
    } else {
        r = c = e - E;
        float d = g_dis[r];
        nv = d * d;
    }
    int pos = atomicAdd(&g_fill[c], 1);
    g_csr_row[pos] = r;
    g_csr_nrm[pos] = nv;
}

// ---------------- pack W2|W3 into one [H1,128] weight ------------------------
__global__ void k_pack_w23(const float* __restrict__ W2, const float* __restrict__ W3,
                           float* __restrict__ W23) {
    int i = blockIdx.x * blockDim.x + threadIdx.x;
    if (i >= H1 * 64) return;
    int k = i >> 6, j = i & 63;
    W23[k * 128 + j]      = W2[i];
    W23[k * 128 + 64 + j] = W3[i];
}

// ---------------- generic tiled SGEMM: C[MxNc] = A[MxK] @ B[KxNc] ------------
__global__ __launch_bounds__(256) void k_sgemm(
    const float* __restrict__ A, const float* __restrict__ B,
    float* __restrict__ C, int M, int K, int Nc)
{
    __shared__ float As[16][68];   // As[k][m]
    __shared__ float Bs[16][68];   // Bs[k][n]
    int bm = blockIdx.y * 64, bn = blockIdx.x * 64;
    int tx = threadIdx.x, ty = threadIdx.y;
    int tid = ty * 16 + tx;

    float acc[4][4] = {};
    for (int k0 = 0; k0 < K; k0 += 16) {
        #pragma unroll
        for (int i = tid; i < 1024; i += 256) {
            int m = i >> 4, k = i & 15;
            int gm = bm + m;
            As[k][m] = (gm < M) ? A[(size_t)gm * K + k0 + k] : 0.0f;
        }
        #pragma unroll
        for (int i = tid; i < 1024; i += 256) {
            int k = i >> 6, n = i & 63;
            Bs[k][n] = B[(size_t)(k0 + k) * Nc + bn + n];
        }
        __syncthreads();
        #pragma unroll
        for (int k = 0; k < 16; k++) {
            float4 a = *(const float4*)&As[k][4 * ty];
            float4 b = *(const float4*)&Bs[k][4 * tx];
            acc[0][0] += a.x * b.x; acc[0][1] += a.x * b.y; acc[0][2] += a.x * b.z; acc[0][3] += a.x * b.w;
            acc[1][0] += a.y * b.x; acc[1][1] += a.y * b.y; acc[1][2] += a.y * b.z; acc[1][3] += a.y * b.w;
            acc[2][0] += a.z * b.x; acc[2][1] += a.z * b.y; acc[2][2] += a.z * b.z; acc[2][3] += a.z * b.w;
            acc[3][0] += a.w * b.x; acc[3][1] += a.w * b.y; acc[3][2] += a.w * b.z; acc[3][3] += a.w * b.w;
        }
        __syncthreads();
    }
    #pragma unroll
    for (int i = 0; i < 4; i++) {
        int gm = bm + 4 * ty + i;
        if (gm < M) {
            float4 v = make_float4(acc[i][0], acc[i][1], acc[i][2], acc[i][3]);
            *(float4*)&C[(size_t)gm * Nc + bn + 4 * tx] = v;
        }
    }
}

// ---------------- CSR gather, layer 1: h1 = relu(agg(hw1) + b1) --------------
__global__ __launch_bounds__(128) void k_gather1(
    const float* __restrict__ hw, float* __restrict__ out,
    const float* __restrict__ bias)
{
    __shared__ int   s_row[128];
    __shared__ float s_nrm[128];
    int c = blockIdx.x;
    int tid = threadIdx.x;
    int beg = g_off[c], end = g_end[c];

    float a0 = 0.f, a1 = 0.f, a2 = 0.f, a3 = 0.f;
    for (int base = beg; base < end; base += 128) {
        int len = min(128, end - base);
        if (tid < len) {
            s_row[tid] = g_csr_row[base + tid];
            s_nrm[tid] = g_csr_nrm[base + tid];
        }
        __syncthreads();
        int j = 0;
        for (; j + 3 < len; j += 4) {
            a0 += s_nrm[j + 0] * hw[(size_t)s_row[j + 0] * H1 + tid];
            a1 += s_nrm[j + 1] * hw[(size_t)s_row[j + 1] * H1 + tid];
            a2 += s_nrm[j + 2] * hw[(size_t)s_row[j + 2] * H1 + tid];
            a3 += s_nrm[j + 3] * hw[(size_t)s_row[j + 3] * H1 + tid];
        }
        for (; j < len; j++)
            a0 += s_nrm[j] * hw[(size_t)s_row[j] * H1 + tid];
        __syncthreads();
    }
    float v = (a0 + a1) + (a2 + a3) + bias[tid];
    out[(size_t)c * H1 + tid] = fmaxf(v, 0.0f);
}

// ---------------- CSR gather: mu + fp16 split (critical path) ----------------
__global__ __launch_bounds__(64) void k_gather_mu(
    const float* __restrict__ hw23, float* __restrict__ mu,
    const float* __restrict__ b2,
    __half* __restrict__ ZH, __half* __restrict__ ZL)
{
    __shared__ int   s_row[64];
    __shared__ float s_nrm[64];
    int c = blockIdx.x;
    int f = threadIdx.x;               // 0..63
    int beg = g_off[c], end = g_end[c];

    float a0 = 0.f, a1 = 0.f, a2 = 0.f, a3 = 0.f;
    for (int base = beg; base < end; base += 64) {
        int len = min(64, end - base);
        if (f < len) {
            s_row[f] = g_csr_row[base + f];
            s_nrm[f] = g_csr_nrm[base + f];
        }
        __syncthreads();
        int j = 0;
        for (; j + 3 < len; j += 4) {
            a0 += s_nrm[j + 0] * hw23[(size_t)s_row[j + 0] * 128 + f];
            a1 += s_nrm[j + 1] * hw23[(size_t)s_row[j + 1] * 128 + f];
            a2 += s_nrm[j + 2] * hw23[(size_t)s_row[j + 2] * 128 + f];
            a3 += s_nrm[j + 3] * hw23[(size_t)s_row[j + 3] * 128 + f];
        }
        for (; j < len; j++)
            a0 += s_nrm[j] * hw23[(size_t)s_row[j] * 128 + f];
        __syncthreads();
    }
    float m = (a0 + a1) + (a2 + a3) + b2[f];
    mu[(size_t)c * H2 + f] = m;
    __half h = __float2half_rn(m);
    __half l = __float2half_rn(m - __half2float(h));
    ZH[(size_t)c * H2 + f] = h;
    ZL[(size_t)c * H2 + f] = l;
}

// ---------------- CSR gather: logvar (overlapped with adj GEMM) --------------
__global__ __launch_bounds__(64) void k_gather_lv(
    const float* __restrict__ hw23, float* __restrict__ lv,
    const float* __restrict__ b3)
{
    __shared__ int   s_row[64];
    __shared__ float s_nrm[64];
    int c = blockIdx.x;
    int f = threadIdx.x;               // 0..63
    int beg = g_off[c], end = g_end[c];

    float a0 = 0.f, a1 = 0.f, a2 = 0.f, a3 = 0.f;
    for (int base = beg; base < end; base += 64) {
        int len = min(64, end - base);
        if (f < len) {
            s_row[f] = g_csr_row[base + f];
            s_nrm[f] = g_csr_nrm[base + f];
        }
        __syncthreads();
        int j = 0;
        for (; j + 3 < len; j += 4) {
            a0 += s_nrm[j + 0] * hw23[(size_t)s_row[j + 0] * 128 + 64 + f];
            a1 += s_nrm[j + 1] * hw23[(size_t)s_row[j + 1] * 128 + 64 + f];
            a2 += s_nrm[j + 2] * hw23[(size_t)s_row[j + 2] * 128 + 64 + f];
            a3 += s_nrm[j + 3] * hw23[(size_t)s_row[j + 3] * 128 + 64 + f];
        }
        for (; j < len; j++)
            a0 += s_nrm[j] * hw23[(size_t)s_row[j] * 128 + 64 + f];
        __syncthreads();
    }
    lv[(size_t)c * H2 + f] = (a0 + a1) + (a2 + a3) + b3[f];
}

// ---------------- adj: fp16 split K=128, A=[H|L], B=[H|H] --------------------
// C = H·H^T + L·H^T  (missing H·L^T ~ 2^-12 relative). Triangular + mirror.
#define ADJ2_SMEM (2 * 128 * BPAD * 2)

__device__ __forceinline__ void ldsm_x4(uint32_t& r0, uint32_t& r1,
                                        uint32_t& r2, uint32_t& r3, uint32_t addr) {
    asm volatile("ldmatrix.sync.aligned.m8n8.x4.shared.b16 {%0,%1,%2,%3}, [%4];"
                 : "=r"(r0), "=r"(r1), "=r"(r2), "=r"(r3) : "r"(addr));
}

__global__ __launch_bounds__(256, 2) void k_adj_mma(
    const __half* __restrict__ ZH, const __half* __restrict__ ZL,
    float* __restrict__ C, int n, int mtiles)
{
    extern __shared__ __half sm2[];
    __half* As = sm2;                     // [128][BPAD]  rows = [H | L]
    __half* Bs = sm2 + 128 * BPAD;        // [128][BPAD]  rows = [H | H]
    float* S = (float*)sm2;               // staging reuse: [128][132] fp32

    // triangular decode: blockIdx.x -> (ti, tj), ti <= tj
    int ti = 0, rem = blockIdx.x;
    while (rem >= mtiles - ti) { rem -= mtiles - ti; ti++; }
    int tj = ti + rem;
    int bi = ti * 128, bj = tj * 128;

    int tid = threadIdx.x, lane = tid & 31, warp = tid >> 5;
    int wm = warp >> 2, wn = warp & 3;    // 2 x 4 warp grid

    // prolog: 128 rows x 16 uint4 (128 fp16) per array; H deduplicated in gmem
    const uint4 zero4 = make_uint4(0u, 0u, 0u, 0u);
    for (int i = tid; i < 128 * 16; i += 256) {
        int r = i >> 4, c = i & 15;       // c: 8-fp16 chunk
        int c7 = (c & 7) * 8;
        uint4 va = zero4, vb = zero4;
        if (bi + r < n)
            va = (c < 8) ? *(const uint4*)&ZH[(size_t)(bi + r) * H2 + c7]
                         : *(const uint4*)&ZL[(size_t)(bi + r) * H2 + c7];
        if (bj + r < n)
            vb = *(const uint4*)&ZH[(size_t)(bj + r) * H2 + c7];
        *(uint4*)&As[r * BPAD + c * 8] = va;
        *(uint4*)&Bs[r * BPAD + c * 8] = vb;
    }
    __syncthreads();

    // ldmatrix lane addressing (byte addresses in shared space)
    uint32_t as_u32 = (uint32_t)__cvta_generic_to_shared(As);
    uint32_t bs_u32 = (uint32_t)__cvta_generic_to_shared(Bs);
    int l7 = lane & 7, lb3 = (lane >> 3) & 1, lb4 = lane >> 4;
    uint32_t a_addr[4];
    #pragma unroll
    for (int im = 0; im < 4; im++)
        a_addr[im] = as_u32 +
            (uint32_t)((wm * 64 + im * 16 + lb3 * 8 + l7) * BPAD) * 2 + lb4 * 16;
    uint32_t b_addr[2];
    #pragma unroll
    for (int p = 0; p < 2; p++)
        b_addr[p] = bs_u32 +
            (uint32_t)((wn * 32 + p * 16 + lb4 * 8 + l7) * BPAD) * 2 + lb3 * 16;

    float acc[4][4][4] = {};
    #pragma unroll
    for (int ks = 0; ks < KADJ / 16; ks++) {
        uint32_t koff = ks * 32;          // 16 fp16 = 32 bytes
        uint32_t b[4][2];
        ldsm_x4(b[0][0], b[0][1], b[1][0], b[1][1], b_addr[0] + koff);
        ldsm_x4(b[2][0], b[2][1], b[3][0], b[3][1], b_addr[1] + koff);
        #pragma unroll
        for (int im = 0; im < 4; im++) {
            uint32_t a0, a1, a2, a3;
            ldsm_x4(a0, a1, a2, a3, a_addr[im] + koff);
            #pragma unroll
            for (int jn = 0; jn < 4; jn++) {
                asm volatile(
                    "mma.sync.aligned.m16n8k16.row.col.f32.f16.f16.f32 "
                    "{%0,%1,%2,%3}, {%4,%5,%6,%7}, {%8,%9}, {%0,%1,%2,%3};"
                    : "+f"(acc[im][jn][0]), "+f"(acc[im][jn][1]),
                      "+f"(acc[im][jn][2]), "+f"(acc[im][jn][3])
                    : "r"(a0), "r"(a1), "r"(a2), "r"(a3),
                      "r"(b[jn][0]), "r"(b[jn][1]));
            }
        }
    }

    int kq = lane & 3;
    // direct store of tile (bi, bj) — streaming (evict-first) stores
    #pragma unroll
    for (int im = 0; im < 4; im++) {
        int r0 = bi + wm * 64 + im * 16 + (lane >> 2);
        #pragma unroll
        for (int jn = 0; jn < 4; jn++) {
            int cc = bj + wn * 32 + jn * 8 + kq * 2;
            if (r0 < n) {
                if (cc + 1 < n)
                    __stcs((float2*)&C[(size_t)r0 * n + cc],
                           make_float2(acc[im][jn][0], acc[im][jn][1]));
                else if (cc < n)
                    C[(size_t)r0 * n + cc] = acc[im][jn][0];
            }
            int r1 = r0 + 8;
            if (r1 < n) {
                if (cc + 1 < n)
                    __stcs((float2*)&C[(size_t)r1 * n + cc],
                           make_float2(acc[im][jn][2], acc[im][jn][3]));
                else if (cc < n)
                    C[(size_t)r1 * n + cc] = acc[im][jn][2];
            }
        }
    }

    // mirror store of tile (bj, bi) via smem transpose staging
    if (ti != tj) {
        __syncthreads();                  // done reading As/Bs
        int rbase = wm * 64 + (lane >> 2);
        int cbase = wn * 32 + kq * 2;
        #pragma unroll
        for (int im = 0; im < 4; im++) {
            int r = rbase + im * 16;
            #pragma unroll
            for (int jn = 0; jn < 4; jn++) {
                int c = cbase + jn * 8;
                S[(c + 0) * 132 + r]     = acc[im][jn][0];
                S[(c + 1) * 132 + r]     = acc[im][jn][1];
                S[(c + 0) * 132 + r + 8] = acc[im][jn][2];
                S[(c + 1) * 132 + r + 8] = acc[im][jn][3];
            }
        }
        __syncthreads();
        #pragma unroll
        for (int rr = warp * 16; rr < warp * 16 + 16; rr++) {
            int grow = bj + rr;
            if (grow < n) {
                float4 v = *(const float4*)&S[rr * 132 + lane * 4];
                __stcs((float4*)&C[(size_t)grow * n + bi + lane * 4], v);
            }
        }
    }
}

// ---------------- launch ------------------------------------------------------
extern "C" void kernel_launch(void* const* d_in, const int* in_sizes, int n_in,
                              void* d_out, int out_size) {
    const float* x   = (const float*)d_in[0];
    const void*  ei  = d_in[1];                 // edge_index [2,E], int64 or int32
    const float* ew  = (const float*)d_in[2];
    const float* W1  = (const float*)d_in[3];
    const float* b1  = (const float*)d_in[4];
    const float* W2  = (const float*)d_in[5];
    const float* b2  = (const float*)d_in[6];
    const float* W3  = (const float*)d_in[7];
    const float* b3  = (const float*)d_in[8];

    const int n = N_NODES;
    const int E = in_sizes[1] / 2;

    float* adj    = (float*)d_out;                                  // [N,N]
    float* mu     = (float*)d_out + (size_t)n * n;                  // [N,H2]
    float* logvar = mu + (size_t)n * H2;                            // [N,H2]

    float* g_hw1_p;  cudaGetSymbolAddress((void**)&g_hw1_p,  g_hw1);
    float* g_h1_p;   cudaGetSymbolAddress((void**)&g_h1_p,   g_h1);
    float* g_w23_p;  cudaGetSymbolAddress((void**)&g_w23_p,  g_w23);
    float* g_hw23_p; cudaGetSymbolAddress((void**)&g_hw23_p, g_hw23);
    __half* g_zh_p; cudaGetSymbolAddress((void**)&g_zh_p, g_zh);
    __half* g_zl_p; cudaGetSymbolAddress((void**)&g_zl_p, g_zl);

    static int s_init = 0;
    static cudaStream_t s2;
    static cudaEvent_t evF, evB, evC, evD;
    if (!s_init) {
        cudaFuncSetAttribute(k_adj_mma, cudaFuncAttributeMaxDynamicSharedMemorySize, ADJ2_SMEM);
        cudaStreamCreateWithFlags(&s2, cudaStreamNonBlocking);
        cudaEventCreateWithFlags(&evF, cudaEventDisableTiming);
        cudaEventCreateWithFlags(&evB, cudaEventDisableTiming);
        cudaEventCreateWithFlags(&evC, cudaEventDisableTiming);
        cudaEventCreateWithFlags(&evD, cudaEventDisableTiming);
        s_init = 1;
    }

    const int T = 256;
    dim3 blk(16, 16);

    // fork: branch B (stream s2) runs x@W1 + weight packing concurrently
    cudaEventRecord(evF, 0);
    cudaStreamWaitEvent(s2, evF, 0);
    k_pack_w23<<<(H1 * 64 + T - 1) / T, T, 0, s2>>>(W2, W3, g_w23_p);
    k_sgemm<<<dim3(H1 / 64, (n + 63) / 64), blk, 0, s2>>>(x, W1, g_hw1_p, n, F_IN, H1);
    cudaEventRecord(evB, s2);

    // branch A (stream 0): init+detect, packed degree accum + CSR build
    k_init<<<(n + 1023) / 1024, 1024>>>(ei, E, n);
    k_deg_accum<<<(E + T - 1) / T, T>>>(ei, ew, E);
    k_dis_alloc<<<(n + T - 1) / T, T>>>(n);
    k_scatter<<<(E + n + T - 1) / T, T>>>(ei, ew, E, n);

    // join
    cudaStreamWaitEvent(0, evB, 0);

    // 2. layer 1: h1 = relu(gather(hw1) + b1)
    k_gather1<<<n, 128>>>(g_hw1_p, g_h1_p, b1);

    // 3. layer 2: one fused [H1,128] gemm for W2|W3
    k_sgemm<<<dim3(2, (n + 63) / 64), blk>>>(g_h1_p, g_w23_p, g_hw23_p, n, H1, 128);
    cudaEventRecord(evC, 0);

    // mu (+ fp16 split) on critical path; logvar overlapped with adj on s2
    k_gather_mu<<<n, 64>>>(g_hw23_p, mu, b2, g_zh_p, g_zl_p);
    cudaStreamWaitEvent(s2, evC, 0);
    k_gather_lv<<<n, 64, 0, s2>>>(g_hw23_p, logvar, b3);
    cudaEventRecord(evD, s2);

    // 4. adj = mu @ mu^T via fp16-split tensor-core GEMM (triangular + mirror)
    int mtiles = (n + 127) / 128;
    k_adj_mma<<<mtiles * (mtiles + 1) / 2, 256, ADJ2_SMEM>>>(
        g_zh_p, g_zl_p, adj, n, mtiles);

    // rejoin s2 so capture ends with a single terminal stream
    cudaStreamWaitEvent(0, evD, 0);
}

// round 17
// speedup vs baseline: 3.0903x; 1.0118x over previous
#include <cuda_runtime.h>
#include <cuda_bf16.h>
#include <cuda_fp16.h>
#include <cstdint>

#define N_NODES 10000
#define F_IN    256
#define H1      128
#define H2      64
#define E_MAX   320000
#define CSR_MAX (E_MAX + N_NODES)
#define KADJ    128
#define BPAD    136     // fp16 row stride in smem (272 B) — conflict-free ldmatrix

typedef unsigned long long ull;

// fixed-point degree packing: low 40 bits = weight sum * 2^20, high bits = count
#define DEG_SCALE 1048576.0f
#define CNT_SHIFT 40

// ---------------- scratch (static device globals; no allocation) ------------
__device__ ull   g_degcnt[N_NODES];
__device__ float g_dis[N_NODES];
__device__ int   g_off[N_NODES];
__device__ int   g_end[N_NODES];
__device__ int   g_fill[N_NODES];
__device__ int   g_total;
__device__ int   g_csr_row[CSR_MAX];
__device__ float g_csr_nrm[CSR_MAX];
__device__ float g_hw1[N_NODES * H1];
__device__ float g_w23[H1 * 128];
__device__ float g_hw23[N_NODES * 128];
__device__ __align__(16) __half g_zh[N_NODES * H2];
__device__ __align__(16) __half g_zl[N_NODES * H2];
__device__ int   g_is64;

__device__ __forceinline__ int edge_at(const void* ei, long long i) {
    if (g_is64) return (int)((const long long*)ei)[i];
    return ((const int*)ei)[i];
}

// ---------------- init degcnt + parallel int64/int32 detection ---------------
__global__ __launch_bounds__(1024) void k_init(const void* ei, int E, int n) {
    int i = blockIdx.x * 1024 + threadIdx.x;
    if (i == 0) g_total = 0;
    if (i < n)                                        // self-loop: w=1, cnt=1
        g_degcnt[i] = ((ull)1 << CNT_SHIFT) | (ull)(unsigned)(DEG_SCALE);
    if (blockIdx.x == 0) {
        int m = E < 1024 ? E : 1024;
        int ok = 1;
        if ((int)threadIdx.x < m) {
            long long v = ((const long long*)ei)[threadIdx.x];
            ok = (v >= 0 && v < (long long)n) ? 1 : 0;
        }
        int all = __syncthreads_and(ok);
        if (threadIdx.x == 0) g_is64 = all;
    }
}

// single 64-bit atomic per edge: packed (count, fixed-point weight sum)
__global__ void k_deg_accum(const void* ei, const float* __restrict__ w, int E) {
    int e = blockIdx.x * blockDim.x + threadIdx.x;
    if (e >= E) return;
    int c = edge_at(ei, (long long)E + e);            // col
    ull pk = ((ull)1 << CNT_SHIFT) | (ull)(unsigned)(w[e] * DEG_SCALE + 0.5f);
    atomicAdd(&g_degcnt[c], pk);
}

// dis + CSR range allocation (order-free contiguous chunks via atomic cursor)
__global__ void k_dis_alloc(int n) {
    int i = blockIdx.x * blockDim.x + threadIdx.x;
    if (i < n) {
        ull v = g_degcnt[i];
        int cnt = (int)(v >> CNT_SHIFT);
        float d = (float)(v & (((ull)1 << CNT_SHIFT) - 1)) * (1.0f / DEG_SCALE);
        g_dis[i] = (d > 0.0f) ? rsqrtf(d) : 0.0f;
        int pos = atomicAdd(&g_total, cnt);
        g_off[i]  = pos;
        g_end[i]  = pos + cnt;
        g_fill[i] = pos;
    }
}

// ---------------- scatter edges into CSR (grouped by col) --------------------
__global__ void k_scatter(const void* ei, const float* __restrict__ w, int E, int n) {
    int e = blockIdx.x * blockDim.x + threadIdx.x;
    if (e >= E + n) return;
    int r, c; float nv;
    if (e < E) {
        r = edge_at(ei, e);
        c = edge_at(ei, (long long)E + e);
        nv = g_dis[r] * w[e] * g_dis[c];
    } else {
        r = c = e - E;
        float d = g_dis[r];
        nv = d * d;
    }
    int pos = atomicAdd(&g_fill[c], 1);
    g_csr_row[pos] = r;
    g_csr_nrm[pos] = nv;
}

// ---------------- pack W2|W3 into one [H1,128] weight ------------------------
__global__ void k_pack_w23(const float* __restrict__ W2, const float* __restrict__ W3,
                           float* __restrict__ W23) {
    int i = blockIdx.x * blockDim.x + threadIdx.x;
    if (i >= H1 * 64) return;
    int k = i >> 6, j = i & 63;
    W23[k * 128 + j]      = W2[i];
    W23[k * 128 + 64 + j] = W3[i];
}

// ---------------- generic tiled SGEMM: C[MxNc] = A[MxK] @ B[KxNc] ------------
__global__ __launch_bounds__(256) void k_sgemm(
    const float* __restrict__ A, const float* __restrict__ B,
    float* __restrict__ C, int M, int K, int Nc)
{
    __shared__ float As[16][68];   // As[k][m]
    __shared__ float Bs[16][68];   // Bs[k][n]
    int bm = blockIdx.y * 64, bn = blockIdx.x * 64;
    int tx = threadIdx.x, ty = threadIdx.y;
    int tid = ty * 16 + tx;

    float acc[4][4] = {};
    for (int k0 = 0; k0 < K; k0 += 16) {
        #pragma unroll
        for (int i = tid; i < 1024; i += 256) {
            int m = i >> 4, k = i & 15;
            int gm = bm + m;
            As[k][m] = (gm < M) ? A[(size_t)gm * K + k0 + k] : 0.0f;
        }
        #pragma unroll
        for (int i = tid; i < 1024; i += 256) {
            int k = i >> 6, n = i & 63;
            Bs[k][n] = B[(size_t)(k0 + k) * Nc + bn + n];
        }
        __syncthreads();
        #pragma unroll
        for (int k = 0; k < 16; k++) {
            float4 a = *(const float4*)&As[k][4 * ty];
            float4 b = *(const float4*)&Bs[k][4 * tx];
            acc[0][0] += a.x * b.x; acc[0][1] += a.x * b.y; acc[0][2] += a.x * b.z; acc[0][3] += a.x * b.w;
            acc[1][0] += a.y * b.x; acc[1][1] += a.y * b.y; acc[1][2] += a.y * b.z; acc[1][3] += a.y * b.w;
            acc[2][0] += a.z * b.x; acc[2][1] += a.z * b.y; acc[2][2] += a.z * b.z; acc[2][3] += a.z * b.w;
            acc[3][0] += a.w * b.x; acc[3][1] += a.w * b.y; acc[3][2] += a.w * b.z; acc[3][3] += a.w * b.w;
        }
        __syncthreads();
    }
    #pragma unroll
    for (int i = 0; i < 4; i++) {
        int gm = bm + 4 * ty + i;
        if (gm < M) {
            float4 v = make_float4(acc[i][0], acc[i][1], acc[i][2], acc[i][3]);
            *(float4*)&C[(size_t)gm * Nc + bn + 4 * tx] = v;
        }
    }
}

// ------- fused layer 1 + layer 2 transform:  hw23[c] = relu(agg+b1) @ W23 ----
// Phase 1: CSR gather of hw1 into smem h1 row (with bias+relu).
// Phase 2: 128-wide dense GEMV against W23 (L2-resident), write hw23 row.
__global__ __launch_bounds__(128) void k_gather1_gemm(
    const float* __restrict__ hw, const float* __restrict__ bias,
    const float* __restrict__ W23, float* __restrict__ hw23)
{
    __shared__ int   s_row[128];
    __shared__ float s_nrm[128];
    __shared__ float s_h1[128];
    int c = blockIdx.x;
    int tid = threadIdx.x;
    int beg = g_off[c], end = g_end[c];

    float a0 = 0.f, a1 = 0.f, a2 = 0.f, a3 = 0.f;
    for (int base = beg; base < end; base += 128) {
        int len = min(128, end - base);
        if (tid < len) {
            s_row[tid] = g_csr_row[base + tid];
            s_nrm[tid] = g_csr_nrm[base + tid];
        }
        __syncthreads();
        int j = 0;
        for (; j + 3 < len; j += 4) {
            a0 += s_nrm[j + 0] * hw[(size_t)s_row[j + 0] * H1 + tid];
            a1 += s_nrm[j + 1] * hw[(size_t)s_row[j + 1] * H1 + tid];
            a2 += s_nrm[j + 2] * hw[(size_t)s_row[j + 2] * H1 + tid];
            a3 += s_nrm[j + 3] * hw[(size_t)s_row[j + 3] * H1 + tid];
        }
        for (; j < len; j++)
            a0 += s_nrm[j] * hw[(size_t)s_row[j] * H1 + tid];
        __syncthreads();
    }
    float v = (a0 + a1) + (a2 + a3) + bias[tid];
    s_h1[tid] = fmaxf(v, 0.0f);
    __syncthreads();

    // Phase 2: hw23 row = s_h1 (1x128) @ W23 (128x128); thread = out column
    float o0 = 0.f, o1 = 0.f, o2 = 0.f, o3 = 0.f;
    #pragma unroll 8
    for (int k = 0; k < 128; k += 4) {
        o0 += s_h1[k + 0] * W23[(k + 0) * 128 + tid];
        o1 += s_h1[k + 1] * W23[(k + 1) * 128 + tid];
        o2 += s_h1[k + 2] * W23[(k + 2) * 128 + tid];
        o3 += s_h1[k + 3] * W23[(k + 3) * 128 + tid];
    }
    hw23[(size_t)c * 128 + tid] = (o0 + o1) + (o2 + o3);
}

// ---------------- CSR gather: mu + fp16 split (critical path) ----------------
__global__ __launch_bounds__(64) void k_gather_mu(
    const float* __restrict__ hw23, float* __restrict__ mu,
    const float* __restrict__ b2,
    __half* __restrict__ ZH, __half* __restrict__ ZL)
{
    __shared__ int   s_row[64];
    __shared__ float s_nrm[64];
    int c = blockIdx.x;
    int f = threadIdx.x;               // 0..63
    int beg = g_off[c], end = g_end[c];

    float a0 = 0.f, a1 = 0.f, a2 = 0.f, a3 = 0.f;
    for (int base = beg; base < end; base += 64) {
        int len = min(64, end - base);
        if (f < len) {
            s_row[f] = g_csr_row[base + f];
            s_nrm[f] = g_csr_nrm[base + f];
        }
        __syncthreads();
        int j = 0;
        for (; j + 3 < len; j += 4) {
            a0 += s_nrm[j + 0] * hw23[(size_t)s_row[j + 0] * 128 + f];
            a1 += s_nrm[j + 1] * hw23[(size_t)s_row[j + 1] * 128 + f];
            a2 += s_nrm[j + 2] * hw23[(size_t)s_row[j + 2] * 128 + f];
            a3 += s_nrm[j + 3] * hw23[(size_t)s_row[j + 3] * 128 + f];
        }
        for (; j < len; j++)
            a0 += s_nrm[j] * hw23[(size_t)s_row[j] * 128 + f];
        __syncthreads();
    }
    float m = (a0 + a1) + (a2 + a3) + b2[f];
    mu[(size_t)c * H2 + f] = m;
    __half h = __float2half_rn(m);
    __half l = __float2half_rn(m - __half2float(h));
    ZH[(size_t)c * H2 + f] = h;
    ZL[(size_t)c * H2 + f] = l;
}

// ---------------- CSR gather: logvar (overlapped with adj GEMM) --------------
__global__ __launch_bounds__(64) void k_gather_lv(
    const float* __restrict__ hw23, float* __restrict__ lv,
    const float* __restrict__ b3)
{
    __shared__ int   s_row[64];
    __shared__ float s_nrm[64];
    int c = blockIdx.x;
    int f = threadIdx.x;               // 0..63
    int beg = g_off[c], end = g_end[c];

    float a0 = 0.f, a1 = 0.f, a2 = 0.f, a3 = 0.f;
    for (int base = beg; base < end; base += 64) {
        int len = min(64, end - base);
        if (f < len) {
            s_row[f] = g_csr_row[base + f];
            s_nrm[f] = g_csr_nrm[base + f];
        }
        __syncthreads();
        int j = 0;
        for (; j + 3 < len; j += 4) {
            a0 += s_nrm[j + 0] * hw23[(size_t)s_row[j + 0] * 128 + 64 + f];
            a1 += s_nrm[j + 1] * hw23[(size_t)s_row[j + 1] * 128 + 64 + f];
            a2 += s_nrm[j + 2] * hw23[(size_t)s_row[j + 2] * 128 + 64 + f];
            a3 += s_nrm[j + 3] * hw23[(size_t)s_row[j + 3] * 128 + 64 + f];
        }
        for (; j < len; j++)
            a0 += s_nrm[j] * hw23[(size_t)s_row[j] * 128 + 64 + f];
        __syncthreads();
    }
    lv[(size_t)c * H2 + f] = (a0 + a1) + (a2 + a3) + b3[f];
}

// ---------------- adj: fp16 split K=128, A=[H|L], B=[H|H] --------------------
// C = H·H^T + L·H^T  (missing H·L^T ~ 2^-12 relative). Triangular + mirror.
#define ADJ2_SMEM (2 * 128 * BPAD * 2)

__device__ __forceinline__ void ldsm_x4(uint32_t& r0, uint32_t& r1,
                                        uint32_t& r2, uint32_t& r3, uint32_t addr) {
    asm volatile("ldmatrix.sync.aligned.m8n8.x4.shared.b16 {%0,%1,%2,%3}, [%4];"
                 : "=r"(r0), "=r"(r1), "=r"(r2), "=r"(r3) : "r"(addr));
}

__global__ __launch_bounds__(256, 2) void k_adj_mma(
    const __half* __restrict__ ZH, const __half* __restrict__ ZL,
    float* __restrict__ C, int n, int mtiles)
{
    extern __shared__ __half sm2[];
    __half* As = sm2;                     // [128][BPAD]  rows = [H | L]
    __half* Bs = sm2 + 128 * BPAD;        // [128][BPAD]  rows = [H | H]
    float* S = (float*)sm2;               // staging reuse: [128][132] fp32

    // triangular decode: blockIdx.x -> (ti, tj), ti <= tj
    int ti = 0, rem = blockIdx.x;
    while (rem >= mtiles - ti) { rem -= mtiles - ti; ti++; }
    int tj = ti + rem;
    int bi = ti * 128, bj = tj * 128;

    int tid = threadIdx.x, lane = tid & 31, warp = tid >> 5;
    int wm = warp >> 2, wn = warp & 3;    // 2 x 4 warp grid

    // prolog: 128 rows x 16 uint4 (128 fp16) per array; H deduplicated in gmem
    const uint4 zero4 = make_uint4(0u, 0u, 0u, 0u);
    for (int i = tid; i < 128 * 16; i += 256) {
        int r = i >> 4, c = i & 15;       // c: 8-fp16 chunk
        int c7 = (c & 7) * 8;
        uint4 va = zero4, vb = zero4;
        if (bi + r < n)
            va = (c < 8) ? *(const uint4*)&ZH[(size_t)(bi + r) * H2 + c7]
                         : *(const uint4*)&ZL[(size_t)(bi + r) * H2 + c7];
        if (bj + r < n)
            vb = *(const uint4*)&ZH[(size_t)(bj + r) * H2 + c7];
        *(uint4*)&As[r * BPAD + c * 8] = va;
        *(uint4*)&Bs[r * BPAD + c * 8] = vb;
    }
    __syncthreads();

    // ldmatrix lane addressing (byte addresses in shared space)
    uint32_t as_u32 = (uint32_t)__cvta_generic_to_shared(As);
    uint32_t bs_u32 = (uint32_t)__cvta_generic_to_shared(Bs);
    int l7 = lane & 7, lb3 = (lane >> 3) & 1, lb4 = lane >> 4;
    uint32_t a_addr[4];
    #pragma unroll
    for (int im = 0; im < 4; im++)
        a_addr[im] = as_u32 +
            (uint32_t)((wm * 64 + im * 16 + lb3 * 8 + l7) * BPAD) * 2 + lb4 * 16;
    uint32_t b_addr[2];
    #pragma unroll
    for (int p = 0; p < 2; p++)
        b_addr[p] = bs_u32 +
            (uint32_t)((wn * 32 + p * 16 + lb4 * 8 + l7) * BPAD) * 2 + lb3 * 16;

    float acc[4][4][4] = {};
    #pragma unroll
    for (int ks = 0; ks < KADJ / 16; ks++) {
        uint32_t koff = ks * 32;          // 16 fp16 = 32 bytes
        uint32_t b[4][2];
        ldsm_x4(b[0][0], b[0][1], b[1][0], b[1][1], b_addr[0] + koff);
        ldsm_x4(b[2][0], b[2][1], b[3][0], b[3][1], b_addr[1] + koff);
        #pragma unroll
        for (int im = 0; im < 4; im++) {
            uint32_t a0, a1, a2, a3;
            ldsm_x4(a0, a1, a2, a3, a_addr[im] + koff);
            #pragma unroll
            for (int jn = 0; jn < 4; jn++) {
                asm volatile(
                    "mma.sync.aligned.m16n8k16.row.col.f32.f16.f16.f32 "
                    "{%0,%1,%2,%3}, {%4,%5,%6,%7}, {%8,%9}, {%0,%1,%2,%3};"
                    : "+f"(acc[im][jn][0]), "+f"(acc[im][jn][1]),
                      "+f"(acc[im][jn][2]), "+f"(acc[im][jn][3])
                    : "r"(a0), "r"(a1), "r"(a2), "r"(a3),
                      "r"(b[jn][0]), "r"(b[jn][1]));
            }
        }
    }

    int kq = lane & 3;
    // direct store of tile (bi, bj) — streaming (evict-first) stores
    #pragma unroll
    for (int im = 0; im < 4; im++) {
        int r0 = bi + wm * 64 + im * 16 + (lane >> 2);
        #pragma unroll
        for (int jn = 0; jn < 4; jn++) {
            int cc = bj + wn * 32 + jn * 8 + kq * 2;
            if (r0 < n) {
                if (cc + 1 < n)
                    __stcs((float2*)&C[(size_t)r0 * n + cc],
                           make_float2(acc[im][jn][0], acc[im][jn][1]));
                else if (cc < n)
                    C[(size_t)r0 * n + cc] = acc[im][jn][0];
            }
            int r1 = r0 + 8;
            if (r1 < n) {
                if (cc + 1 < n)
                    __stcs((float2*)&C[(size_t)r1 * n + cc],
                           make_float2(acc[im][jn][2], acc[im][jn][3]));
                else if (cc < n)
                    C[(size_t)r1 * n + cc] = acc[im][jn][2];
            }
        }
    }

    // mirror store of tile (bj, bi) via smem transpose staging
    if (ti != tj) {
        __syncthreads();                  // done reading As/Bs
        int rbase = wm * 64 + (lane >> 2);
        int cbase = wn * 32 + kq * 2;
        #pragma unroll
        for (int im = 0; im < 4; im++) {
            int r = rbase + im * 16;
            #pragma unroll
            for (int jn = 0; jn < 4; jn++) {
                int c = cbase + jn * 8;
                S[(c + 0) * 132 + r]     = acc[im][jn][0];
                S[(c + 1) * 132 + r]     = acc[im][jn][1];
                S[(c + 0) * 132 + r + 8] = acc[im][jn][2];
                S[(c + 1) * 132 + r + 8] = acc[im][jn][3];
            }
        }
        __syncthreads();
        #pragma unroll
        for (int rr = warp * 16; rr < warp * 16 + 16; rr++) {
            int grow = bj + rr;
            if (grow < n) {
                float4 v = *(const float4*)&S[rr * 132 + lane * 4];
                __stcs((float4*)&C[(size_t)grow * n + bi + lane * 4], v);
            }
        }
    }
}

// ---------------- launch ------------------------------------------------------
extern "C" void kernel_launch(void* const* d_in, const int* in_sizes, int n_in,
                              void* d_out, int out_size) {
    const float* x   = (const float*)d_in[0];
    const void*  ei  = d_in[1];                 // edge_index [2,E], int64 or int32
    const float* ew  = (const float*)d_in[2];
    const float* W1  = (const float*)d_in[3];
    const float* b1  = (const float*)d_in[4];
    const float* W2  = (const float*)d_in[5];
    const float* b2  = (const float*)d_in[6];
    const float* W3  = (const float*)d_in[7];
    const float* b3  = (const float*)d_in[8];

    const int n = N_NODES;
    const int E = in_sizes[1] / 2;

    float* adj    = (float*)d_out;                                  // [N,N]
    float* mu     = (float*)d_out + (size_t)n * n;                  // [N,H2]
    float* logvar = mu + (size_t)n * H2;                            // [N,H2]

    float* g_hw1_p;  cudaGetSymbolAddress((void**)&g_hw1_p,  g_hw1);
    float* g_w23_p;  cudaGetSymbolAddress((void**)&g_w23_p,  g_w23);
    float* g_hw23_p; cudaGetSymbolAddress((void**)&g_hw23_p, g_hw23);
    __half* g_zh_p; cudaGetSymbolAddress((void**)&g_zh_p, g_zh);
    __half* g_zl_p; cudaGetSymbolAddress((void**)&g_zl_p, g_zl);

    static int s_init = 0;
    static cudaStream_t s2;
    static cudaEvent_t evF, evB, evC, evD;
    if (!s_init) {
        cudaFuncSetAttribute(k_adj_mma, cudaFuncAttributeMaxDynamicSharedMemorySize, ADJ2_SMEM);
        cudaStreamCreateWithFlags(&s2, cudaStreamNonBlocking);
        cudaEventCreateWithFlags(&evF, cudaEventDisableTiming);
        cudaEventCreateWithFlags(&evB, cudaEventDisableTiming);
        cudaEventCreateWithFlags(&evC, cudaEventDisableTiming);
        cudaEventCreateWithFlags(&evD, cudaEventDisableTiming);
        s_init = 1;
    }

    const int T = 256;
    dim3 blk(16, 16);

    // fork: branch B (stream s2) runs x@W1 + weight packing concurrently
    cudaEventRecord(evF, 0);
    cudaStreamWaitEvent(s2, evF, 0);
    k_pack_w23<<<(H1 * 64 + T - 1) / T, T, 0, s2>>>(W2, W3, g_w23_p);
    k_sgemm<<<dim3(H1 / 64, (n + 63) / 64), blk, 0, s2>>>(x, W1, g_hw1_p, n, F_IN, H1);
    cudaEventRecord(evB, s2);

    // branch A (stream 0): init+detect, packed degree accum + CSR build
    k_init<<<(n + 1023) / 1024, 1024>>>(ei, E, n);
    k_deg_accum<<<(E + T - 1) / T, T>>>(ei, ew, E);
    k_dis_alloc<<<(n + T - 1) / T, T>>>(n);
    k_scatter<<<(E + n + T - 1) / T, T>>>(ei, ew, E, n);

    // join
    cudaStreamWaitEvent(0, evB, 0);

    // 2+3. fused: h1 row (gather+relu, smem-resident) -> hw23 row GEMV
    k_gather1_gemm<<<n, 128>>>(g_hw1_p, b1, g_w23_p, g_hw23_p);
    cudaEventRecord(evC, 0);

    // mu (+ fp16 split) on critical path; logvar overlapped with adj on s2
    k_gather_mu<<<n, 64>>>(g_hw23_p, mu, b2, g_zh_p, g_zl_p);
    cudaStreamWaitEvent(s2, evC, 0);
    k_gather_lv<<<n, 64, 0, s2>>>(g_hw23_p, logvar, b3);
    cudaEventRecord(evD, s2);

    // 4. adj = mu @ mu^T via fp16-split tensor-core GEMM (triangular + mirror)
    int mtiles = (n + 127) / 128;
    k_adj_mma<<<mtiles * (mtiles + 1) / 2, 256, ADJ2_SMEM>>>(
        g_zh_p, g_zl_p, adj, n, mtiles);

    // rejoin s2 so capture ends with a single terminal stream
    cudaStreamWaitEvent(0, evD, 0);
}